// round 1
// baseline (speedup 1.0000x reference)
#include <cuda_runtime.h>
#include <math.h>

// Problem constants
// B=16, W=H=32, C=512, HEADS=4, DH=128, N=1024, P=16, HID=2048
// n = h*32 + w ; BN = B*N = 16384

// ---------------- scratch (device globals; no allocation allowed) -------------
__device__ float g_xf[16384 * 512];        // xf[bn][c]
__device__ float g_qkvv[16384 * 2048];     // qkvv[bn][j]
__device__ float g_qkvvT[4 * 8192 * 1024]; // [m][b*4+h][d][n]  (8192 rows of 1024 per m)
__device__ float g_kproj[64 * 128 * 16];   // [bz][d][p]
__device__ float g_vproj[64 * 128 * 16];
__device__ float g_attnca[64 * 128 * 128]; // [bz][d][e]
__device__ float g_xca[16 * 512 * 1024];   // [b][h*128+d][n]
__device__ float g_xsa[16 * 512 * 1024];   // [b][d*4+h][n]  == row-major (n', c') view
__device__ float g_t1[16 * 2048 * 1024];   // [b][o][n]
__device__ float g_t2[16 * 2048 * 1024];   // [b][o][n]

// ---------------- epilogues ---------------------------------------------------
struct EpiPlain {
    float* C; long csb; int ldc;
    const float* biasRow; const float* biasCol;
    __device__ __forceinline__ void operator()(int bz, int i, int j, float v) const {
        if (biasRow) v += biasRow[i];
        if (biasCol) v += biasCol[j];
        C[(long)bz * csb + (long)i * ldc + j] = v;
    }
};

// store into d_out (B,W,H,C) with row index n -> (h=n>>5, w=n&31), col offset, opt accumulate
struct EpiOut {
    float* out; const float* bias; int coff; int accum;
    __device__ __forceinline__ void operator()(int b, int n, int j, float v) const {
        v += bias[j];
        int h = n >> 5, w = n & 31;
        long idx = (((long)(b * 32 + w)) * 32 + h) * 512 + coff + j;
        if (accum) out[idx] += v; else out[idx] = v;
    }
};

// ---------------- generic 128x128x8 SGEMM -------------------------------------
// C[i][j] = sum_k A(i,k) * B(j,k)
// AT=false: A stored (M,K) row-major (lda=K-stride). AT=true: A stored (K,M) (lda=M-stride).
// BT=true : B stored (N,K) row-major.              BT=false: B stored (K,N).
template<bool AT, bool BT, class Epi>
__global__ void __launch_bounds__(256) gemm128(
    const float* __restrict__ A, const float* __restrict__ B,
    int M, int N, int K, int lda, int ldb, long asb, long bsb, Epi epi)
{
    __shared__ float As[8][128];
    __shared__ float Bs[8][128];
    int bz = blockIdx.z;
    const float* Ab = A + (long)bz * asb;
    const float* Bb = B + (long)bz * bsb;
    int bm = blockIdx.y * 128, bn = blockIdx.x * 128;
    int tid = threadIdx.x;
    int tr = tid >> 4, tc = tid & 15;
    float acc[8][8];
#pragma unroll
    for (int i = 0; i < 8; i++)
#pragma unroll
        for (int j = 0; j < 8; j++) acc[i][j] = 0.f;

    for (int k0 = 0; k0 < K; k0 += 8) {
        if (AT) {
            int k = tid >> 5, i4 = (tid & 31) << 2;
            float4 v = *(const float4*)(Ab + (long)(k0 + k) * lda + bm + i4);
            *(float4*)&As[k][i4] = v;
        } else {
            int i = tid >> 1, kk = (tid & 1) << 2;
            float4 v = *(const float4*)(Ab + (long)(bm + i) * lda + k0 + kk);
            As[kk + 0][i] = v.x; As[kk + 1][i] = v.y; As[kk + 2][i] = v.z; As[kk + 3][i] = v.w;
        }
        if (BT) {
            int j = tid >> 1, kk = (tid & 1) << 2;
            float4 v = *(const float4*)(Bb + (long)(bn + j) * ldb + k0 + kk);
            Bs[kk + 0][j] = v.x; Bs[kk + 1][j] = v.y; Bs[kk + 2][j] = v.z; Bs[kk + 3][j] = v.w;
        } else {
            int k = tid >> 5, j4 = (tid & 31) << 2;
            float4 v = *(const float4*)(Bb + (long)(k0 + k) * ldb + bn + j4);
            *(float4*)&Bs[k][j4] = v;
        }
        __syncthreads();
#pragma unroll
        for (int k = 0; k < 8; k++) {
            float4 a0 = *(const float4*)&As[k][tr * 8];
            float4 a1 = *(const float4*)&As[k][tr * 8 + 4];
            float4 b0 = *(const float4*)&Bs[k][tc * 8];
            float4 b1 = *(const float4*)&Bs[k][tc * 8 + 4];
            float ar[8] = {a0.x, a0.y, a0.z, a0.w, a1.x, a1.y, a1.z, a1.w};
            float br[8] = {b0.x, b0.y, b0.z, b0.w, b1.x, b1.y, b1.z, b1.w};
#pragma unroll
            for (int i = 0; i < 8; i++)
#pragma unroll
                for (int j = 0; j < 8; j++) acc[i][j] += ar[i] * br[j];
        }
        __syncthreads();
    }
#pragma unroll
    for (int i = 0; i < 8; i++)
#pragma unroll
        for (int j = 0; j < 8; j++)
            epi(bz, bm + tr * 8 + i, bn + tc * 8 + j, acc[i][j]);
}

// ---------------- pack: x (B,W,H,C) -> xf[bn][c], n=h*32+w ---------------------
__global__ void pack_xf(const float* __restrict__ x) {
    int blk = blockIdx.x;                  // dst row = b*1024 + n
    int b = blk >> 10, n = blk & 1023;
    int h = n >> 5, w = n & 31;
    const float* src = x + (((long)(b * 32 + w)) * 32 + h) * 512;
    float* dst = g_xf + (long)blk * 512;
    int t = threadIdx.x; // 128
    *(float4*)&dst[t * 4] = *(const float4*)&src[t * 4];
}

// ---------------- transpose qkvv[bn][j] -> g_qkvvT[m][b*4+h][d][n] ------------
__global__ void transpose_qkvv() {
    __shared__ float tile[32][33];
    int b = blockIdx.z;
    int j0 = blockIdx.x * 32, n0 = blockIdx.y * 32;
    int tx = threadIdx.x, ty = threadIdx.y; // 32 x 8
#pragma unroll
    for (int r = 0; r < 32; r += 8)
        tile[ty + r][tx] = g_qkvv[((long)(b * 1024 + n0 + ty + r)) * 2048 + j0 + tx];
    __syncthreads();
#pragma unroll
    for (int r = 0; r < 32; r += 8) {
        int j = j0 + ty + r;
        int n = n0 + tx;
        int m = j >> 9, hh = (j >> 7) & 3, d = j & 127;
        g_qkvvT[((long)(m * 64 + b * 4 + hh)) * 131072 + (long)d * 1024 + n] = tile[tx][ty + r];
    }
}

// ---------------- k_proj / v_proj (P=16, contract over N=1024) -----------------
__global__ void kv_proj(const float* __restrict__ E_w, const float* __restrict__ E_b,
                        const float* __restrict__ F_w, const float* __restrict__ F_b) {
    int g = (blockIdx.x * blockDim.x + threadIdx.x) >> 5; // global warp id
    int lane = threadIdx.x & 31;
    int src = g >> 13;        // 0 = k (m=1), 1 = v_sa (m=3)
    int rem = g & 8191;       // bz*128 + d
    const float* row = g_qkvvT + (long)(src ? 3 : 1) * 8388608 + (long)rem * 1024;
    const float* W = src ? F_w : E_w;
    const float* bias = src ? F_b : E_b;
    float acc[16];
#pragma unroll
    for (int p = 0; p < 16; p++) acc[p] = 0.f;
    for (int n = lane; n < 1024; n += 32) {
        float v = row[n];
#pragma unroll
        for (int p = 0; p < 16; p++) acc[p] += v * W[p * 1024 + n];
    }
#pragma unroll
    for (int p = 0; p < 16; p++) {
#pragma unroll
        for (int o = 16; o > 0; o >>= 1) acc[p] += __shfl_xor_sync(0xffffffffu, acc[p], o);
    }
    if (lane == 0) {
        float* o = (src ? g_vproj : g_kproj) + (long)rem * 16;
#pragma unroll
        for (int p = 0; p < 16; p++) o[p] = acc[p] + bias[p];
    }
}

// ---------------- L2-normalize q and k rows in place ---------------------------
__global__ void norm_scale() {
    int r = blockIdx.x;                       // 0..16383 (m=0 rows then m=1 rows, contiguous)
    float* row = g_qkvvT + (long)r * 1024;
    int t = threadIdx.x; // 256
    float4 v = *(float4*)&row[t * 4];
    float s = v.x * v.x + v.y * v.y + v.z * v.z + v.w * v.w;
    __shared__ float sd[256];
    sd[t] = s; __syncthreads();
    for (int o = 128; o > 0; o >>= 1) { if (t < o) sd[t] += sd[t + o]; __syncthreads(); }
    float inv = 1.0f / fmaxf(sqrtf(sd[0]), 1e-12f);
    v.x *= inv; v.y *= inv; v.z *= inv; v.w *= inv;
    *(float4*)&row[t * 4] = v;
}

// ---------------- softmax over e (128) for channel attention -------------------
__global__ void softmax_ca(const float* __restrict__ temp) {
    int r = blockIdx.x;           // bz*128 + d, 8192 rows
    int h = (r >> 7) & 3;
    float tv = temp[h];
    float* row = g_attnca + (long)r * 128;
    int t = threadIdx.x; // 128
    float v = row[t] * tv;
    __shared__ float sd[128];
    sd[t] = v; __syncthreads();
    for (int o = 64; o > 0; o >>= 1) { if (t < o) sd[t] = fmaxf(sd[t], sd[t + o]); __syncthreads(); }
    float mx = sd[0]; __syncthreads();
    float e = expf(v - mx);
    sd[t] = e; __syncthreads();
    for (int o = 64; o > 0; o >>= 1) { if (t < o) sd[t] += sd[t + o]; __syncthreads(); }
    row[t] = e / sd[0];
}

// ---------------- fused projected spatial attention ----------------------------
// per (bz=b*4+h, n): logits[p] = sum_d qn[d,n]*kproj[d,p]; softmax*temp2; x_sa[n,d'] = sum_p a[p]*vproj[d',p]
// stored to g_xsa[b][(d'*4+h)*1024 + n]
__global__ void spatial_attn(const float* __restrict__ temp2) {
    int bz = blockIdx.y; int b = bz >> 2, h = bz & 3;
    int n = blockIdx.x * 128 + threadIdx.x;
    __shared__ float kps[128][16];
    __shared__ float vps[128][16];
    const float* kpb = g_kproj + (long)bz * 2048;
    const float* vpb = g_vproj + (long)bz * 2048;
    for (int i = threadIdx.x; i < 2048; i += 128) {
        kps[i >> 4][i & 15] = kpb[i];
        vps[i >> 4][i & 15] = vpb[i];
    }
    __syncthreads();
    const float* q = g_qkvvT + (long)bz * 131072 + n; // m=0 (qn, already normalized)
    float lg[16];
#pragma unroll
    for (int p = 0; p < 16; p++) lg[p] = 0.f;
    for (int d = 0; d < 128; d++) {
        float qv = q[(long)d * 1024];
#pragma unroll
        for (int p = 0; p < 16; p++) lg[p] += qv * kps[d][p];
    }
    float tv = temp2[h];
    float mx = -1e30f;
#pragma unroll
    for (int p = 0; p < 16; p++) { lg[p] *= tv; mx = fmaxf(mx, lg[p]); }
    float s = 0.f;
#pragma unroll
    for (int p = 0; p < 16; p++) { lg[p] = expf(lg[p] - mx); s += lg[p]; }
    float inv = 1.0f / s;
#pragma unroll
    for (int p = 0; p < 16; p++) lg[p] *= inv;
    float* ob = g_xsa + (long)b * 524288 + h * 1024 + n;
    for (int c = 0; c < 128; c += 8) {
        float acc[8];
#pragma unroll
        for (int dd = 0; dd < 8; dd++) acc[dd] = 0.f;
#pragma unroll
        for (int p = 0; p < 16; p++) {
            float ap = lg[p];
#pragma unroll
            for (int dd = 0; dd < 8; dd++) acc[dd] += ap * vps[c + dd][p];
        }
#pragma unroll
        for (int dd = 0; dd < 8; dd++) ob[(long)(c + dd) * 4096] = acc[dd];
    }
}

// ---------------- depthwise 3x3 (SAME, zero pad) + exact GELU ------------------
__global__ void dwconv_gelu(const float* __restrict__ w, const float* __restrict__ bias) {
    long bo = blockIdx.x;                 // b*2048 + o
    int och = (int)(bo & 2047);
    const float* img = g_t1 + bo * 1024;
    __shared__ float s[1024];
    int tid = threadIdx.x; // 256
    *(float4*)&s[tid * 4] = *(const float4*)&img[tid * 4];
    float wv[9];
#pragma unroll
    for (int k = 0; k < 9; k++) wv[k] = w[och * 9 + k];
    float bb = bias[och];
    __syncthreads();
    float* ob = g_t2 + bo * 1024;
    for (int p = tid; p < 1024; p += 256) {
        int h = p >> 5, ww = p & 31;
        float acc = bb;
#pragma unroll
        for (int i = 0; i < 3; i++) {
            int hh = h + i - 1;
            if (hh < 0 || hh > 31) continue;
#pragma unroll
            for (int j = 0; j < 3; j++) {
                int w2 = ww + j - 1;
                if (w2 < 0 || w2 > 31) continue;
                acc += s[hh * 32 + w2] * wv[i * 3 + j];
            }
        }
        ob[p] = 0.5f * acc * (1.0f + erff(acc * 0.70710678118654752440f));
    }
}

// ---------------- launch ------------------------------------------------------
extern "C" void kernel_launch(void* const* d_in, const int* in_sizes, int n_in,
                              void* d_out_v, int out_size) {
    const float* x      = (const float*)d_in[0];
    const float* qkvv_w = (const float*)d_in[1];
    const float* E_w    = (const float*)d_in[2];
    const float* E_b    = (const float*)d_in[3];
    const float* F_w    = (const float*)d_in[4];
    const float* F_b    = (const float*)d_in[5];
    const float* temp   = (const float*)d_in[6];
    const float* temp2  = (const float*)d_in[7];
    const float* out_w  = (const float*)d_in[8];
    const float* out_b  = (const float*)d_in[9];
    const float* out2_w = (const float*)d_in[10];
    const float* out2_b = (const float*)d_in[11];
    const float* fc1_w  = (const float*)d_in[12];
    const float* fc1_b  = (const float*)d_in[13];
    const float* dw_w   = (const float*)d_in[14];
    const float* dw_b   = (const float*)d_in[15];
    const float* fc2_w  = (const float*)d_in[16];
    const float* fc2_b  = (const float*)d_in[17];
    float* dout = (float*)d_out_v;

    float *p_xf, *p_qkvv, *p_qkvvT, *p_attnca, *p_xca, *p_xsa, *p_t1, *p_t2;
    cudaGetSymbolAddress((void**)&p_xf, g_xf);
    cudaGetSymbolAddress((void**)&p_qkvv, g_qkvv);
    cudaGetSymbolAddress((void**)&p_qkvvT, g_qkvvT);
    cudaGetSymbolAddress((void**)&p_attnca, g_attnca);
    cudaGetSymbolAddress((void**)&p_xca, g_xca);
    cudaGetSymbolAddress((void**)&p_xsa, g_xsa);
    cudaGetSymbolAddress((void**)&p_t1, g_t1);
    cudaGetSymbolAddress((void**)&p_t2, g_t2);

    // 1. pack x -> xf
    pack_xf<<<16384, 128>>>(x);

    // 2. qkvv GEMM: [16384,2048] = xf[16384,512] @ qkvv_w^T
    {
        EpiPlain e{p_qkvv, 0, 2048, nullptr, nullptr};
        gemm128<false, true, EpiPlain><<<dim3(16, 128, 1), 256>>>(
            p_xf, qkvv_w, 16384, 2048, 512, 512, 512, 0, 0, e);
    }

    // 3. transpose to [m][bz][d][n]
    transpose_qkvv<<<dim3(64, 32, 16), dim3(32, 8)>>>();

    // 4. k_proj / v_proj (from un-normalized k, v_sa)
    kv_proj<<<2048, 256>>>(E_w, E_b, F_w, F_b);

    // 5. L2-normalize q, k rows in place
    norm_scale<<<16384, 256>>>();

    // 6. channel-attn logits: per bz, [128,128] = qn @ kn^T (K=1024)
    {
        EpiPlain e{p_attnca, 128 * 128, 128, nullptr, nullptr};
        gemm128<false, true, EpiPlain><<<dim3(1, 1, 64), 256>>>(
            p_qkvvT, p_qkvvT + 8388608, 128, 128, 1024, 1024, 1024, 131072, 131072, e);
    }

    // 7. softmax (* temp)
    softmax_ca<<<8192, 128>>>(temp);

    // 8. x_ca: per bz, [128,1024] = attn @ v_ca  (K=128)
    {
        EpiPlain e{p_xca, 131072, 1024, nullptr, nullptr};
        gemm128<false, false, EpiPlain><<<dim3(8, 1, 64), 256>>>(
            p_attnca, p_qkvvT + 2 * 8388608, 128, 1024, 128, 128, 1024, 16384, 131072, e);
    }

    // 9. fused spatial attention -> g_xsa
    spatial_attn<<<dim3(8, 64), 128>>>(temp2);

    // 10. LFE fc1: per b, [2048,1024] = fc1_w @ xf_b^T
    {
        EpiPlain e{p_t1, 2097152, 1024, fc1_b, nullptr};
        gemm128<false, true, EpiPlain><<<dim3(8, 16, 16), 256>>>(
            fc1_w, p_xf, 2048, 1024, 512, 512, 512, 0, 524288, e);
    }

    // 11. depthwise conv + GELU
    dwconv_gelu<<<32768, 256>>>(dw_w, dw_b);

    // 12. LFE fc2 -> d_out (assign, includes swap to (B,W,H,C))
    {
        EpiOut e{dout, fc2_b, 0, 0};
        gemm128<true, true, EpiOut><<<dim3(4, 8, 16), 256>>>(
            p_t2, fc2_w, 1024, 512, 2048, 1024, 2048, 2097152, 0, e);
    }

    // 13. out projection (spatial) -> d_out[..., 0:256] +=
    {
        EpiOut e{dout, out_b, 0, 1};
        gemm128<false, true, EpiOut><<<dim3(2, 8, 16), 256>>>(
            p_xsa, out_w, 1024, 256, 512, 512, 512, 524288, 0, e);
    }

    // 14. out2 projection (channel) -> d_out[..., 256:512] +=
    {
        EpiOut e{dout, out2_b, 256, 1};
        gemm128<true, true, EpiOut><<<dim3(2, 8, 16), 256>>>(
            p_xca, out2_w, 1024, 256, 512, 1024, 512, 524288, 0, e);
    }
}

// round 2
// speedup vs baseline: 1.7045x; 1.7045x over previous
#include <cuda_runtime.h>
#include <math.h>

// Problem constants
// B=16, W=H=32, C=512, HEADS=4, DH=128, N=1024, P=16, HID=2048
// n = h*32 + w ; BN = B*N = 16384

// ---------------- scratch (device globals; no allocation allowed) -------------
__device__ float g_xf[16384 * 512];        // xf[bn][c]
__device__ float g_qkvv[16384 * 2048];     // qkvv[bn][j]
__device__ float g_qkvvT[4 * 8192 * 1024]; // [m][b*4+h][d][n]
__device__ float g_kproj[64 * 128 * 16];   // [bz][d][p]
__device__ float g_vproj[64 * 128 * 16];
__device__ float g_attnca[64 * 128 * 128]; // [bz][d][e]
__device__ float g_xca[16 * 512 * 1024];   // [b][h*128+d][n]
__device__ float g_xsa[16 * 512 * 1024];   // [b][d*4+h][n]
__device__ float g_t1[16 * 2048 * 1024];   // [b][o][n]
__device__ float g_t2[16 * 2048 * 1024];   // [b][o][n]

// ---------------- tf32 helper --------------------------------------------------
__device__ __forceinline__ unsigned f2tf(float x) {
    unsigned u;
    asm("cvt.rna.tf32.f32 %0, %1;" : "=r"(u) : "f"(x));
    return u;
}

// ---------------- epilogues ---------------------------------------------------
struct EpiPlain {
    float* C; long csb; int ldc;
    const float* biasRow; const float* biasCol;
    __device__ __forceinline__ void operator()(int bz, int i, int j, float v) const {
        if (biasRow) v += biasRow[i];
        if (biasCol) v += biasCol[j];
        C[(long)bz * csb + (long)i * ldc + j] = v;
    }
};

// store into d_out (B,W,H,C) with row index n -> (h=n>>5, w=n&31), col offset, opt accumulate
struct EpiOut {
    float* out; const float* bias; int coff; int accum;
    __device__ __forceinline__ void operator()(int b, int n, int j, float v) const {
        v += bias[j];
        int h = n >> 5, w = n & 31;
        long idx = (((long)(b * 32 + w)) * 32 + h) * 512 + coff + j;
        if (accum) out[idx] += v; else out[idx] = v;
    }
};

// ---------------- TF32 tensor-core GEMM, 128x128 block, K-step 32 --------------
// C[i][j] = sum_k A(i,k) * B(j,k)
// AT=false: A stored (M,K) row-major (k-contiguous).  AT=true: A stored (K,M) (m-contiguous).
// BT=true : B stored (N,K) row-major (k-contiguous).  BT=false: B stored (K,N) (n-contiguous).
//
// smem layouts (conflict-free for both the gmem->smem stores and fragment loads):
//   k-contiguous operand  : S[m][k], pitch 36  (idx = m*36 + k)
//   m/n-contiguous operand: S[k][m], pitch 136 (idx = k*136 + m)
template<bool AT, bool BT, class Epi>
__global__ void __launch_bounds__(256) gemmT(
    const float* __restrict__ A, const float* __restrict__ B,
    int M, int N, int K, int lda, int ldb, long asb, long bsb, Epi epi)
{
    constexpr int ASZ = AT ? 32 * 136 : 128 * 36;
    constexpr int BSZ = BT ? 128 * 36 : 32 * 136;
    __shared__ unsigned As[ASZ];
    __shared__ unsigned Bs[BSZ];

    int bz = blockIdx.z;
    const float* Ab = A + (long)bz * asb;
    const float* Bb = B + (long)bz * bsb;
    int bm = blockIdx.y * 128, bn = blockIdx.x * 128;
    int tid = threadIdx.x;
    int warp = tid >> 5, lane = tid & 31;
    int wm = (warp >> 2) * 64;   // 2 warp rows (64 each)
    int wn = (warp & 3) * 32;    // 4 warp cols (32 each)
    int g = lane >> 2, t = lane & 3;

    float c[4][4][4];
#pragma unroll
    for (int mt = 0; mt < 4; mt++)
#pragma unroll
        for (int nt = 0; nt < 4; nt++)
#pragma unroll
            for (int r = 0; r < 4; r++) c[mt][nt][r] = 0.f;

    float4 pa[4], pb[4];

    // ---- prefetch first tile into registers
#pragma unroll
    for (int i = 0; i < 4; i++) {
        int idx = tid + i * 256;
        if (AT) {
            int k = idx >> 5, m4 = (idx & 31) << 2;
            pa[i] = *(const float4*)(Ab + (long)(0 + k) * lda + bm + m4);
        } else {
            int m = idx >> 3, k4 = (idx & 7) << 2;
            pa[i] = *(const float4*)(Ab + (long)(bm + m) * lda + 0 + k4);
        }
    }
#pragma unroll
    for (int i = 0; i < 4; i++) {
        int idx = tid + i * 256;
        if (BT) {
            int n = idx >> 3, k4 = (idx & 7) << 2;
            pb[i] = *(const float4*)(Bb + (long)(bn + n) * ldb + 0 + k4);
        } else {
            int k = idx >> 5, n4 = (idx & 31) << 2;
            pb[i] = *(const float4*)(Bb + (long)(0 + k) * ldb + bn + n4);
        }
    }

    for (int k0 = 0; k0 < K; k0 += 32) {
        __syncthreads();   // previous compute done before overwriting smem
        // ---- store prefetched tile to smem (cvt to tf32)
#pragma unroll
        for (int i = 0; i < 4; i++) {
            int idx = tid + i * 256;
            uint4 v;
            v.x = f2tf(pa[i].x); v.y = f2tf(pa[i].y); v.z = f2tf(pa[i].z); v.w = f2tf(pa[i].w);
            if (AT) {
                int k = idx >> 5, m4 = (idx & 31) << 2;
                *(uint4*)&As[k * 136 + m4] = v;
            } else {
                int m = idx >> 3, k4 = (idx & 7) << 2;
                *(uint4*)&As[m * 36 + k4] = v;
            }
        }
#pragma unroll
        for (int i = 0; i < 4; i++) {
            int idx = tid + i * 256;
            uint4 v;
            v.x = f2tf(pb[i].x); v.y = f2tf(pb[i].y); v.z = f2tf(pb[i].z); v.w = f2tf(pb[i].w);
            if (BT) {
                int n = idx >> 3, k4 = (idx & 7) << 2;
                *(uint4*)&Bs[n * 36 + k4] = v;
            } else {
                int k = idx >> 5, n4 = (idx & 31) << 2;
                *(uint4*)&Bs[k * 136 + n4] = v;
            }
        }
        __syncthreads();

        // ---- prefetch next tile
        if (k0 + 32 < K) {
            int kn0 = k0 + 32;
#pragma unroll
            for (int i = 0; i < 4; i++) {
                int idx = tid + i * 256;
                if (AT) {
                    int k = idx >> 5, m4 = (idx & 31) << 2;
                    pa[i] = *(const float4*)(Ab + (long)(kn0 + k) * lda + bm + m4);
                } else {
                    int m = idx >> 3, k4 = (idx & 7) << 2;
                    pa[i] = *(const float4*)(Ab + (long)(bm + m) * lda + kn0 + k4);
                }
            }
#pragma unroll
            for (int i = 0; i < 4; i++) {
                int idx = tid + i * 256;
                if (BT) {
                    int n = idx >> 3, k4 = (idx & 7) << 2;
                    pb[i] = *(const float4*)(Bb + (long)(bn + n) * ldb + kn0 + k4);
                } else {
                    int k = idx >> 5, n4 = (idx & 31) << 2;
                    pb[i] = *(const float4*)(Bb + (long)(kn0 + k) * ldb + bn + n4);
                }
            }
        }

        // ---- compute 4 k-chunks of 8
#pragma unroll
        for (int kc = 0; kc < 4; kc++) {
            int kb = kc * 8;
            unsigned af[4][4], bf[4][2];
#pragma unroll
            for (int mt = 0; mt < 4; mt++) {
                int m0 = wm + mt * 16 + g;
                if (AT) {
                    af[mt][0] = As[(kb + t) * 136 + m0];
                    af[mt][1] = As[(kb + t) * 136 + m0 + 8];
                    af[mt][2] = As[(kb + t + 4) * 136 + m0];
                    af[mt][3] = As[(kb + t + 4) * 136 + m0 + 8];
                } else {
                    af[mt][0] = As[m0 * 36 + kb + t];
                    af[mt][1] = As[(m0 + 8) * 36 + kb + t];
                    af[mt][2] = As[m0 * 36 + kb + t + 4];
                    af[mt][3] = As[(m0 + 8) * 36 + kb + t + 4];
                }
            }
#pragma unroll
            for (int nt = 0; nt < 4; nt++) {
                int n0 = wn + nt * 8 + g;
                if (BT) {
                    bf[nt][0] = Bs[n0 * 36 + kb + t];
                    bf[nt][1] = Bs[n0 * 36 + kb + t + 4];
                } else {
                    bf[nt][0] = Bs[(kb + t) * 136 + n0];
                    bf[nt][1] = Bs[(kb + t + 4) * 136 + n0];
                }
            }
#pragma unroll
            for (int mt = 0; mt < 4; mt++)
#pragma unroll
                for (int nt = 0; nt < 4; nt++) {
                    asm volatile(
                        "mma.sync.aligned.m16n8k8.row.col.f32.tf32.tf32.f32 "
                        "{%0,%1,%2,%3},{%4,%5,%6,%7},{%8,%9},{%0,%1,%2,%3};\n"
                        : "+f"(c[mt][nt][0]), "+f"(c[mt][nt][1]),
                          "+f"(c[mt][nt][2]), "+f"(c[mt][nt][3])
                        : "r"(af[mt][0]), "r"(af[mt][1]), "r"(af[mt][2]), "r"(af[mt][3]),
                          "r"(bf[nt][0]), "r"(bf[nt][1]));
                }
        }
    }

    // ---- epilogue
#pragma unroll
    for (int mt = 0; mt < 4; mt++)
#pragma unroll
        for (int nt = 0; nt < 4; nt++) {
            int i = wm + mt * 16 + g;
            int j = wn + nt * 8 + t * 2;
            epi(bz, bm + i,     bn + j,     c[mt][nt][0]);
            epi(bz, bm + i,     bn + j + 1, c[mt][nt][1]);
            epi(bz, bm + i + 8, bn + j,     c[mt][nt][2]);
            epi(bz, bm + i + 8, bn + j + 1, c[mt][nt][3]);
        }
}

// ---------------- pack: x (B,W,H,C) -> xf[bn][c], n=h*32+w ---------------------
__global__ void pack_xf(const float* __restrict__ x) {
    int blk = blockIdx.x;                  // dst row = b*1024 + n
    int b = blk >> 10, n = blk & 1023;
    int h = n >> 5, w = n & 31;
    const float* src = x + (((long)(b * 32 + w)) * 32 + h) * 512;
    float* dst = g_xf + (long)blk * 512;
    int t = threadIdx.x; // 128
    *(float4*)&dst[t * 4] = *(const float4*)&src[t * 4];
}

// ---------------- transpose qkvv[bn][j] -> g_qkvvT[m][b*4+h][d][n] ------------
__global__ void transpose_qkvv() {
    __shared__ float tile[32][33];
    int b = blockIdx.z;
    int j0 = blockIdx.x * 32, n0 = blockIdx.y * 32;
    int tx = threadIdx.x, ty = threadIdx.y; // 32 x 8
#pragma unroll
    for (int r = 0; r < 32; r += 8)
        tile[ty + r][tx] = g_qkvv[((long)(b * 1024 + n0 + ty + r)) * 2048 + j0 + tx];
    __syncthreads();
#pragma unroll
    for (int r = 0; r < 32; r += 8) {
        int j = j0 + ty + r;
        int n = n0 + tx;
        int m = j >> 9, hh = (j >> 7) & 3, d = j & 127;
        g_qkvvT[((long)(m * 64 + b * 4 + hh)) * 131072 + (long)d * 1024 + n] = tile[tx][ty + r];
    }
}

// ---------------- k_proj / v_proj with smem-cached weights ---------------------
// grid: src(2) x phalf(2) x rowblocks(256) = 1024 blocks; 256 threads
__global__ void __launch_bounds__(256) kv_proj2(
    const float* __restrict__ E_w, const float* __restrict__ E_b,
    const float* __restrict__ F_w, const float* __restrict__ F_b)
{
    __shared__ float Ws[8][1024];   // 32 KB
    int blk = blockIdx.x;
    int src = blk >> 9;            // 0 = k (m=1), 1 = v_sa (m=3)
    int ph  = (blk >> 8) & 1;      // p half: 0 -> p 0..7, 1 -> p 8..15
    int row0 = (blk & 255) * 32;
    const float* W = (src ? F_w : E_w) + ph * 8 * 1024;
    const float* bias = (src ? F_b : E_b) + ph * 8;

    for (int i = threadIdx.x; i < 2048; i += 256)
        *(float4*)&Ws[0][i * 4] = *(const float4*)&W[i * 4];
    __syncthreads();

    int warp = threadIdx.x >> 5, lane = threadIdx.x & 31;
    const float* basep = g_qkvvT + (long)(src ? 3 : 1) * 8388608;
#pragma unroll
    for (int rr = 0; rr < 4; rr++) {
        int rem = row0 + warp * 4 + rr;          // bz*128 + d
        const float* rowp = basep + (long)rem * 1024;
        float acc[8];
#pragma unroll
        for (int p = 0; p < 8; p++) acc[p] = 0.f;
        for (int n = lane; n < 1024; n += 32) {
            float v = rowp[n];
#pragma unroll
            for (int p = 0; p < 8; p++) acc[p] += v * Ws[p][n];
        }
#pragma unroll
        for (int p = 0; p < 8; p++) {
#pragma unroll
            for (int o = 16; o > 0; o >>= 1) acc[p] += __shfl_xor_sync(0xffffffffu, acc[p], o);
        }
        if (lane == 0) {
            float* o = (src ? g_vproj : g_kproj) + (long)rem * 16 + ph * 8;
#pragma unroll
            for (int p = 0; p < 8; p++) o[p] = acc[p] + bias[p];
        }
    }
}

// ---------------- L2-normalize q and k rows in place ---------------------------
__global__ void norm_scale() {
    int r = blockIdx.x;                       // 0..16383 (m=0 rows then m=1 rows)
    float* row = g_qkvvT + (long)r * 1024;
    int t = threadIdx.x; // 256
    float4 v = *(float4*)&row[t * 4];
    float s = v.x * v.x + v.y * v.y + v.z * v.z + v.w * v.w;
    __shared__ float sd[256];
    sd[t] = s; __syncthreads();
    for (int o = 128; o > 0; o >>= 1) { if (t < o) sd[t] += sd[t + o]; __syncthreads(); }
    float inv = 1.0f / fmaxf(sqrtf(sd[0]), 1e-12f);
    v.x *= inv; v.y *= inv; v.z *= inv; v.w *= inv;
    *(float4*)&row[t * 4] = v;
}

// ---------------- softmax over e (128) for channel attention -------------------
__global__ void softmax_ca(const float* __restrict__ temp) {
    int r = blockIdx.x;           // bz*128 + d, 8192 rows
    int h = (r >> 7) & 3;
    float tv = temp[h];
    float* row = g_attnca + (long)r * 128;
    int t = threadIdx.x; // 128
    float v = row[t] * tv;
    __shared__ float sd[128];
    sd[t] = v; __syncthreads();
    for (int o = 64; o > 0; o >>= 1) { if (t < o) sd[t] = fmaxf(sd[t], sd[t + o]); __syncthreads(); }
    float mx = sd[0]; __syncthreads();
    float e = expf(v - mx);
    sd[t] = e; __syncthreads();
    for (int o = 64; o > 0; o >>= 1) { if (t < o) sd[t] += sd[t + o]; __syncthreads(); }
    row[t] = e / sd[0];
}

// ---------------- fused projected spatial attention ----------------------------
__global__ void spatial_attn(const float* __restrict__ temp2) {
    int bz = blockIdx.y; int b = bz >> 2, h = bz & 3;
    int n = blockIdx.x * 128 + threadIdx.x;
    __shared__ float kps[128][16];
    __shared__ float vps[128][16];
    const float* kpb = g_kproj + (long)bz * 2048;
    const float* vpb = g_vproj + (long)bz * 2048;
    for (int i = threadIdx.x; i < 2048; i += 128) {
        kps[i >> 4][i & 15] = kpb[i];
        vps[i >> 4][i & 15] = vpb[i];
    }
    __syncthreads();
    const float* q = g_qkvvT + (long)bz * 131072 + n; // m=0 (normalized q)
    float lg[16];
#pragma unroll
    for (int p = 0; p < 16; p++) lg[p] = 0.f;
    for (int d = 0; d < 128; d++) {
        float qv = q[(long)d * 1024];
#pragma unroll
        for (int p = 0; p < 16; p++) lg[p] += qv * kps[d][p];
    }
    float tv = temp2[h];
    float mx = -1e30f;
#pragma unroll
    for (int p = 0; p < 16; p++) { lg[p] *= tv; mx = fmaxf(mx, lg[p]); }
    float s = 0.f;
#pragma unroll
    for (int p = 0; p < 16; p++) { lg[p] = expf(lg[p] - mx); s += lg[p]; }
    float inv = 1.0f / s;
#pragma unroll
    for (int p = 0; p < 16; p++) lg[p] *= inv;
    float* ob = g_xsa + (long)b * 524288 + h * 1024 + n;
    for (int c = 0; c < 128; c += 8) {
        float acc[8];
#pragma unroll
        for (int dd = 0; dd < 8; dd++) acc[dd] = 0.f;
#pragma unroll
        for (int p = 0; p < 16; p++) {
            float ap = lg[p];
#pragma unroll
            for (int dd = 0; dd < 8; dd++) acc[dd] += ap * vps[c + dd][p];
        }
#pragma unroll
        for (int dd = 0; dd < 8; dd++) ob[(long)(c + dd) * 4096] = acc[dd];
    }
}

// ---------------- depthwise 3x3 (SAME, zero pad) + exact GELU ------------------
__global__ void dwconv_gelu(const float* __restrict__ w, const float* __restrict__ bias) {
    long bo = blockIdx.x;                 // b*2048 + o
    int och = (int)(bo & 2047);
    const float* img = g_t1 + bo * 1024;
    __shared__ float s[1024];
    int tid = threadIdx.x; // 256
    *(float4*)&s[tid * 4] = *(const float4*)&img[tid * 4];
    float wv[9];
#pragma unroll
    for (int k = 0; k < 9; k++) wv[k] = w[och * 9 + k];
    float bb = bias[och];
    __syncthreads();
    float* ob = g_t2 + bo * 1024;
    for (int p = tid; p < 1024; p += 256) {
        int h = p >> 5, ww = p & 31;
        float acc = bb;
#pragma unroll
        for (int i = 0; i < 3; i++) {
            int hh = h + i - 1;
            if (hh < 0 || hh > 31) continue;
#pragma unroll
            for (int j = 0; j < 3; j++) {
                int w2 = ww + j - 1;
                if (w2 < 0 || w2 > 31) continue;
                acc += s[hh * 32 + w2] * wv[i * 3 + j];
            }
        }
        ob[p] = 0.5f * acc * (1.0f + erff(acc * 0.70710678118654752440f));
    }
}

// ---------------- launch ------------------------------------------------------
extern "C" void kernel_launch(void* const* d_in, const int* in_sizes, int n_in,
                              void* d_out_v, int out_size) {
    const float* x      = (const float*)d_in[0];
    const float* qkvv_w = (const float*)d_in[1];
    const float* E_w    = (const float*)d_in[2];
    const float* E_b    = (const float*)d_in[3];
    const float* F_w    = (const float*)d_in[4];
    const float* F_b    = (const float*)d_in[5];
    const float* temp   = (const float*)d_in[6];
    const float* temp2  = (const float*)d_in[7];
    const float* out_w  = (const float*)d_in[8];
    const float* out_b  = (const float*)d_in[9];
    const float* out2_w = (const float*)d_in[10];
    const float* out2_b = (const float*)d_in[11];
    const float* fc1_w  = (const float*)d_in[12];
    const float* fc1_b  = (const float*)d_in[13];
    const float* dw_w   = (const float*)d_in[14];
    const float* dw_b   = (const float*)d_in[15];
    const float* fc2_w  = (const float*)d_in[16];
    const float* fc2_b  = (const float*)d_in[17];
    float* dout = (float*)d_out_v;

    float *p_xf, *p_qkvv, *p_qkvvT, *p_attnca, *p_xca, *p_xsa, *p_t1, *p_t2;
    cudaGetSymbolAddress((void**)&p_xf, g_xf);
    cudaGetSymbolAddress((void**)&p_qkvv, g_qkvv);
    cudaGetSymbolAddress((void**)&p_qkvvT, g_qkvvT);
    cudaGetSymbolAddress((void**)&p_attnca, g_attnca);
    cudaGetSymbolAddress((void**)&p_xca, g_xca);
    cudaGetSymbolAddress((void**)&p_xsa, g_xsa);
    cudaGetSymbolAddress((void**)&p_t1, g_t1);
    cudaGetSymbolAddress((void**)&p_t2, g_t2);

    // 1. pack x -> xf
    pack_xf<<<16384, 128>>>(x);

    // 2. qkvv GEMM: [16384,2048] = xf[16384,512] @ qkvv_w^T
    {
        EpiPlain e{p_qkvv, 0, 2048, nullptr, nullptr};
        gemmT<false, true, EpiPlain><<<dim3(16, 128, 1), 256>>>(
            p_xf, qkvv_w, 16384, 2048, 512, 512, 512, 0, 0, e);
    }

    // 3. transpose to [m][bz][d][n]
    transpose_qkvv<<<dim3(64, 32, 16), dim3(32, 8)>>>();

    // 4. k_proj / v_proj (from un-normalized k, v_sa)
    kv_proj2<<<1024, 256>>>(E_w, E_b, F_w, F_b);

    // 5. L2-normalize q, k rows in place
    norm_scale<<<16384, 256>>>();

    // 6. channel-attn logits: per bz, [128,128] = qn @ kn^T (K=1024)
    {
        EpiPlain e{p_attnca, 128 * 128, 128, nullptr, nullptr};
        gemmT<false, true, EpiPlain><<<dim3(1, 1, 64), 256>>>(
            p_qkvvT, p_qkvvT + 8388608, 128, 128, 1024, 1024, 1024, 131072, 131072, e);
    }

    // 7. softmax (* temp)
    softmax_ca<<<8192, 128>>>(temp);

    // 8. x_ca: per bz, [128,1024] = attn @ v_ca  (K=128)
    {
        EpiPlain e{p_xca, 131072, 1024, nullptr, nullptr};
        gemmT<false, false, EpiPlain><<<dim3(8, 1, 64), 256>>>(
            p_attnca, p_qkvvT + 2 * 8388608, 128, 1024, 128, 128, 1024, 16384, 131072, e);
    }

    // 9. fused spatial attention -> g_xsa
    spatial_attn<<<dim3(8, 64), 128>>>(temp2);

    // 10. LFE fc1: per b, [2048,1024] = fc1_w @ xf_b^T
    {
        EpiPlain e{p_t1, 2097152, 1024, fc1_b, nullptr};
        gemmT<false, true, EpiPlain><<<dim3(8, 16, 16), 256>>>(
            fc1_w, p_xf, 2048, 1024, 512, 512, 512, 0, 524288, e);
    }

    // 11. depthwise conv + GELU
    dwconv_gelu<<<32768, 256>>>(dw_w, dw_b);

    // 12. LFE fc2 -> d_out (assign, includes swap to (B,W,H,C))
    {
        EpiOut e{dout, fc2_b, 0, 0};
        gemmT<true, true, EpiOut><<<dim3(4, 8, 16), 256>>>(
            p_t2, fc2_w, 1024, 512, 2048, 1024, 2048, 2097152, 0, e);
    }

    // 13. out projection (spatial) -> d_out[..., 0:256] +=
    {
        EpiOut e{dout, out_b, 0, 1};
        gemmT<false, true, EpiOut><<<dim3(2, 8, 16), 256>>>(
            p_xsa, out_w, 1024, 256, 512, 512, 512, 524288, 0, e);
    }

    // 14. out2 projection (channel) -> d_out[..., 256:512] +=
    {
        EpiOut e{dout, out2_b, 256, 1};
        gemmT<true, true, EpiOut><<<dim3(2, 8, 16), 256>>>(
            p_xca, out2_w, 1024, 256, 512, 1024, 512, 524288, 0, e);
    }
}

// round 4
// speedup vs baseline: 3.2261x; 1.8927x over previous
#include <cuda_runtime.h>
#include <cuda_fp16.h>
#include <math.h>

// Problem constants
// B=16, W=H=32, C=512, HEADS=4, DH=128, N=1024, P=16, HID=2048
// n = h*32 + w ; BN = B*N = 16384

// ---------------- scratch (device globals; no allocation allowed) -------------
__device__ float g_xf[16384 * 512];        // xf[bn][c]
__device__ float g_qkvv[16384 * 2048];     // qkvv[bn][j]
__device__ float g_qkvvT[4 * 8192 * 1024]; // [m][b*4+h][d][n]
__device__ float g_kproj[64 * 128 * 16];   // [bz][d][p]
__device__ float g_vproj[64 * 128 * 16];
__device__ float g_attnca[64 * 128 * 128]; // [bz][d][e]
__device__ float g_xca[16 * 512 * 1024];   // [b][h*128+d][n]
__device__ float g_xsa[16 * 512 * 1024];   // [b][d*4+h][n]
__device__ float g_t1[16 * 2048 * 1024];   // [b][o][n]
__device__ float g_t2[16 * 2048 * 1024];   // [b][o][n]

// ---------------- epilogues ---------------------------------------------------
struct EpiPlain {
    float* C; long csb; int ldc;
    const float* biasRow; const float* biasCol;
    __device__ __forceinline__ void operator()(int bz, int i, int j, float v) const {
        if (biasRow) v += biasRow[i];
        if (biasCol) v += biasCol[j];
        C[(long)bz * csb + (long)i * ldc + j] = v;
    }
};

// store into d_out (B,W,H,C) with row index n -> (h=n>>5, w=n&31), col offset, opt accumulate
struct EpiOut {
    float* out; const float* bias; int coff; int accum;
    __device__ __forceinline__ void operator()(int b, int n, int j, float v) const {
        v += bias[j];
        int h = n >> 5, w = n & 31;
        long idx = (((long)(b * 32 + w)) * 32 + h) * 512 + coff + j;
        if (accum) out[idx] += v; else out[idx] = v;
    }
};

// ---------------- FP16 tensor-core GEMM, 128x128 block, K-step 32 --------------
// C[i][j] = sum_k A(i,k) * B(j,k), fp32 accumulate, fp16 multiplicands.
// AT=false: A stored (M,K) row-major (k-contiguous).  AT=true: A stored (K,M) (m-contiguous).
// BT=true : B stored (N,K) row-major (k-contiguous).  BT=false: B stored (K,N) (n-contiguous).
//
// smem layouts (bank-conflict-free for stores and half2 fragment loads):
//   k-contiguous operand  : half  S[m][k],  pitch 40 halves (80 B)
//   m/n-contiguous operand: half2 S[k2][m], pitch 136 half2 (544 B), k2 packs (2k,2k+1)
template<bool AT, bool BT, class Epi>
__global__ void __launch_bounds__(256) gemmH(
    const float* __restrict__ A, const float* __restrict__ B,
    int M, int N, int K, int lda, int ldb, long asb, long bsb, Epi epi)
{
    constexpr int ASZ = AT ? (16 * 136 * 4) : (128 * 40 * 2);
    constexpr int BSZ = BT ? (128 * 40 * 2) : (16 * 136 * 4);
    __shared__ __align__(16) unsigned char AsB[ASZ];
    __shared__ __align__(16) unsigned char BsB[BSZ];
    half*  As  = (half*)AsB;   half2* As2 = (half2*)AsB;
    half*  Bs  = (half*)BsB;   half2* Bs2 = (half2*)BsB;

    int bz = blockIdx.z;
    const float* Ab = A + (long)bz * asb;
    const float* Bb = B + (long)bz * bsb;
    int bm = blockIdx.y * 128, bn = blockIdx.x * 128;
    int tid = threadIdx.x;
    int warp = tid >> 5, lane = tid & 31;
    int wm = (warp >> 2) * 64;   // 2 warp rows (64 each)
    int wn = (warp & 3) * 32;    // 4 warp cols (32 each)
    int g = lane >> 2, t = lane & 3;

    float c[4][4][4];
#pragma unroll
    for (int mt = 0; mt < 4; mt++)
#pragma unroll
        for (int nt = 0; nt < 4; nt++)
#pragma unroll
            for (int r = 0; r < 4; r++) c[mt][nt][r] = 0.f;

    float4 pa[4], pb[4];

    // ---- prefetch tile at k0 into registers
    auto pref_a = [&](int k0) {
        if (AT) {
#pragma unroll
            for (int i = 0; i < 2; i++) {
                int item = tid + i * 256;
                int k2 = item >> 5, m4 = (item & 31) << 2;
                pa[2 * i]     = *(const float4*)(Ab + (long)(k0 + 2 * k2)     * lda + bm + m4);
                pa[2 * i + 1] = *(const float4*)(Ab + (long)(k0 + 2 * k2 + 1) * lda + bm + m4);
            }
        } else {
#pragma unroll
            for (int i = 0; i < 4; i++) {
                int item = tid + i * 256;
                int m = item >> 3, k4 = (item & 7) << 2;
                pa[i] = *(const float4*)(Ab + (long)(bm + m) * lda + k0 + k4);
            }
        }
    };
    auto pref_b = [&](int k0) {
        if (BT) {
#pragma unroll
            for (int i = 0; i < 4; i++) {
                int item = tid + i * 256;
                int n = item >> 3, k4 = (item & 7) << 2;
                pb[i] = *(const float4*)(Bb + (long)(bn + n) * ldb + k0 + k4);
            }
        } else {
#pragma unroll
            for (int i = 0; i < 2; i++) {
                int item = tid + i * 256;
                int k2 = item >> 5, n4 = (item & 31) << 2;
                pb[2 * i]     = *(const float4*)(Bb + (long)(k0 + 2 * k2)     * ldb + bn + n4);
                pb[2 * i + 1] = *(const float4*)(Bb + (long)(k0 + 2 * k2 + 1) * ldb + bn + n4);
            }
        }
    };

    pref_a(0); pref_b(0);

    for (int k0 = 0; k0 < K; k0 += 32) {
        __syncthreads();   // previous compute done before overwriting smem
        // ---- store prefetched tile to smem (cvt to half)
        if (AT) {
#pragma unroll
            for (int i = 0; i < 2; i++) {
                int item = tid + i * 256;
                int k2 = item >> 5, m4 = (item & 31) << 2;
                float4 v0 = pa[2 * i], v1 = pa[2 * i + 1];
                half2* dst = &As2[k2 * 136 + m4];
                dst[0] = __floats2half2_rn(v0.x, v1.x);
                dst[1] = __floats2half2_rn(v0.y, v1.y);
                dst[2] = __floats2half2_rn(v0.z, v1.z);
                dst[3] = __floats2half2_rn(v0.w, v1.w);
            }
        } else {
#pragma unroll
            for (int i = 0; i < 4; i++) {
                int item = tid + i * 256;
                int m = item >> 3, k4 = (item & 7) << 2;
                float4 v = pa[i];
                half2* dst = (half2*)(As + m * 40 + k4);
                dst[0] = __floats2half2_rn(v.x, v.y);
                dst[1] = __floats2half2_rn(v.z, v.w);
            }
        }
        if (BT) {
#pragma unroll
            for (int i = 0; i < 4; i++) {
                int item = tid + i * 256;
                int n = item >> 3, k4 = (item & 7) << 2;
                float4 v = pb[i];
                half2* dst = (half2*)(Bs + n * 40 + k4);
                dst[0] = __floats2half2_rn(v.x, v.y);
                dst[1] = __floats2half2_rn(v.z, v.w);
            }
        } else {
#pragma unroll
            for (int i = 0; i < 2; i++) {
                int item = tid + i * 256;
                int k2 = item >> 5, n4 = (item & 31) << 2;
                float4 v0 = pb[2 * i], v1 = pb[2 * i + 1];
                half2* dst = &Bs2[k2 * 136 + n4];
                dst[0] = __floats2half2_rn(v0.x, v1.x);
                dst[1] = __floats2half2_rn(v0.y, v1.y);
                dst[2] = __floats2half2_rn(v0.z, v1.z);
                dst[3] = __floats2half2_rn(v0.w, v1.w);
            }
        }
        __syncthreads();

        // ---- prefetch next tile
        if (k0 + 32 < K) { pref_a(k0 + 32); pref_b(k0 + 32); }

        // ---- compute 2 k-chunks of 16
#pragma unroll
        for (int kc = 0; kc < 2; kc++) {
            int kb = kc * 16;   // half index base (k-contig layout)
            int kb2 = kc * 8;   // half2 row base (m-contig layout)
            unsigned af[4][4], bf[4][2];
#pragma unroll
            for (int mt = 0; mt < 4; mt++) {
                int m0 = wm + mt * 16 + g;
                if (AT) {
                    af[mt][0] = *(const unsigned*)&As2[(kb2 + t) * 136 + m0];
                    af[mt][1] = *(const unsigned*)&As2[(kb2 + t) * 136 + m0 + 8];
                    af[mt][2] = *(const unsigned*)&As2[(kb2 + t + 4) * 136 + m0];
                    af[mt][3] = *(const unsigned*)&As2[(kb2 + t + 4) * 136 + m0 + 8];
                } else {
                    af[mt][0] = *(const unsigned*)(As + m0 * 40 + kb + 2 * t);
                    af[mt][1] = *(const unsigned*)(As + (m0 + 8) * 40 + kb + 2 * t);
                    af[mt][2] = *(const unsigned*)(As + m0 * 40 + kb + 2 * t + 8);
                    af[mt][3] = *(const unsigned*)(As + (m0 + 8) * 40 + kb + 2 * t + 8);
                }
            }
#pragma unroll
            for (int nt = 0; nt < 4; nt++) {
                int n0 = wn + nt * 8 + g;
                if (BT) {
                    bf[nt][0] = *(const unsigned*)(Bs + n0 * 40 + kb + 2 * t);
                    bf[nt][1] = *(const unsigned*)(Bs + n0 * 40 + kb + 2 * t + 8);
                } else {
                    bf[nt][0] = *(const unsigned*)&Bs2[(kb2 + t) * 136 + n0];
                    bf[nt][1] = *(const unsigned*)&Bs2[(kb2 + t + 4) * 136 + n0];
                }
            }
#pragma unroll
            for (int mt = 0; mt < 4; mt++)
#pragma unroll
                for (int nt = 0; nt < 4; nt++) {
                    asm volatile(
                        "mma.sync.aligned.m16n8k16.row.col.f32.f16.f16.f32 "
                        "{%0,%1,%2,%3},{%4,%5,%6,%7},{%8,%9},{%0,%1,%2,%3};\n"
                        : "+f"(c[mt][nt][0]), "+f"(c[mt][nt][1]),
                          "+f"(c[mt][nt][2]), "+f"(c[mt][nt][3])
                        : "r"(af[mt][0]), "r"(af[mt][1]), "r"(af[mt][2]), "r"(af[mt][3]),
                          "r"(bf[nt][0]), "r"(bf[nt][1]));
                }
        }
    }

    // ---- epilogue
#pragma unroll
    for (int mt = 0; mt < 4; mt++)
#pragma unroll
        for (int nt = 0; nt < 4; nt++) {
            int i = wm + mt * 16 + g;
            int j = wn + nt * 8 + t * 2;
            epi(bz, bm + i,     bn + j,     c[mt][nt][0]);
            epi(bz, bm + i,     bn + j + 1, c[mt][nt][1]);
            epi(bz, bm + i + 8, bn + j,     c[mt][nt][2]);
            epi(bz, bm + i + 8, bn + j + 1, c[mt][nt][3]);
        }
}

// ---------------- pack: x (B,W,H,C) -> xf[bn][c], n=h*32+w ---------------------
__global__ void pack_xf(const float* __restrict__ x) {
    int blk = blockIdx.x;                  // dst row = b*1024 + n
    int b = blk >> 10, n = blk & 1023;
    int h = n >> 5, w = n & 31;
    const float* src = x + (((long)(b * 32 + w)) * 32 + h) * 512;
    float* dst = g_xf + (long)blk * 512;
    int t = threadIdx.x; // 128
    *(float4*)&dst[t * 4] = *(const float4*)&src[t * 4];
}

// ---------------- transpose qkvv[bn][j] -> g_qkvvT[m][b*4+h][d][n] ------------
__global__ void transpose_qkvv() {
    __shared__ float tile[32][33];
    int b = blockIdx.z;
    int j0 = blockIdx.x * 32, n0 = blockIdx.y * 32;
    int tx = threadIdx.x, ty = threadIdx.y; // 32 x 8
#pragma unroll
    for (int r = 0; r < 32; r += 8)
        tile[ty + r][tx] = g_qkvv[((long)(b * 1024 + n0 + ty + r)) * 2048 + j0 + tx];
    __syncthreads();
#pragma unroll
    for (int r = 0; r < 32; r += 8) {
        int j = j0 + ty + r;
        int n = n0 + tx;
        int m = j >> 9, hh = (j >> 7) & 3, d = j & 127;
        g_qkvvT[((long)(m * 64 + b * 4 + hh)) * 131072 + (long)d * 1024 + n] = tile[tx][ty + r];
    }
}

// ---------------- k_proj / v_proj: float4 MLP + 2 rows/warp --------------------
// grid: src(2) x phalf(2) x rowblocks(256) = 1024 blocks; 256 threads
__global__ void __launch_bounds__(256) kv_proj3(
    const float* __restrict__ E_w, const float* __restrict__ E_b,
    const float* __restrict__ F_w, const float* __restrict__ F_b)
{
    __shared__ float Ws[8][1024];   // 32 KB
    int blk = blockIdx.x;
    int src = blk >> 9;            // 0 = k (m=1), 1 = v_sa (m=3)
    int ph  = (blk >> 8) & 1;      // p half
    int row0 = (blk & 255) * 32;
    const float* W = (src ? F_w : E_w) + ph * 8 * 1024;
    const float* bias = (src ? F_b : E_b) + ph * 8;

    for (int i = threadIdx.x; i < 2048; i += 256)
        *(float4*)&Ws[0][i * 4] = *(const float4*)&W[i * 4];
    __syncthreads();

    int warp = threadIdx.x >> 5, lane = threadIdx.x & 31;
    const float* basep = g_qkvvT + (long)(src ? 3 : 1) * 8388608;
#pragma unroll
    for (int pass = 0; pass < 2; pass++) {
        int rem = row0 + pass * 16 + warp * 2;   // rows rem, rem+1
        const float* r0 = basep + (long)rem * 1024;
        const float* r1 = r0 + 1024;
        float a0[8], a1[8];
#pragma unroll
        for (int p = 0; p < 8; p++) { a0[p] = 0.f; a1[p] = 0.f; }
#pragma unroll
        for (int i = 0; i < 8; i++) {
            int n0 = i * 128 + lane * 4;
            float4 v0 = *(const float4*)&r0[n0];
            float4 v1 = *(const float4*)&r1[n0];
#pragma unroll
            for (int p = 0; p < 8; p++) {
                float4 w = *(const float4*)&Ws[p][n0];
                a0[p] += v0.x * w.x + v0.y * w.y + v0.z * w.z + v0.w * w.w;
                a1[p] += v1.x * w.x + v1.y * w.y + v1.z * w.z + v1.w * w.w;
            }
        }
#pragma unroll
        for (int p = 0; p < 8; p++) {
#pragma unroll
            for (int o = 16; o > 0; o >>= 1) {
                a0[p] += __shfl_xor_sync(0xffffffffu, a0[p], o);
                a1[p] += __shfl_xor_sync(0xffffffffu, a1[p], o);
            }
        }
        if (lane == 0) {
            float* o = (src ? g_vproj : g_kproj) + (long)rem * 16 + ph * 8;
#pragma unroll
            for (int p = 0; p < 8; p++) { o[p] = a0[p] + bias[p]; o[16 + p] = a1[p] + bias[p]; }
        }
    }
}

// ---------------- L2-normalize q and k rows in place ---------------------------
__global__ void norm_scale() {
    int r = blockIdx.x;                       // 0..16383 (m=0 rows then m=1 rows)
    float* row = g_qkvvT + (long)r * 1024;
    int t = threadIdx.x; // 256
    float4 v = *(float4*)&row[t * 4];
    float s = v.x * v.x + v.y * v.y + v.z * v.z + v.w * v.w;
    __shared__ float sd[256];
    sd[t] = s; __syncthreads();
    for (int o = 128; o > 0; o >>= 1) { if (t < o) sd[t] += sd[t + o]; __syncthreads(); }
    float inv = 1.0f / fmaxf(sqrtf(sd[0]), 1e-12f);
    v.x *= inv; v.y *= inv; v.z *= inv; v.w *= inv;
    *(float4*)&row[t * 4] = v;
}

// ---------------- softmax over e (128) for channel attention -------------------
__global__ void softmax_ca(const float* __restrict__ temp) {
    int r = blockIdx.x;           // bz*128 + d, 8192 rows
    int h = (r >> 7) & 3;
    float tv = temp[h];
    float* row = g_attnca + (long)r * 128;
    int t = threadIdx.x; // 128
    float v = row[t] * tv;
    __shared__ float sd[128];
    sd[t] = v; __syncthreads();
    for (int o = 64; o > 0; o >>= 1) { if (t < o) sd[t] = fmaxf(sd[t], sd[t + o]); __syncthreads(); }
    float mx = sd[0]; __syncthreads();
    float e = expf(v - mx);
    sd[t] = e; __syncthreads();
    for (int o = 64; o > 0; o >>= 1) { if (t < o) sd[t] += sd[t + o]; __syncthreads(); }
    row[t] = e / sd[0];
}

// ---------------- fused projected spatial attention ----------------------------
__global__ void spatial_attn(const float* __restrict__ temp2) {
    int bz = blockIdx.y; int b = bz >> 2, h = bz & 3;
    int n = blockIdx.x * 128 + threadIdx.x;
    __shared__ float kps[128][16];
    __shared__ float vps[128][16];
    const float* kpb = g_kproj + (long)bz * 2048;
    const float* vpb = g_vproj + (long)bz * 2048;
    for (int i = threadIdx.x; i < 2048; i += 128) {
        kps[i >> 4][i & 15] = kpb[i];
        vps[i >> 4][i & 15] = vpb[i];
    }
    __syncthreads();
    const float* q = g_qkvvT + (long)bz * 131072 + n; // m=0 (normalized q)
    float lg[16];
#pragma unroll
    for (int p = 0; p < 16; p++) lg[p] = 0.f;
    for (int d = 0; d < 128; d++) {
        float qv = q[(long)d * 1024];
#pragma unroll
        for (int p = 0; p < 16; p++) lg[p] += qv * kps[d][p];
    }
    float tv = temp2[h];
    float mx = -1e30f;
#pragma unroll
    for (int p = 0; p < 16; p++) { lg[p] *= tv; mx = fmaxf(mx, lg[p]); }
    float s = 0.f;
#pragma unroll
    for (int p = 0; p < 16; p++) { lg[p] = expf(lg[p] - mx); s += lg[p]; }
    float inv = 1.0f / s;
#pragma unroll
    for (int p = 0; p < 16; p++) lg[p] *= inv;
    float* ob = g_xsa + (long)b * 524288 + h * 1024 + n;
    for (int c = 0; c < 128; c += 8) {
        float acc[8];
#pragma unroll
        for (int dd = 0; dd < 8; dd++) acc[dd] = 0.f;
#pragma unroll
        for (int p = 0; p < 16; p++) {
            float ap = lg[p];
#pragma unroll
            for (int dd = 0; dd < 8; dd++) acc[dd] += ap * vps[c + dd][p];
        }
#pragma unroll
        for (int dd = 0; dd < 8; dd++) ob[(long)(c + dd) * 4096] = acc[dd];
    }
}

// ---------------- depthwise 3x3 (SAME, zero pad) + exact GELU ------------------
__global__ void dwconv_gelu(const float* __restrict__ w, const float* __restrict__ bias) {
    long bo = blockIdx.x;                 // b*2048 + o
    int och = (int)(bo & 2047);
    const float* img = g_t1 + bo * 1024;
    __shared__ float s[1024];
    int tid = threadIdx.x; // 256
    *(float4*)&s[tid * 4] = *(const float4*)&img[tid * 4];
    float wv[9];
#pragma unroll
    for (int k = 0; k < 9; k++) wv[k] = w[och * 9 + k];
    float bb = bias[och];
    __syncthreads();
    float* ob = g_t2 + bo * 1024;
    for (int p = tid; p < 1024; p += 256) {
        int h = p >> 5, ww = p & 31;
        float acc = bb;
#pragma unroll
        for (int i = 0; i < 3; i++) {
            int hh = h + i - 1;
            if (hh < 0 || hh > 31) continue;
#pragma unroll
            for (int j = 0; j < 3; j++) {
                int w2 = ww + j - 1;
                if (w2 < 0 || w2 > 31) continue;
                acc += s[hh * 32 + w2] * wv[i * 3 + j];
            }
        }
        ob[p] = 0.5f * acc * (1.0f + erff(acc * 0.70710678118654752440f));
    }
}

// ---------------- launch ------------------------------------------------------
extern "C" void kernel_launch(void* const* d_in, const int* in_sizes, int n_in,
                              void* d_out_v, int out_size) {
    const float* x      = (const float*)d_in[0];
    const float* qkvv_w = (const float*)d_in[1];
    const float* E_w    = (const float*)d_in[2];
    const float* E_b    = (const float*)d_in[3];
    const float* F_w    = (const float*)d_in[4];
    const float* F_b    = (const float*)d_in[5];
    const float* temp   = (const float*)d_in[6];
    const float* temp2  = (const float*)d_in[7];
    const float* out_w  = (const float*)d_in[8];
    const float* out_b  = (const float*)d_in[9];
    const float* out2_w = (const float*)d_in[10];
    const float* out2_b = (const float*)d_in[11];
    const float* fc1_w  = (const float*)d_in[12];
    const float* fc1_b  = (const float*)d_in[13];
    const float* dw_w   = (const float*)d_in[14];
    const float* dw_b   = (const float*)d_in[15];
    const float* fc2_w  = (const float*)d_in[16];
    const float* fc2_b  = (const float*)d_in[17];
    float* dout = (float*)d_out_v;

    float *p_xf, *p_qkvv, *p_qkvvT, *p_attnca, *p_xca, *p_xsa, *p_t1, *p_t2;
    cudaGetSymbolAddress((void**)&p_xf, g_xf);
    cudaGetSymbolAddress((void**)&p_qkvv, g_qkvv);
    cudaGetSymbolAddress((void**)&p_qkvvT, g_qkvvT);
    cudaGetSymbolAddress((void**)&p_attnca, g_attnca);
    cudaGetSymbolAddress((void**)&p_xca, g_xca);
    cudaGetSymbolAddress((void**)&p_xsa, g_xsa);
    cudaGetSymbolAddress((void**)&p_t1, g_t1);
    cudaGetSymbolAddress((void**)&p_t2, g_t2);

    // 1. pack x -> xf
    pack_xf<<<16384, 128>>>(x);

    // 2. qkvv GEMM: [16384,2048] = xf[16384,512] @ qkvv_w^T
    {
        EpiPlain e{p_qkvv, 0, 2048, nullptr, nullptr};
        gemmH<false, true, EpiPlain><<<dim3(16, 128, 1), 256>>>(
            p_xf, qkvv_w, 16384, 2048, 512, 512, 512, 0, 0, e);
    }

    // 3. transpose to [m][bz][d][n]
    transpose_qkvv<<<dim3(64, 32, 16), dim3(32, 8)>>>();

    // 4. k_proj / v_proj (from un-normalized k, v_sa)
    kv_proj3<<<1024, 256>>>(E_w, E_b, F_w, F_b);

    // 5. L2-normalize q, k rows in place
    norm_scale<<<16384, 256>>>();

    // 6. channel-attn logits: per bz, [128,128] = qn @ kn^T (K=1024)
    {
        EpiPlain e{p_attnca, 128 * 128, 128, nullptr, nullptr};
        gemmH<false, true, EpiPlain><<<dim3(1, 1, 64), 256>>>(
            p_qkvvT, p_qkvvT + 8388608, 128, 128, 1024, 1024, 1024, 131072, 131072, e);
    }

    // 7. softmax (* temp)
    softmax_ca<<<8192, 128>>>(temp);

    // 8. x_ca: per bz, [128,1024] = attn @ v_ca  (K=128)
    {
        EpiPlain e{p_xca, 131072, 1024, nullptr, nullptr};
        gemmH<false, false, EpiPlain><<<dim3(8, 1, 64), 256>>>(
            p_attnca, p_qkvvT + 2 * 8388608, 128, 1024, 128, 128, 1024, 16384, 131072, e);
    }

    // 9. fused spatial attention -> g_xsa
    spatial_attn<<<dim3(8, 64), 128>>>(temp2);

    // 10. LFE fc1: per b, [2048,1024] = fc1_w @ xf_b^T
    {
        EpiPlain e{p_t1, 2097152, 1024, fc1_b, nullptr};
        gemmH<false, true, EpiPlain><<<dim3(8, 16, 16), 256>>>(
            fc1_w, p_xf, 2048, 1024, 512, 512, 512, 0, 524288, e);
    }

    // 11. depthwise conv + GELU
    dwconv_gelu<<<32768, 256>>>(dw_w, dw_b);

    // 12. LFE fc2 -> d_out (assign, includes swap to (B,W,H,C))
    {
        EpiOut e{dout, fc2_b, 0, 0};
        gemmH<true, true, EpiOut><<<dim3(4, 8, 16), 256>>>(
            p_t2, fc2_w, 1024, 512, 2048, 1024, 2048, 2097152, 0, e);
    }

    // 13. out projection (spatial) -> d_out[..., 0:256] +=
    {
        EpiOut e{dout, out_b, 0, 1};
        gemmH<false, true, EpiOut><<<dim3(2, 8, 16), 256>>>(
            p_xsa, out_w, 1024, 256, 512, 512, 512, 524288, 0, e);
    }

    // 14. out2 projection (channel) -> d_out[..., 256:512] +=
    {
        EpiOut e{dout, out2_b, 256, 1};
        gemmH<true, true, EpiOut><<<dim3(2, 8, 16), 256>>>(
            p_xca, out2_w, 1024, 256, 512, 1024, 512, 524288, 0, e);
    }
}

// round 5
// speedup vs baseline: 3.3269x; 1.0312x over previous
#include <cuda_runtime.h>
#include <cuda_fp16.h>
#include <math.h>

// Problem constants
// B=16, W=H=32, C=512, HEADS=4, DH=128, N=1024, P=16, HID=2048
// n = h*32 + w ; BN = B*N = 16384

// ---------------- scratch (device globals; no allocation allowed) -------------
__device__ float g_xf[16384 * 512];        // xf[bn][c]
__device__ float g_qkvvT[4 * 8192 * 1024]; // [m][b*4+h][d][n]
__device__ float g_kproj[64 * 128 * 16];   // [bz][d][p]
__device__ float g_vproj[64 * 128 * 16];
__device__ float g_attnca[64 * 128 * 128]; // [bz][d][e]
__device__ float g_xca[16 * 512 * 1024];   // [b][h*128+d][n]
__device__ float g_xsa[16 * 512 * 1024];   // [b][d*4+h][n]
__device__ float g_t1[16 * 2048 * 1024];   // [b][o][n]
__device__ float g_t2[16 * 2048 * 1024];   // [b][o][n]

// ---------------- epilogues ---------------------------------------------------
struct EpiPlain {
    float* C; long csb; int ldc;
    const float* biasRow; const float* biasCol;
    __device__ __forceinline__ void operator()(int bz, int i, int j, float v) const {
        if (biasRow) v += biasRow[i];
        if (biasCol) v += biasCol[j];
        C[(long)bz * csb + (long)i * ldc + j] = v;
    }
};

// qkvv direct-to-transposed: i = weight row j (0..2047) -> (m, h, d); j = n
struct EpiQT {
    float* out;  // g_qkvvT
    __device__ __forceinline__ void operator()(int b, int i, int j, float v) const {
        int m = i >> 9, hh = (i >> 7) & 3, d = i & 127;
        out[((long)(m * 64 + b * 4 + hh)) * 131072 + (long)d * 1024 + j] = v;
    }
};

// store into d_out (B,W,H,C) with row index n -> (h=n>>5, w=n&31), col offset, opt accumulate
struct EpiOut {
    float* out; const float* bias; int coff; int accum;
    __device__ __forceinline__ void operator()(int b, int n, int j, float v) const {
        v += bias[j];
        int h = n >> 5, w = n & 31;
        long idx = (((long)(b * 32 + w)) * 32 + h) * 512 + coff + j;
        if (accum) out[idx] += v; else out[idx] = v;
    }
};

// ---------------- FP16 tensor-core GEMM, 128x128 block, K-step 32 --------------
// C[i][j] = sum_k A(i,k) * B(j,k), fp32 accumulate, fp16 multiplicands.
// AT=false: A stored (M,K) row-major (k-contiguous).  AT=true: A stored (K,M) (m-contiguous).
// BT=true : B stored (N,K) row-major (k-contiguous).  BT=false: B stored (K,N) (n-contiguous).
//
// smem layouts:
//   k-contiguous operand  : half  S[m][k],  pitch 40 halves (80 B)   -> ldmatrix loads
//   m/n-contiguous operand: half2 S[k2][m], pitch 136 half2 (544 B)  -> scalar LDS loads
template<bool AT, bool BT, class Epi>
__global__ void __launch_bounds__(256) gemmH(
    const float* __restrict__ A, const float* __restrict__ B,
    int M, int N, int K, int lda, int ldb, long asb, long bsb, Epi epi)
{
    constexpr int ASZ = AT ? (16 * 136 * 4) : (128 * 40 * 2);
    constexpr int BSZ = BT ? (128 * 40 * 2) : (16 * 136 * 4);
    __shared__ __align__(16) unsigned char AsB[ASZ];
    __shared__ __align__(16) unsigned char BsB[BSZ];
    half*  As  = (half*)AsB;   half2* As2 = (half2*)AsB;
    half*  Bs  = (half*)BsB;   half2* Bs2 = (half2*)BsB;
    unsigned AsU = (unsigned)__cvta_generic_to_shared(AsB);
    unsigned BsU = (unsigned)__cvta_generic_to_shared(BsB);

    int bz = blockIdx.z;
    const float* Ab = A + (long)bz * asb;
    const float* Bb = B + (long)bz * bsb;
    int bm = blockIdx.y * 128, bn = blockIdx.x * 128;
    int tid = threadIdx.x;
    int warp = tid >> 5, lane = tid & 31;
    int wm = (warp >> 2) * 64;   // 2 warp rows (64 each)
    int wn = (warp & 3) * 32;    // 4 warp cols (32 each)
    int g = lane >> 2, t = lane & 3;

    float c[4][4][4];
#pragma unroll
    for (int mt = 0; mt < 4; mt++)
#pragma unroll
        for (int nt = 0; nt < 4; nt++)
#pragma unroll
            for (int r = 0; r < 4; r++) c[mt][nt][r] = 0.f;

    float4 pa[4], pb[4];

    auto pref_a = [&](int k0) {
        if (AT) {
#pragma unroll
            for (int i = 0; i < 2; i++) {
                int item = tid + i * 256;
                int k2 = item >> 5, m4 = (item & 31) << 2;
                pa[2 * i]     = *(const float4*)(Ab + (long)(k0 + 2 * k2)     * lda + bm + m4);
                pa[2 * i + 1] = *(const float4*)(Ab + (long)(k0 + 2 * k2 + 1) * lda + bm + m4);
            }
        } else {
#pragma unroll
            for (int i = 0; i < 4; i++) {
                int item = tid + i * 256;
                int m = item >> 3, k4 = (item & 7) << 2;
                pa[i] = *(const float4*)(Ab + (long)(bm + m) * lda + k0 + k4);
            }
        }
    };
    auto pref_b = [&](int k0) {
        if (BT) {
#pragma unroll
            for (int i = 0; i < 4; i++) {
                int item = tid + i * 256;
                int n = item >> 3, k4 = (item & 7) << 2;
                pb[i] = *(const float4*)(Bb + (long)(bn + n) * ldb + k0 + k4);
            }
        } else {
#pragma unroll
            for (int i = 0; i < 2; i++) {
                int item = tid + i * 256;
                int k2 = item >> 5, n4 = (item & 31) << 2;
                pb[2 * i]     = *(const float4*)(Bb + (long)(k0 + 2 * k2)     * ldb + bn + n4);
                pb[2 * i + 1] = *(const float4*)(Bb + (long)(k0 + 2 * k2 + 1) * ldb + bn + n4);
            }
        }
    };

    pref_a(0); pref_b(0);

    for (int k0 = 0; k0 < K; k0 += 32) {
        __syncthreads();
        // ---- store prefetched tile to smem (cvt to half)
        if (AT) {
#pragma unroll
            for (int i = 0; i < 2; i++) {
                int item = tid + i * 256;
                int k2 = item >> 5, m4 = (item & 31) << 2;
                float4 v0 = pa[2 * i], v1 = pa[2 * i + 1];
                half2* dst = &As2[k2 * 136 + m4];
                dst[0] = __floats2half2_rn(v0.x, v1.x);
                dst[1] = __floats2half2_rn(v0.y, v1.y);
                dst[2] = __floats2half2_rn(v0.z, v1.z);
                dst[3] = __floats2half2_rn(v0.w, v1.w);
            }
        } else {
#pragma unroll
            for (int i = 0; i < 4; i++) {
                int item = tid + i * 256;
                int m = item >> 3, k4 = (item & 7) << 2;
                float4 v = pa[i];
                half2* dst = (half2*)(As + m * 40 + k4);
                dst[0] = __floats2half2_rn(v.x, v.y);
                dst[1] = __floats2half2_rn(v.z, v.w);
            }
        }
        if (BT) {
#pragma unroll
            for (int i = 0; i < 4; i++) {
                int item = tid + i * 256;
                int n = item >> 3, k4 = (item & 7) << 2;
                float4 v = pb[i];
                half2* dst = (half2*)(Bs + n * 40 + k4);
                dst[0] = __floats2half2_rn(v.x, v.y);
                dst[1] = __floats2half2_rn(v.z, v.w);
            }
        } else {
#pragma unroll
            for (int i = 0; i < 2; i++) {
                int item = tid + i * 256;
                int k2 = item >> 5, n4 = (item & 31) << 2;
                float4 v0 = pb[2 * i], v1 = pb[2 * i + 1];
                half2* dst = &Bs2[k2 * 136 + n4];
                dst[0] = __floats2half2_rn(v0.x, v1.x);
                dst[1] = __floats2half2_rn(v0.y, v1.y);
                dst[2] = __floats2half2_rn(v0.z, v1.z);
                dst[3] = __floats2half2_rn(v0.w, v1.w);
            }
        }
        __syncthreads();

        // ---- prefetch next tile
        if (k0 + 32 < K) { pref_a(k0 + 32); pref_b(k0 + 32); }

        // ---- compute 2 k-chunks of 16
#pragma unroll
        for (int kc = 0; kc < 2; kc++) {
            int kb = kc * 16;   // half index base (k-contig layout)
            int kb2 = kc * 8;   // half2 row base (m-contig layout)
            unsigned af[4][4], bf[4][2];
            if (!AT) {
                // ldmatrix x4: matrix0 rows m0..7 @kb, m1 rows m0+8..15 @kb,
                //              m2 rows m0..7 @kb+8, m3 rows m0+8..15 @kb+8
#pragma unroll
                for (int mt = 0; mt < 4; mt++) {
                    int row = wm + mt * 16 + (lane & 15);
                    int kof = kb + ((lane >> 4) << 3);
                    unsigned addr = AsU + ((row * 40 + kof) << 1);
                    asm volatile(
                        "ldmatrix.sync.aligned.m8n8.x4.shared.b16 {%0,%1,%2,%3}, [%4];"
                        : "=r"(af[mt][0]), "=r"(af[mt][1]), "=r"(af[mt][2]), "=r"(af[mt][3])
                        : "r"(addr));
                }
            } else {
#pragma unroll
                for (int mt = 0; mt < 4; mt++) {
                    int m0 = wm + mt * 16 + g;
                    af[mt][0] = *(const unsigned*)&As2[(kb2 + t) * 136 + m0];
                    af[mt][1] = *(const unsigned*)&As2[(kb2 + t) * 136 + m0 + 8];
                    af[mt][2] = *(const unsigned*)&As2[(kb2 + t + 4) * 136 + m0];
                    af[mt][3] = *(const unsigned*)&As2[(kb2 + t + 4) * 136 + m0 + 8];
                }
            }
            if (BT) {
                // ldmatrix x4 covers 2 nt: lanes 0-7 nt(2p) @kb, 8-15 nt(2p) @kb+8,
                //                          16-23 nt(2p+1) @kb, 24-31 nt(2p+1) @kb+8
#pragma unroll
                for (int p = 0; p < 2; p++) {
                    int nt = 2 * p + (lane >> 4);
                    int row = wn + nt * 8 + (lane & 7);
                    int kof = kb + (((lane >> 3) & 1) << 3);
                    unsigned addr = BsU + ((row * 40 + kof) << 1);
                    asm volatile(
                        "ldmatrix.sync.aligned.m8n8.x4.shared.b16 {%0,%1,%2,%3}, [%4];"
                        : "=r"(bf[2 * p][0]), "=r"(bf[2 * p][1]),
                          "=r"(bf[2 * p + 1][0]), "=r"(bf[2 * p + 1][1])
                        : "r"(addr));
                }
            } else {
#pragma unroll
                for (int nt = 0; nt < 4; nt++) {
                    int n0 = wn + nt * 8 + g;
                    bf[nt][0] = *(const unsigned*)&Bs2[(kb2 + t) * 136 + n0];
                    bf[nt][1] = *(const unsigned*)&Bs2[(kb2 + t + 4) * 136 + n0];
                }
            }
#pragma unroll
            for (int mt = 0; mt < 4; mt++)
#pragma unroll
                for (int nt = 0; nt < 4; nt++) {
                    asm volatile(
                        "mma.sync.aligned.m16n8k16.row.col.f32.f16.f16.f32 "
                        "{%0,%1,%2,%3},{%4,%5,%6,%7},{%8,%9},{%0,%1,%2,%3};\n"
                        : "+f"(c[mt][nt][0]), "+f"(c[mt][nt][1]),
                          "+f"(c[mt][nt][2]), "+f"(c[mt][nt][3])
                        : "r"(af[mt][0]), "r"(af[mt][1]), "r"(af[mt][2]), "r"(af[mt][3]),
                          "r"(bf[nt][0]), "r"(bf[nt][1]));
                }
        }
    }

    // ---- epilogue
#pragma unroll
    for (int mt = 0; mt < 4; mt++)
#pragma unroll
        for (int nt = 0; nt < 4; nt++) {
            int i = wm + mt * 16 + g;
            int j = wn + nt * 8 + t * 2;
            epi(bz, bm + i,     bn + j,     c[mt][nt][0]);
            epi(bz, bm + i,     bn + j + 1, c[mt][nt][1]);
            epi(bz, bm + i + 8, bn + j,     c[mt][nt][2]);
            epi(bz, bm + i + 8, bn + j + 1, c[mt][nt][3]);
        }
}

// ---------------- pack: x (B,W,H,C) -> xf[bn][c], n=h*32+w ---------------------
__global__ void pack_xf(const float* __restrict__ x) {
    int blk = blockIdx.x;                  // dst row = b*1024 + n
    int b = blk >> 10, n = blk & 1023;
    int h = n >> 5, w = n & 31;
    const float* src = x + (((long)(b * 32 + w)) * 32 + h) * 512;
    float* dst = g_xf + (long)blk * 512;
    int t = threadIdx.x; // 128
    *(float4*)&dst[t * 4] = *(const float4*)&src[t * 4];
}

// ---------------- k_proj / v_proj: row preload, no spill -----------------------
// grid: src(2) x phalf(2) x rowblocks(256) = 1024 blocks; 256 threads
__global__ void __launch_bounds__(256) kv_proj4(
    const float* __restrict__ E_w, const float* __restrict__ E_b,
    const float* __restrict__ F_w, const float* __restrict__ F_b)
{
    __shared__ float Ws[8][1024];   // 32 KB
    int blk = blockIdx.x;
    int src = blk >> 9;            // 0 = k (m=1), 1 = v_sa (m=3)
    int ph  = (blk >> 8) & 1;      // p half
    int row0 = (blk & 255) * 32;
    const float* W = (src ? F_w : E_w) + ph * 8 * 1024;
    const float* bias = (src ? F_b : E_b) + ph * 8;

    for (int i = threadIdx.x; i < 2048; i += 256)
        *(float4*)&Ws[0][i * 4] = *(const float4*)&W[i * 4];
    __syncthreads();

    int warp = threadIdx.x >> 5, lane = threadIdx.x & 31;
    const float* basep = g_qkvvT + (long)(src ? 3 : 1) * 8388608;
    float* outb = (src ? g_vproj : g_kproj);
#pragma unroll
    for (int rr = 0; rr < 4; rr++) {
        int rem = row0 + rr * 8 + warp;          // bz*128 + d
        const float* rp = basep + (long)rem * 1024;
        float4 v[8];
#pragma unroll
        for (int i = 0; i < 8; i++) v[i] = *(const float4*)&rp[i * 128 + lane * 4];
        float acc[8];
#pragma unroll
        for (int p = 0; p < 8; p++) {
            float s = 0.f;
#pragma unroll
            for (int i = 0; i < 8; i++) {
                float4 w = *(const float4*)&Ws[p][i * 128 + lane * 4];
                s += v[i].x * w.x + v[i].y * w.y + v[i].z * w.z + v[i].w * w.w;
            }
            acc[p] = s;
        }
#pragma unroll
        for (int p = 0; p < 8; p++) {
#pragma unroll
            for (int o = 16; o > 0; o >>= 1) acc[p] += __shfl_xor_sync(0xffffffffu, acc[p], o);
        }
        if (lane == 0) {
            float* o = outb + (long)rem * 16 + ph * 8;
#pragma unroll
            for (int p = 0; p < 8; p++) o[p] = acc[p] + bias[p];
        }
    }
}

// ---------------- L2-normalize q and k rows in place ---------------------------
__global__ void norm_scale() {
    int r = blockIdx.x;                       // 0..16383 (m=0 rows then m=1 rows)
    float* row = g_qkvvT + (long)r * 1024;
    int t = threadIdx.x; // 256
    float4 v = *(float4*)&row[t * 4];
    float s = v.x * v.x + v.y * v.y + v.z * v.z + v.w * v.w;
    __shared__ float sd[256];
    sd[t] = s; __syncthreads();
    for (int o = 128; o > 0; o >>= 1) { if (t < o) sd[t] += sd[t + o]; __syncthreads(); }
    float inv = 1.0f / fmaxf(sqrtf(sd[0]), 1e-12f);
    v.x *= inv; v.y *= inv; v.z *= inv; v.w *= inv;
    *(float4*)&row[t * 4] = v;
}

// ---------------- softmax over e (128) for channel attention -------------------
__global__ void softmax_ca(const float* __restrict__ temp) {
    int r = blockIdx.x;           // bz*128 + d, 8192 rows
    int h = (r >> 7) & 3;
    float tv = temp[h];
    float* row = g_attnca + (long)r * 128;
    int t = threadIdx.x; // 128
    float v = row[t] * tv;
    __shared__ float sd[128];
    sd[t] = v; __syncthreads();
    for (int o = 64; o > 0; o >>= 1) { if (t < o) sd[t] = fmaxf(sd[t], sd[t + o]); __syncthreads(); }
    float mx = sd[0]; __syncthreads();
    float e = expf(v - mx);
    sd[t] = e; __syncthreads();
    for (int o = 64; o > 0; o >>= 1) { if (t < o) sd[t] += sd[t + o]; __syncthreads(); }
    row[t] = e / sd[0];
}

// ---------------- fused projected spatial attention ----------------------------
__global__ void spatial_attn(const float* __restrict__ temp2) {
    int bz = blockIdx.y; int b = bz >> 2, h = bz & 3;
    int n = blockIdx.x * 128 + threadIdx.x;
    __shared__ float kps[128][16];
    __shared__ float vps[128][16];
    const float* kpb = g_kproj + (long)bz * 2048;
    const float* vpb = g_vproj + (long)bz * 2048;
    for (int i = threadIdx.x; i < 2048; i += 128) {
        kps[i >> 4][i & 15] = kpb[i];
        vps[i >> 4][i & 15] = vpb[i];
    }
    __syncthreads();
    const float* q = g_qkvvT + (long)bz * 131072 + n; // m=0 (normalized q)
    float lg[16];
#pragma unroll
    for (int p = 0; p < 16; p++) lg[p] = 0.f;
    for (int d = 0; d < 128; d++) {
        float qv = q[(long)d * 1024];
#pragma unroll
        for (int p = 0; p < 16; p++) lg[p] += qv * kps[d][p];
    }
    float tv = temp2[h];
    float mx = -1e30f;
#pragma unroll
    for (int p = 0; p < 16; p++) { lg[p] *= tv; mx = fmaxf(mx, lg[p]); }
    float s = 0.f;
#pragma unroll
    for (int p = 0; p < 16; p++) { lg[p] = expf(lg[p] - mx); s += lg[p]; }
    float inv = 1.0f / s;
#pragma unroll
    for (int p = 0; p < 16; p++) lg[p] *= inv;
    float* ob = g_xsa + (long)b * 524288 + h * 1024 + n;
    for (int c = 0; c < 128; c += 8) {
        float acc[8];
#pragma unroll
        for (int dd = 0; dd < 8; dd++) acc[dd] = 0.f;
#pragma unroll
        for (int p = 0; p < 16; p++) {
            float ap = lg[p];
#pragma unroll
            for (int dd = 0; dd < 8; dd++) acc[dd] += ap * vps[c + dd][p];
        }
#pragma unroll
        for (int dd = 0; dd < 8; dd++) ob[(long)(c + dd) * 4096] = acc[dd];
    }
}

// ---------------- depthwise 3x3 (SAME, zero pad) + exact GELU ------------------
__global__ void dwconv_gelu(const float* __restrict__ w, const float* __restrict__ bias) {
    long bo = blockIdx.x;                 // b*2048 + o
    int och = (int)(bo & 2047);
    const float* img = g_t1 + bo * 1024;
    __shared__ float s[1024];
    int tid = threadIdx.x; // 256
    *(float4*)&s[tid * 4] = *(const float4*)&img[tid * 4];
    float wv[9];
#pragma unroll
    for (int k = 0; k < 9; k++) wv[k] = w[och * 9 + k];
    float bb = bias[och];
    __syncthreads();
    float* ob = g_t2 + bo * 1024;
    for (int p = tid; p < 1024; p += 256) {
        int h = p >> 5, ww = p & 31;
        float acc = bb;
#pragma unroll
        for (int i = 0; i < 3; i++) {
            int hh = h + i - 1;
            if (hh < 0 || hh > 31) continue;
#pragma unroll
            for (int j = 0; j < 3; j++) {
                int w2 = ww + j - 1;
                if (w2 < 0 || w2 > 31) continue;
                acc += s[hh * 32 + w2] * wv[i * 3 + j];
            }
        }
        ob[p] = 0.5f * acc * (1.0f + erff(acc * 0.70710678118654752440f));
    }
}

// ---------------- launch ------------------------------------------------------
extern "C" void kernel_launch(void* const* d_in, const int* in_sizes, int n_in,
                              void* d_out_v, int out_size) {
    const float* x      = (const float*)d_in[0];
    const float* qkvv_w = (const float*)d_in[1];
    const float* E_w    = (const float*)d_in[2];
    const float* E_b    = (const float*)d_in[3];
    const float* F_w    = (const float*)d_in[4];
    const float* F_b    = (const float*)d_in[5];
    const float* temp   = (const float*)d_in[6];
    const float* temp2  = (const float*)d_in[7];
    const float* out_w  = (const float*)d_in[8];
    const float* out_b  = (const float*)d_in[9];
    const float* out2_w = (const float*)d_in[10];
    const float* out2_b = (const float*)d_in[11];
    const float* fc1_w  = (const float*)d_in[12];
    const float* fc1_b  = (const float*)d_in[13];
    const float* dw_w   = (const float*)d_in[14];
    const float* dw_b   = (const float*)d_in[15];
    const float* fc2_w  = (const float*)d_in[16];
    const float* fc2_b  = (const float*)d_in[17];
    float* dout = (float*)d_out_v;

    float *p_xf, *p_qkvvT, *p_attnca, *p_xca, *p_xsa, *p_t1, *p_t2;
    cudaGetSymbolAddress((void**)&p_xf, g_xf);
    cudaGetSymbolAddress((void**)&p_qkvvT, g_qkvvT);
    cudaGetSymbolAddress((void**)&p_attnca, g_attnca);
    cudaGetSymbolAddress((void**)&p_xca, g_xca);
    cudaGetSymbolAddress((void**)&p_xsa, g_xsa);
    cudaGetSymbolAddress((void**)&p_t1, g_t1);
    cudaGetSymbolAddress((void**)&p_t2, g_t2);

    // 1. pack x -> xf
    pack_xf<<<16384, 128>>>(x);

    // 2. qkvv GEMM, directly into transposed layout:
    //    per batch b: C[j][n] = qkvv_w[j,:] . xf_b[n,:],  j=0..2047, n=0..1023
    {
        EpiQT e{p_qkvvT};
        gemmH<false, true, EpiQT><<<dim3(8, 16, 16), 256>>>(
            qkvv_w, p_xf, 2048, 1024, 512, 512, 512, 0, 524288, e);
    }

    // 3. k_proj / v_proj (from un-normalized k, v_sa)
    kv_proj4<<<1024, 256>>>(E_w, E_b, F_w, F_b);

    // 4. L2-normalize q, k rows in place
    norm_scale<<<16384, 256>>>();

    // 5. channel-attn logits: per bz, [128,128] = qn @ kn^T (K=1024)
    {
        EpiPlain e{p_attnca, 128 * 128, 128, nullptr, nullptr};
        gemmH<false, true, EpiPlain><<<dim3(1, 1, 64), 256>>>(
            p_qkvvT, p_qkvvT + 8388608, 128, 128, 1024, 1024, 1024, 131072, 131072, e);
    }

    // 6. softmax (* temp)
    softmax_ca<<<8192, 128>>>(temp);

    // 7. x_ca: per bz, [128,1024] = attn @ v_ca  (K=128)
    {
        EpiPlain e{p_xca, 131072, 1024, nullptr, nullptr};
        gemmH<false, false, EpiPlain><<<dim3(8, 1, 64), 256>>>(
            p_attnca, p_qkvvT + 2 * 8388608, 128, 1024, 128, 128, 1024, 16384, 131072, e);
    }

    // 8. fused spatial attention -> g_xsa
    spatial_attn<<<dim3(8, 64), 128>>>(temp2);

    // 9. LFE fc1: per b, [2048,1024] = fc1_w @ xf_b^T
    {
        EpiPlain e{p_t1, 2097152, 1024, fc1_b, nullptr};
        gemmH<false, true, EpiPlain><<<dim3(8, 16, 16), 256>>>(
            fc1_w, p_xf, 2048, 1024, 512, 512, 512, 0, 524288, e);
    }

    // 10. depthwise conv + GELU
    dwconv_gelu<<<32768, 256>>>(dw_w, dw_b);

    // 11. LFE fc2 -> d_out (assign, includes swap to (B,W,H,C))
    {
        EpiOut e{dout, fc2_b, 0, 0};
        gemmH<true, true, EpiOut><<<dim3(4, 8, 16), 256>>>(
            p_t2, fc2_w, 1024, 512, 2048, 1024, 2048, 2097152, 0, e);
    }

    // 12. out projection (spatial) -> d_out[..., 0:256] +=
    {
        EpiOut e{dout, out_b, 0, 1};
        gemmH<false, true, EpiOut><<<dim3(2, 8, 16), 256>>>(
            p_xsa, out_w, 1024, 256, 512, 512, 512, 524288, 0, e);
    }

    // 13. out2 projection (channel) -> d_out[..., 256:512] +=
    {
        EpiOut e{dout, out2_b, 256, 1};
        gemmH<true, true, EpiOut><<<dim3(2, 8, 16), 256>>>(
            p_xca, out2_w, 1024, 256, 512, 1024, 512, 524288, 0, e);
    }
}

// round 8
// speedup vs baseline: 3.8798x; 1.1662x over previous
#include <cuda_runtime.h>
#include <cuda_fp16.h>
#include <math.h>

// Problem constants
// B=16, W=H=32, C=512, HEADS=4, DH=128, N=1024, P=16, HID=2048
// n = h*32 + w ; BN = B*N = 16384

// ---------------- scratch (device globals; no allocation allowed) -------------
__device__ half  g_xfh[16384 * 512];         // xf[bn][c]
__device__ half  g_qkvvTh[4 * 8192 * 1024];  // [m][b*4+h][d][n]
__device__ float g_kproj[64 * 128 * 16];     // [bz][d][p]
__device__ float g_vproj[64 * 128 * 16];
__device__ half  g_attncah[64 * 128 * 128];  // [bz][d][e]
__device__ half  g_xcah[16 * 512 * 1024];    // [b][h*128+d][n]
__device__ half  g_xsah[16 * 512 * 1024];    // [b][n'*512+c'] flat
__device__ half  g_t1h[16 * 2048 * 1024];    // [b][o][n]
__device__ half  g_t2h[16 * 2048 * 1024];    // [b][o][n]
// fp16 weight copies
__device__ half  g_wq[2048 * 512];
__device__ half  g_wfc1[2048 * 512];
__device__ half  g_wfc2[512 * 2048];
__device__ half  g_wout[256 * 512];
__device__ half  g_wout2[256 * 512];

// ---------------- async copy helpers ------------------------------------------
__device__ __forceinline__ void cpa16(unsigned dst, const void* src) {
    asm volatile("cp.async.cg.shared.global [%0], [%1], 16;\n" :: "r"(dst), "l"(src));
}

// ---------------- epilogues (pair interface: j, j+1) ---------------------------
struct EpiH {
    half* C; long csb; int ldc; const float* biasRow;
    __device__ __forceinline__ void operator()(int bz, int i, int j, float v0, float v1) const {
        if (biasRow) { float b = biasRow[i]; v0 += b; v1 += b; }
        *(half2*)&C[(long)bz * csb + (long)i * ldc + j] = __floats2half2_rn(v0, v1);
    }
};
// qkvv direct-to-transposed: i = weight row (0..2047) -> (m,h,d); j = n
struct EpiQT {
    half* out;
    __device__ __forceinline__ void operator()(int b, int i, int j, float v0, float v1) const {
        int m = i >> 9, hh = (i >> 7) & 3, d = i & 127;
        *(half2*)&out[((long)(m * 64 + b * 4 + hh)) * 131072 + (long)d * 1024 + j] =
            __floats2half2_rn(v0, v1);
    }
};
// final d_out (B,W,H,C) fp32, n -> (h=n>>5, w=n&31), col offset, opt accumulate
struct EpiOut {
    float* out; const float* bias; int coff; int accum;
    __device__ __forceinline__ void operator()(int b, int n, int j, float v0, float v1) const {
        v0 += bias[j]; v1 += bias[j + 1];
        int h = n >> 5, w = n & 31;
        long idx = (((long)(b * 32 + w)) * 32 + h) * 512 + coff + j;
        if (accum) { out[idx] += v0; out[idx + 1] += v1; }
        else       { out[idx] = v0;  out[idx + 1] = v1; }
    }
};

// ---------------- FP16 GEMM: cp.async double-buffer + all-ldmatrix -------------
// C[i][j] = sum_k A(i,k)*B(j,k), fp32 accumulate.
// AT=false: A (M,K) k-contiguous -> smem [m][k] pitch 40, ldmatrix
// AT=true : A (K,M) m-contiguous -> smem [k][m] pitch 136, ldmatrix.trans
// BT=true : B (N,K) k-contiguous;  BT=false: B (K,N) n-contiguous.
template<bool AT, bool BT, class Epi>
__global__ void __launch_bounds__(256) gemmH(
    const half* __restrict__ A, const half* __restrict__ B,
    int M, int N, int K, int lda, int ldb, long asb, long bsb, Epi epi)
{
    constexpr int ATILE = AT ? 32 * 136 : 128 * 40;   // halves
    constexpr int BTILE = BT ? 128 * 40 : 32 * 136;
    __shared__ __align__(16) half As[2][ATILE];
    __shared__ __align__(16) half Bs[2][BTILE];

    int bz = blockIdx.z;
    const half* Ab = A + (long)bz * asb;
    const half* Bb = B + (long)bz * bsb;
    int bm = blockIdx.y * 128, bn = blockIdx.x * 128;
    int tid = threadIdx.x, lane = tid & 31, warp = tid >> 5;
    int wm = (warp >> 2) * 64, wn = (warp & 3) * 32;
    int g = lane >> 2, t = lane & 3;

    unsigned AsU = (unsigned)__cvta_generic_to_shared(&As[0][0]);
    unsigned BsU = (unsigned)__cvta_generic_to_shared(&Bs[0][0]);

    float c[4][4][4];
#pragma unroll
    for (int mt = 0; mt < 4; mt++)
#pragma unroll
        for (int nt = 0; nt < 4; nt++)
#pragma unroll
            for (int r = 0; r < 4; r++) c[mt][nt][r] = 0.f;

    auto issue = [&](int stage, int k0) {
#pragma unroll
        for (int i = 0; i < 2; i++) {
            int item = tid + i * 256;
            if (!AT) {
                int row = item >> 2, cc = item & 3;
                cpa16(AsU + stage * ATILE * 2 + (row * 40 + cc * 8) * 2,
                      Ab + (long)(bm + row) * lda + k0 + cc * 8);
            } else {
                int k = item >> 4, cc = item & 15;
                cpa16(AsU + stage * ATILE * 2 + (k * 136 + cc * 8) * 2,
                      Ab + (long)(k0 + k) * lda + bm + cc * 8);
            }
        }
#pragma unroll
        for (int i = 0; i < 2; i++) {
            int item = tid + i * 256;
            if (BT) {
                int row = item >> 2, cc = item & 3;
                cpa16(BsU + stage * BTILE * 2 + (row * 40 + cc * 8) * 2,
                      Bb + (long)(bn + row) * ldb + k0 + cc * 8);
            } else {
                int k = item >> 4, cc = item & 15;
                cpa16(BsU + stage * BTILE * 2 + (k * 136 + cc * 8) * 2,
                      Bb + (long)(k0 + k) * ldb + bn + cc * 8);
            }
        }
        asm volatile("cp.async.commit_group;\n" ::: "memory");
    };

    issue(0, 0);
    int stage = 0;

    for (int k0 = 0; k0 < K; k0 += 32) {
        bool nxt = (k0 + 32) < K;
        if (nxt) {
            issue(stage ^ 1, k0 + 32);
            asm volatile("cp.async.wait_group 1;\n" ::: "memory");
        } else {
            asm volatile("cp.async.wait_group 0;\n" ::: "memory");
        }
        __syncthreads();

        unsigned abase = AsU + stage * ATILE * 2;
        unsigned bbase = BsU + stage * BTILE * 2;

#pragma unroll
        for (int kc = 0; kc < 2; kc++) {
            int kb = kc * 16;
            unsigned af[4][4], bf[4][2];
            if (!AT) {
#pragma unroll
                for (int mt = 0; mt < 4; mt++) {
                    int row = wm + mt * 16 + (lane & 15);
                    int kof = kb + ((lane >> 4) << 3);
                    unsigned addr = abase + (row * 40 + kof) * 2;
                    asm volatile(
                        "ldmatrix.sync.aligned.m8n8.x4.shared.b16 {%0,%1,%2,%3}, [%4];"
                        : "=r"(af[mt][0]), "=r"(af[mt][1]), "=r"(af[mt][2]), "=r"(af[mt][3])
                        : "r"(addr));
                }
            } else {
#pragma unroll
                for (int mt = 0; mt < 4; mt++) {
                    int row_k = kb + ((lane >> 4) & 1) * 8 + (lane & 7);
                    int col_m = wm + mt * 16 + ((lane >> 3) & 1) * 8;
                    unsigned addr = abase + (row_k * 136 + col_m) * 2;
                    asm volatile(
                        "ldmatrix.sync.aligned.m8n8.x4.trans.shared.b16 {%0,%1,%2,%3}, [%4];"
                        : "=r"(af[mt][0]), "=r"(af[mt][1]), "=r"(af[mt][2]), "=r"(af[mt][3])
                        : "r"(addr));
                }
            }
            if (BT) {
#pragma unroll
                for (int p = 0; p < 2; p++) {
                    int nt = 2 * p + (lane >> 4);
                    int row = wn + nt * 8 + (lane & 7);
                    int kof = kb + (((lane >> 3) & 1) << 3);
                    unsigned addr = bbase + (row * 40 + kof) * 2;
                    asm volatile(
                        "ldmatrix.sync.aligned.m8n8.x4.shared.b16 {%0,%1,%2,%3}, [%4];"
                        : "=r"(bf[2 * p][0]), "=r"(bf[2 * p][1]),
                          "=r"(bf[2 * p + 1][0]), "=r"(bf[2 * p + 1][1])
                        : "r"(addr));
                }
            } else {
#pragma unroll
                for (int p = 0; p < 2; p++) {
                    int row_k = kb + ((lane >> 3) & 1) * 8 + (lane & 7);
                    int col_n = wn + (2 * p + (lane >> 4)) * 8;
                    unsigned addr = bbase + (row_k * 136 + col_n) * 2;
                    asm volatile(
                        "ldmatrix.sync.aligned.m8n8.x4.trans.shared.b16 {%0,%1,%2,%3}, [%4];"
                        : "=r"(bf[2 * p][0]), "=r"(bf[2 * p][1]),
                          "=r"(bf[2 * p + 1][0]), "=r"(bf[2 * p + 1][1])
                        : "r"(addr));
                }
            }
#pragma unroll
            for (int mt = 0; mt < 4; mt++)
#pragma unroll
                for (int nt = 0; nt < 4; nt++) {
                    asm volatile(
                        "mma.sync.aligned.m16n8k16.row.col.f32.f16.f16.f32 "
                        "{%0,%1,%2,%3},{%4,%5,%6,%7},{%8,%9},{%0,%1,%2,%3};\n"
                        : "+f"(c[mt][nt][0]), "+f"(c[mt][nt][1]),
                          "+f"(c[mt][nt][2]), "+f"(c[mt][nt][3])
                        : "r"(af[mt][0]), "r"(af[mt][1]), "r"(af[mt][2]), "r"(af[mt][3]),
                          "r"(bf[nt][0]), "r"(bf[nt][1]));
                }
        }
        __syncthreads();
        stage ^= 1;
    }

#pragma unroll
    for (int mt = 0; mt < 4; mt++)
#pragma unroll
        for (int nt = 0; nt < 4; nt++) {
            int i = wm + mt * 16 + g;
            int j = wn + nt * 8 + t * 2;
            epi(bz, bm + i,     bn + j, c[mt][nt][0], c[mt][nt][1]);
            epi(bz, bm + i + 8, bn + j, c[mt][nt][2], c[mt][nt][3]);
        }
}

// ---------------- weight conversion fp32 -> fp16 -------------------------------
// segments in float4 units: wq 262144 | wfc1 262144 | wfc2 262144 | wout 32768 | wout2 32768
__global__ void cvt_weights(const float* __restrict__ qw, const float* __restrict__ f1,
                            const float* __restrict__ f2, const float* __restrict__ ow,
                            const float* __restrict__ o2) {
    long i4 = (long)blockIdx.x * 256 + threadIdx.x;   // < 851968
    const float* src; half* dst; long off;
    if (i4 < 262144)      { src = qw; dst = g_wq;   off = i4; }
    else if (i4 < 524288) { src = f1; dst = g_wfc1; off = i4 - 262144; }
    else if (i4 < 786432) { src = f2; dst = g_wfc2; off = i4 - 524288; }
    else if (i4 < 819200) { src = ow; dst = g_wout; off = i4 - 786432; }
    else                  { src = o2; dst = g_wout2; off = i4 - 819200; }
    float4 v = *(const float4*)(src + off * 4);
    half2 h0 = __floats2half2_rn(v.x, v.y), h1 = __floats2half2_rn(v.z, v.w);
    uint2 u; u.x = *(unsigned*)&h0; u.y = *(unsigned*)&h1;
    *(uint2*)(dst + off * 4) = u;
}

// ---------------- pack: x (B,W,H,C) fp32 -> xf half [bn][c] --------------------
__global__ void pack_xf(const float* __restrict__ x) {
    int blk = blockIdx.x;                  // b*1024 + n
    int b = blk >> 10, n = blk & 1023;
    int h = n >> 5, w = n & 31;
    const float* src = x + (((long)(b * 32 + w)) * 32 + h) * 512;
    half* dst = g_xfh + (long)blk * 512;
    int t = threadIdx.x; // 128
    float4 v = *(const float4*)&src[t * 4];
    half2 h0 = __floats2half2_rn(v.x, v.y), h1 = __floats2half2_rn(v.z, v.w);
    uint2 u; u.x = *(unsigned*)&h0; u.y = *(unsigned*)&h1;
    *(uint2*)&dst[t * 4] = u;
}

// ---------------- k_proj / v_proj from fp16 rows -------------------------------
// grid: src(2) x phalf(2) x rowblocks(256) = 1024 blocks; 256 threads
__global__ void __launch_bounds__(256) kv_proj5(
    const float* __restrict__ E_w, const float* __restrict__ E_b,
    const float* __restrict__ F_w, const float* __restrict__ F_b)
{
    __shared__ float Ws[8][1024];   // 32 KB
    int blk = blockIdx.x;
    int src = blk >> 9;            // 0 = k (m=1), 1 = v_sa (m=3)
    int ph  = (blk >> 8) & 1;
    int row0 = (blk & 255) * 32;
    const float* W = (src ? F_w : E_w) + ph * 8 * 1024;
    const float* bias = (src ? F_b : E_b) + ph * 8;

    for (int i = threadIdx.x; i < 2048; i += 256)
        *(float4*)&Ws[0][i * 4] = *(const float4*)&W[i * 4];
    __syncthreads();

    int warp = threadIdx.x >> 5, lane = threadIdx.x & 31;
    const half* basep = g_qkvvTh + (long)(src ? 3 : 1) * 8388608;
    float* outb = (src ? g_vproj : g_kproj);
#pragma unroll
    for (int rr = 0; rr < 4; rr++) {
        int rem = row0 + rr * 8 + warp;          // bz*128 + d
        const half* rp = basep + (long)rem * 1024;
        half2 hv[16];
#pragma unroll
        for (int i = 0; i < 4; i++)
            *(uint4*)&hv[i * 4] = *(const uint4*)(rp + i * 256 + lane * 8);
        float acc[8];
#pragma unroll
        for (int p = 0; p < 8; p++) acc[p] = 0.f;
#pragma unroll
        for (int i = 0; i < 4; i++) {
            float v[8];
#pragma unroll
            for (int q = 0; q < 4; q++) {
                float2 f = __half22float2(hv[i * 4 + q]);
                v[2 * q] = f.x; v[2 * q + 1] = f.y;
            }
            int n0 = i * 256 + lane * 8;
#pragma unroll
            for (int p = 0; p < 8; p++) {
                float4 w0 = *(const float4*)&Ws[p][n0];
                float4 w1 = *(const float4*)&Ws[p][n0 + 4];
                acc[p] += v[0]*w0.x + v[1]*w0.y + v[2]*w0.z + v[3]*w0.w
                        + v[4]*w1.x + v[5]*w1.y + v[6]*w1.z + v[7]*w1.w;
            }
        }
#pragma unroll
        for (int p = 0; p < 8; p++) {
#pragma unroll
            for (int o = 16; o > 0; o >>= 1) acc[p] += __shfl_xor_sync(0xffffffffu, acc[p], o);
        }
        if (lane == 0) {
            float* o = outb + (long)rem * 16 + ph * 8;
#pragma unroll
            for (int p = 0; p < 8; p++) o[p] = acc[p] + bias[p];
        }
    }
}

// ---------------- L2-normalize q and k rows (fp16 in place, fp32 math) ---------
__global__ void norm_scale() {
    half* row = g_qkvvTh + (long)blockIdx.x * 1024;   // rows 0..16383 = m0,m1
    int t = threadIdx.x; // 256
    half2 h[2];
    *(uint2*)h = *(const uint2*)(row + t * 4);
    float2 a = __half22float2(h[0]), b = __half22float2(h[1]);
    float s = a.x*a.x + a.y*a.y + b.x*b.x + b.y*b.y;
    __shared__ float sd[256];
    sd[t] = s; __syncthreads();
    for (int o = 128; o > 0; o >>= 1) { if (t < o) sd[t] += sd[t + o]; __syncthreads(); }
    float inv = 1.0f / fmaxf(sqrtf(sd[0]), 1e-12f);
    h[0] = __floats2half2_rn(a.x * inv, a.y * inv);
    h[1] = __floats2half2_rn(b.x * inv, b.y * inv);
    *(uint2*)(row + t * 4) = *(uint2*)h;
}

// ---------------- softmax over e (128), fp16 in place ---------------------------
__global__ void softmax_ca(const float* __restrict__ temp) {
    int r = blockIdx.x;           // bz*128 + d
    int h = (r >> 7) & 3;
    float tv = temp[h];
    half* row = g_attncah + (long)r * 128;
    int t = threadIdx.x; // 128
    float v = __half2float(row[t]) * tv;
    __shared__ float sd[128];
    sd[t] = v; __syncthreads();
    for (int o = 64; o > 0; o >>= 1) { if (t < o) sd[t] = fmaxf(sd[t], sd[t + o]); __syncthreads(); }
    float mx = sd[0]; __syncthreads();
    float e = expf(v - mx);
    sd[t] = e; __syncthreads();
    for (int o = 64; o > 0; o >>= 1) { if (t < o) sd[t] += sd[t + o]; __syncthreads(); }
    row[t] = __float2half(e / sd[0]);
}

// ---------------- fused projected spatial attention -----------------------------
__global__ void spatial_attn(const float* __restrict__ temp2) {
    int bz = blockIdx.y; int b = bz >> 2, h = bz & 3;
    int n = blockIdx.x * 128 + threadIdx.x;
    __shared__ float kps[128][16];
    __shared__ float vps[128][16];
    const float* kpb = g_kproj + (long)bz * 2048;
    const float* vpb = g_vproj + (long)bz * 2048;
    for (int i = threadIdx.x; i < 2048; i += 128) {
        kps[i >> 4][i & 15] = kpb[i];
        vps[i >> 4][i & 15] = vpb[i];
    }
    __syncthreads();
    const half* q = g_qkvvTh + (long)bz * 131072 + n; // m=0 (normalized q)
    float lg[16];
#pragma unroll
    for (int p = 0; p < 16; p++) lg[p] = 0.f;
    for (int d = 0; d < 128; d++) {
        float qv = __half2float(q[(long)d * 1024]);
#pragma unroll
        for (int p = 0; p < 16; p++) lg[p] += qv * kps[d][p];
    }
    float tv = temp2[h];
    float mx = -1e30f;
#pragma unroll
    for (int p = 0; p < 16; p++) { lg[p] *= tv; mx = fmaxf(mx, lg[p]); }
    float s = 0.f;
#pragma unroll
    for (int p = 0; p < 16; p++) { lg[p] = expf(lg[p] - mx); s += lg[p]; }
    float inv = 1.0f / s;
#pragma unroll
    for (int p = 0; p < 16; p++) lg[p] *= inv;
    half* ob = g_xsah + (long)b * 524288 + h * 1024 + n;
    for (int cc = 0; cc < 128; cc += 8) {
        float acc[8];
#pragma unroll
        for (int dd = 0; dd < 8; dd++) acc[dd] = 0.f;
#pragma unroll
        for (int p = 0; p < 16; p++) {
            float ap = lg[p];
#pragma unroll
            for (int dd = 0; dd < 8; dd++) acc[dd] += ap * vps[cc + dd][p];
        }
#pragma unroll
        for (int dd = 0; dd < 8; dd++) ob[(long)(cc + dd) * 4096] = __float2half(acc[dd]);
    }
}

// ---------------- depthwise 3x3 (SAME) + exact GELU, fp16 io --------------------
__global__ void dwconv_gelu(const float* __restrict__ w, const float* __restrict__ bias) {
    long bo = blockIdx.x;                 // b*2048 + o
    int och = (int)(bo & 2047);
    const half* img = g_t1h + bo * 1024;
    __shared__ float s[1024];
    int tid = threadIdx.x; // 256
    {
        uint2 u = *(const uint2*)&img[tid * 4];
        float2 a = __half22float2(*(half2*)&u.x), b2 = __half22float2(*(half2*)&u.y);
        s[tid * 4] = a.x; s[tid * 4 + 1] = a.y; s[tid * 4 + 2] = b2.x; s[tid * 4 + 3] = b2.y;
    }
    float wv[9];
#pragma unroll
    for (int k = 0; k < 9; k++) wv[k] = w[och * 9 + k];
    float bb = bias[och];
    __syncthreads();
    half* ob = g_t2h + bo * 1024;
    for (int p = tid; p < 1024; p += 256) {
        int h = p >> 5, ww = p & 31;
        float acc = bb;
#pragma unroll
        for (int i = 0; i < 3; i++) {
            int hh = h + i - 1;
            if (hh < 0 || hh > 31) continue;
#pragma unroll
            for (int j = 0; j < 3; j++) {
                int w2 = ww + j - 1;
                if (w2 < 0 || w2 > 31) continue;
                acc += s[hh * 32 + w2] * wv[i * 3 + j];
            }
        }
        ob[p] = __float2half(0.5f * acc * (1.0f + erff(acc * 0.70710678118654752440f)));
    }
}

// ---------------- launch ------------------------------------------------------
extern "C" void kernel_launch(void* const* d_in, const int* in_sizes, int n_in,
                              void* d_out_v, int out_size) {
    const float* x      = (const float*)d_in[0];
    const float* qkvv_w = (const float*)d_in[1];
    const float* E_w    = (const float*)d_in[2];
    const float* E_b    = (const float*)d_in[3];
    const float* F_w    = (const float*)d_in[4];
    const float* F_b    = (const float*)d_in[5];
    const float* temp   = (const float*)d_in[6];
    const float* temp2  = (const float*)d_in[7];
    const float* out_w  = (const float*)d_in[8];
    const float* out_b  = (const float*)d_in[9];
    const float* out2_w = (const float*)d_in[10];
    const float* out2_b = (const float*)d_in[11];
    const float* fc1_w  = (const float*)d_in[12];
    const float* fc1_b  = (const float*)d_in[13];
    const float* dw_w   = (const float*)d_in[14];
    const float* dw_b   = (const float*)d_in[15];
    const float* fc2_w  = (const float*)d_in[16];
    const float* fc2_b  = (const float*)d_in[17];
    float* dout = (float*)d_out_v;

    half *p_xfh, *p_qkvvTh, *p_attncah, *p_xcah, *p_xsah, *p_t1h, *p_t2h;
    half *p_wq, *p_wfc1, *p_wfc2, *p_wout, *p_wout2;
    cudaGetSymbolAddress((void**)&p_xfh, g_xfh);
    cudaGetSymbolAddress((void**)&p_qkvvTh, g_qkvvTh);
    cudaGetSymbolAddress((void**)&p_attncah, g_attncah);
    cudaGetSymbolAddress((void**)&p_xcah, g_xcah);
    cudaGetSymbolAddress((void**)&p_xsah, g_xsah);
    cudaGetSymbolAddress((void**)&p_t1h, g_t1h);
    cudaGetSymbolAddress((void**)&p_t2h, g_t2h);
    cudaGetSymbolAddress((void**)&p_wq, g_wq);
    cudaGetSymbolAddress((void**)&p_wfc1, g_wfc1);
    cudaGetSymbolAddress((void**)&p_wfc2, g_wfc2);
    cudaGetSymbolAddress((void**)&p_wout, g_wout);
    cudaGetSymbolAddress((void**)&p_wout2, g_wout2);

    // 0. weights fp32 -> fp16
    cvt_weights<<<3328, 256>>>(qkvv_w, fc1_w, fc2_w, out_w, out2_w);

    // 1. pack x -> xf (half)
    pack_xf<<<16384, 128>>>(x);

    // 2. qkvv GEMM into transposed layout: per b: C[j][n] = wq[j,:].xf_b[n,:]
    {
        EpiQT e{p_qkvvTh};
        gemmH<false, true, EpiQT><<<dim3(8, 16, 16), 256>>>(
            p_wq, p_xfh, 2048, 1024, 512, 512, 512, 0, 524288, e);
    }

    // 3. k_proj / v_proj (un-normalized k, v_sa)
    kv_proj5<<<1024, 256>>>(E_w, E_b, F_w, F_b);

    // 4. L2-normalize q, k rows in place
    norm_scale<<<16384, 256>>>();

    // 5. channel-attn logits: per bz, [128,128] = qn @ kn^T (K=1024)
    {
        EpiH e{p_attncah, 128 * 128, 128, nullptr};
        gemmH<false, true, EpiH><<<dim3(1, 1, 64), 256>>>(
            p_qkvvTh, p_qkvvTh + 8388608, 128, 128, 1024, 1024, 1024, 131072, 131072, e);
    }

    // 6. softmax (* temp)
    softmax_ca<<<8192, 128>>>(temp);

    // 7. x_ca: per bz, [128,1024] = attn @ v_ca  (K=128)
    {
        EpiH e{p_xcah, 131072, 1024, nullptr};
        gemmH<false, false, EpiH><<<dim3(8, 1, 64), 256>>>(
            p_attncah, p_qkvvTh + 2L * 8388608, 128, 1024, 128, 128, 1024, 16384, 131072, e);
    }

    // 8. fused spatial attention -> g_xsah
    spatial_attn<<<dim3(8, 64), 128>>>(temp2);

    // 9. LFE fc1: per b, [2048,1024] = fc1_w @ xf_b^T (+bias)
    {
        EpiH e{p_t1h, 2097152, 1024, fc1_b};
        gemmH<false, true, EpiH><<<dim3(8, 16, 16), 256>>>(
            p_wfc1, p_xfh, 2048, 1024, 512, 512, 512, 0, 524288, e);
    }

    // 10. depthwise conv + GELU
    dwconv_gelu<<<32768, 256>>>(dw_w, dw_b);

    // 11. LFE fc2 -> d_out (assign, includes swap to (B,W,H,C))
    {
        EpiOut e{dout, fc2_b, 0, 0};
        gemmH<true, true, EpiOut><<<dim3(4, 8, 16), 256>>>(
            p_t2h, p_wfc2, 1024, 512, 2048, 1024, 2048, 2097152, 0, e);
    }

    // 12. out projection (spatial) -> d_out[..., 0:256] +=
    {
        EpiOut e{dout, out_b, 0, 1};
        gemmH<false, true, EpiOut><<<dim3(2, 8, 16), 256>>>(
            p_xsah, p_wout, 1024, 256, 512, 512, 512, 524288, 0, e);
    }

    // 13. out2 projection (channel) -> d_out[..., 256:512] +=
    {
        EpiOut e{dout, out2_b, 256, 1};
        gemmH<true, true, EpiOut><<<dim3(2, 8, 16), 256>>>(
            p_xcah, p_wout2, 1024, 256, 512, 1024, 512, 524288, 0, e);
    }
}

// round 9
// speedup vs baseline: 5.2723x; 1.3589x over previous
#include <cuda_runtime.h>
#include <cuda_fp16.h>
#include <math.h>

// Problem constants
// B=16, W=H=32, C=512, HEADS=4, DH=128, N=1024, P=16, HID=2048
// n = h*32 + w ; BN = B*N = 16384

// ---------------- scratch (device globals; no allocation allowed) -------------
__device__ half  g_xfh[16384 * 512];         // xf[bn][c]
__device__ half  g_qkvvTh[4 * 8192 * 1024];  // [m][b*4+h][d][n]
__device__ float g_kproj[64 * 128 * 16];     // [bz][d][p]
__device__ float g_vproj[64 * 128 * 16];
__device__ half  g_attncah[64 * 128 * 128];  // [bz][d][e]
__device__ half  g_xcah[16 * 512 * 1024];    // [b][h*128+d][n]
__device__ half  g_xsah[16 * 512 * 1024];    // [b][n'*512+c'] flat
__device__ half  g_t1h[16 * 2048 * 1024];    // [b][o][n]
__device__ half  g_t2h[16 * 2048 * 1024];    // [b][o][n]
// fp16 weight copies
__device__ half  g_wq[2048 * 512];
__device__ half  g_wfc1[2048 * 512];
__device__ half  g_wfc2[512 * 2048];
__device__ half  g_wout[256 * 512];
__device__ half  g_wout2[256 * 512];
__device__ half  g_wEFh[2 * 128 * 1024];     // [src][p(128, pad)][n]  rows 16..127 = 0

// ---------------- async copy helpers ------------------------------------------
__device__ __forceinline__ void cpa16(unsigned dst, const void* src) {
    asm volatile("cp.async.cg.shared.global [%0], [%1], 16;\n" :: "r"(dst), "l"(src));
}

// ---------------- epilogues (pair interface: j, j+1) ---------------------------
struct EpiH {
    half* C; long csb; int ldc; const float* biasRow;
    __device__ __forceinline__ void operator()(int bz, int i, int j, float v0, float v1) const {
        if (biasRow) { float b = biasRow[i]; v0 += b; v1 += b; }
        *(half2*)&C[(long)bz * csb + (long)i * ldc + j] = __floats2half2_rn(v0, v1);
    }
};
// qkvv direct-to-transposed: i = weight row (0..2047) -> (m,h,d); j = n
struct EpiQT {
    half* out;
    __device__ __forceinline__ void operator()(int b, int i, int j, float v0, float v1) const {
        int m = i >> 9, hh = (i >> 7) & 3, d = i & 127;
        *(half2*)&out[((long)(m * 64 + b * 4 + hh)) * 131072 + (long)d * 1024 + j] =
            __floats2half2_rn(v0, v1);
    }
};
// kv projection: i = row (bz*128+d), j = p (<16 valid); z selects k/E vs v/F
struct EpiKV {
    float* kp; float* vp; const float* eb; const float* fb;
    __device__ __forceinline__ void operator()(int z, int i, int j, float v0, float v1) const {
        if (j >= 16) return;
        float* o = z ? vp : kp;
        const float* bias = z ? fb : eb;
        long idx = (long)i * 16 + j;
        o[idx]     = v0 + bias[j];
        o[idx + 1] = v1 + bias[j + 1];
    }
};
// final d_out (B,W,H,C) fp32, n -> (h=n>>5, w=n&31), col offset, opt accumulate
struct EpiOut {
    float* out; const float* bias; int coff; int accum;
    __device__ __forceinline__ void operator()(int b, int n, int j, float v0, float v1) const {
        v0 += bias[j]; v1 += bias[j + 1];
        int h = n >> 5, w = n & 31;
        long idx = (((long)(b * 32 + w)) * 32 + h) * 512 + coff + j;
        if (accum) { out[idx] += v0; out[idx + 1] += v1; }
        else       { out[idx] = v0;  out[idx + 1] = v1; }
    }
};

// ---------------- FP16 GEMM: cp.async double-buffer + all-ldmatrix -------------
// C[i][j] = sum_k A(i,k)*B(j,k), fp32 accumulate.
// AT=false: A (M,K) k-contiguous -> smem [m][k] pitch 40, ldmatrix
// AT=true : A (K,M) m-contiguous -> smem [k][m] pitch 136, ldmatrix.trans
// BT=true : B (N,K) k-contiguous;  BT=false: B (K,N) n-contiguous.
template<bool AT, bool BT, class Epi>
__global__ void __launch_bounds__(256) gemmH(
    const half* __restrict__ A, const half* __restrict__ B,
    int M, int N, int K, int lda, int ldb, long asb, long bsb, Epi epi)
{
    constexpr int ATILE = AT ? 32 * 136 : 128 * 40;   // halves
    constexpr int BTILE = BT ? 128 * 40 : 32 * 136;
    __shared__ __align__(16) half As[2][ATILE];
    __shared__ __align__(16) half Bs[2][BTILE];

    int bz = blockIdx.z;
    const half* Ab = A + (long)bz * asb;
    const half* Bb = B + (long)bz * bsb;
    int bm = blockIdx.y * 128, bn = blockIdx.x * 128;
    int tid = threadIdx.x, lane = tid & 31, warp = tid >> 5;
    int wm = (warp >> 2) * 64, wn = (warp & 3) * 32;
    int g = lane >> 2, t = lane & 3;

    unsigned AsU = (unsigned)__cvta_generic_to_shared(&As[0][0]);
    unsigned BsU = (unsigned)__cvta_generic_to_shared(&Bs[0][0]);

    float c[4][4][4];
#pragma unroll
    for (int mt = 0; mt < 4; mt++)
#pragma unroll
        for (int nt = 0; nt < 4; nt++)
#pragma unroll
            for (int r = 0; r < 4; r++) c[mt][nt][r] = 0.f;

    auto issue = [&](int stage, int k0) {
#pragma unroll
        for (int i = 0; i < 2; i++) {
            int item = tid + i * 256;
            if (!AT) {
                int row = item >> 2, cc = item & 3;
                cpa16(AsU + stage * ATILE * 2 + (row * 40 + cc * 8) * 2,
                      Ab + (long)(bm + row) * lda + k0 + cc * 8);
            } else {
                int k = item >> 4, cc = item & 15;
                cpa16(AsU + stage * ATILE * 2 + (k * 136 + cc * 8) * 2,
                      Ab + (long)(k0 + k) * lda + bm + cc * 8);
            }
        }
#pragma unroll
        for (int i = 0; i < 2; i++) {
            int item = tid + i * 256;
            if (BT) {
                int row = item >> 2, cc = item & 3;
                cpa16(BsU + stage * BTILE * 2 + (row * 40 + cc * 8) * 2,
                      Bb + (long)(bn + row) * ldb + k0 + cc * 8);
            } else {
                int k = item >> 4, cc = item & 15;
                cpa16(BsU + stage * BTILE * 2 + (k * 136 + cc * 8) * 2,
                      Bb + (long)(k0 + k) * ldb + bn + cc * 8);
            }
        }
        asm volatile("cp.async.commit_group;\n" ::: "memory");
    };

    issue(0, 0);
    int stage = 0;

    for (int k0 = 0; k0 < K; k0 += 32) {
        bool nxt = (k0 + 32) < K;
        if (nxt) {
            issue(stage ^ 1, k0 + 32);
            asm volatile("cp.async.wait_group 1;\n" ::: "memory");
        } else {
            asm volatile("cp.async.wait_group 0;\n" ::: "memory");
        }
        __syncthreads();

        unsigned abase = AsU + stage * ATILE * 2;
        unsigned bbase = BsU + stage * BTILE * 2;

#pragma unroll
        for (int kc = 0; kc < 2; kc++) {
            int kb = kc * 16;
            unsigned af[4][4], bf[4][2];
            if (!AT) {
#pragma unroll
                for (int mt = 0; mt < 4; mt++) {
                    int row = wm + mt * 16 + (lane & 15);
                    int kof = kb + ((lane >> 4) << 3);
                    unsigned addr = abase + (row * 40 + kof) * 2;
                    asm volatile(
                        "ldmatrix.sync.aligned.m8n8.x4.shared.b16 {%0,%1,%2,%3}, [%4];"
                        : "=r"(af[mt][0]), "=r"(af[mt][1]), "=r"(af[mt][2]), "=r"(af[mt][3])
                        : "r"(addr));
                }
            } else {
#pragma unroll
                for (int mt = 0; mt < 4; mt++) {
                    int row_k = kb + ((lane >> 4) & 1) * 8 + (lane & 7);
                    int col_m = wm + mt * 16 + ((lane >> 3) & 1) * 8;
                    unsigned addr = abase + (row_k * 136 + col_m) * 2;
                    asm volatile(
                        "ldmatrix.sync.aligned.m8n8.x4.trans.shared.b16 {%0,%1,%2,%3}, [%4];"
                        : "=r"(af[mt][0]), "=r"(af[mt][1]), "=r"(af[mt][2]), "=r"(af[mt][3])
                        : "r"(addr));
                }
            }
            if (BT) {
#pragma unroll
                for (int p = 0; p < 2; p++) {
                    int nt = 2 * p + (lane >> 4);
                    int row = wn + nt * 8 + (lane & 7);
                    int kof = kb + (((lane >> 3) & 1) << 3);
                    unsigned addr = bbase + (row * 40 + kof) * 2;
                    asm volatile(
                        "ldmatrix.sync.aligned.m8n8.x4.shared.b16 {%0,%1,%2,%3}, [%4];"
                        : "=r"(bf[2 * p][0]), "=r"(bf[2 * p][1]),
                          "=r"(bf[2 * p + 1][0]), "=r"(bf[2 * p + 1][1])
                        : "r"(addr));
                }
            } else {
#pragma unroll
                for (int p = 0; p < 2; p++) {
                    int row_k = kb + ((lane >> 3) & 1) * 8 + (lane & 7);
                    int col_n = wn + (2 * p + (lane >> 4)) * 8;
                    unsigned addr = bbase + (row_k * 136 + col_n) * 2;
                    asm volatile(
                        "ldmatrix.sync.aligned.m8n8.x4.trans.shared.b16 {%0,%1,%2,%3}, [%4];"
                        : "=r"(bf[2 * p][0]), "=r"(bf[2 * p][1]),
                          "=r"(bf[2 * p + 1][0]), "=r"(bf[2 * p + 1][1])
                        : "r"(addr));
                }
            }
#pragma unroll
            for (int mt = 0; mt < 4; mt++)
#pragma unroll
                for (int nt = 0; nt < 4; nt++) {
                    asm volatile(
                        "mma.sync.aligned.m16n8k16.row.col.f32.f16.f16.f32 "
                        "{%0,%1,%2,%3},{%4,%5,%6,%7},{%8,%9},{%0,%1,%2,%3};\n"
                        : "+f"(c[mt][nt][0]), "+f"(c[mt][nt][1]),
                          "+f"(c[mt][nt][2]), "+f"(c[mt][nt][3])
                        : "r"(af[mt][0]), "r"(af[mt][1]), "r"(af[mt][2]), "r"(af[mt][3]),
                          "r"(bf[nt][0]), "r"(bf[nt][1]));
                }
        }
        __syncthreads();
        stage ^= 1;
    }

#pragma unroll
    for (int mt = 0; mt < 4; mt++)
#pragma unroll
        for (int nt = 0; nt < 4; nt++) {
            int i = wm + mt * 16 + g;
            int j = wn + nt * 8 + t * 2;
            epi(bz, bm + i,     bn + j, c[mt][nt][0], c[mt][nt][1]);
            epi(bz, bm + i + 8, bn + j, c[mt][nt][2], c[mt][nt][3]);
        }
}

// ---------------- weight conversion fp32 -> fp16 -------------------------------
// segments in float4 units: wq 262144 | wfc1 262144 | wfc2 262144 | wout 32768 | wout2 32768
__global__ void cvt_weights(const float* __restrict__ qw, const float* __restrict__ f1,
                            const float* __restrict__ f2, const float* __restrict__ ow,
                            const float* __restrict__ o2) {
    long i4 = (long)blockIdx.x * 256 + threadIdx.x;   // < 851968
    const float* src; half* dst; long off;
    if (i4 < 262144)      { src = qw; dst = g_wq;   off = i4; }
    else if (i4 < 524288) { src = f1; dst = g_wfc1; off = i4 - 262144; }
    else if (i4 < 786432) { src = f2; dst = g_wfc2; off = i4 - 524288; }
    else if (i4 < 819200) { src = ow; dst = g_wout; off = i4 - 786432; }
    else                  { src = o2; dst = g_wout2; off = i4 - 819200; }
    float4 v = *(const float4*)(src + off * 4);
    half2 h0 = __floats2half2_rn(v.x, v.y), h1 = __floats2half2_rn(v.z, v.w);
    uint2 u; u.x = *(unsigned*)&h0; u.y = *(unsigned*)&h1;
    *(uint2*)(dst + off * 4) = u;
}

// ---------------- pad E_w/F_w into fp16 [2][128][1024], rows>=16 zero ----------
__global__ void pad_wEF(const float* __restrict__ E_w, const float* __restrict__ F_w) {
    long i4 = (long)blockIdx.x * 256 + threadIdx.x;   // < 65536 (float4 units)
    int z = (int)(i4 >> 15);                          // src
    long rem = i4 & 32767;                            // within 128*1024/4
    int p = (int)(rem >> 8);                          // row 0..127
    int n4 = (int)(rem & 255);                        // col/4
    half2 h0, h1;
    if (p < 16) {
        const float* w = (z ? F_w : E_w) + (long)p * 1024 + n4 * 4;
        float4 v = *(const float4*)w;
        h0 = __floats2half2_rn(v.x, v.y); h1 = __floats2half2_rn(v.z, v.w);
    } else {
        h0 = __floats2half2_rn(0.f, 0.f); h1 = h0;
    }
    uint2 u; u.x = *(unsigned*)&h0; u.y = *(unsigned*)&h1;
    *(uint2*)(g_wEFh + i4 * 4) = u;
}

// ---------------- pack: x (B,W,H,C) fp32 -> xf half [bn][c] --------------------
__global__ void pack_xf(const float* __restrict__ x) {
    int blk = blockIdx.x;                  // b*1024 + n
    int b = blk >> 10, n = blk & 1023;
    int h = n >> 5, w = n & 31;
    const float* src = x + (((long)(b * 32 + w)) * 32 + h) * 512;
    half* dst = g_xfh + (long)blk * 512;
    int t = threadIdx.x; // 128
    float4 v = *(const float4*)&src[t * 4];
    half2 h0 = __floats2half2_rn(v.x, v.y), h1 = __floats2half2_rn(v.z, v.w);
    uint2 u; u.x = *(unsigned*)&h0; u.y = *(unsigned*)&h1;
    *(uint2*)&dst[t * 4] = u;
}

// ---------------- L2-normalize q and k rows (fp16 in place, fp32 math) ---------
__global__ void norm_scale() {
    half* row = g_qkvvTh + (long)blockIdx.x * 1024;   // rows 0..16383 = m0,m1
    int t = threadIdx.x; // 256
    half2 h[2];
    *(uint2*)h = *(const uint2*)(row + t * 4);
    float2 a = __half22float2(h[0]), b = __half22float2(h[1]);
    float s = a.x*a.x + a.y*a.y + b.x*b.x + b.y*b.y;
    __shared__ float sd[256];
    sd[t] = s; __syncthreads();
    for (int o = 128; o > 0; o >>= 1) { if (t < o) sd[t] += sd[t + o]; __syncthreads(); }
    float inv = 1.0f / fmaxf(sqrtf(sd[0]), 1e-12f);
    h[0] = __floats2half2_rn(a.x * inv, a.y * inv);
    h[1] = __floats2half2_rn(b.x * inv, b.y * inv);
    *(uint2*)(row + t * 4) = *(uint2*)h;
}

// ---------------- softmax over e (128), fp16 in place ---------------------------
__global__ void softmax_ca(const float* __restrict__ temp) {
    int r = blockIdx.x;           // bz*128 + d
    int h = (r >> 7) & 3;
    float tv = temp[h];
    half* row = g_attncah + (long)r * 128;
    int t = threadIdx.x; // 128
    float v = __half2float(row[t]) * tv;
    __shared__ float sd[128];
    sd[t] = v; __syncthreads();
    for (int o = 64; o > 0; o >>= 1) { if (t < o) sd[t] = fmaxf(sd[t], sd[t + o]); __syncthreads(); }
    float mx = sd[0]; __syncthreads();
    float e = expf(v - mx);
    sd[t] = e; __syncthreads();
    for (int o = 64; o > 0; o >>= 1) { if (t < o) sd[t] += sd[t + o]; __syncthreads(); }
    row[t] = __float2half(e / sd[0]);
}

// ---------------- fused projected spatial attention -----------------------------
__global__ void spatial_attn(const float* __restrict__ temp2) {
    int bz = blockIdx.y; int b = bz >> 2, h = bz & 3;
    int n = blockIdx.x * 128 + threadIdx.x;
    __shared__ float kps[128][16];
    __shared__ float vps[128][16];
    const float* kpb = g_kproj + (long)bz * 2048;
    const float* vpb = g_vproj + (long)bz * 2048;
    for (int i = threadIdx.x; i < 2048; i += 128) {
        kps[i >> 4][i & 15] = kpb[i];
        vps[i >> 4][i & 15] = vpb[i];
    }
    __syncthreads();
    const half* q = g_qkvvTh + (long)bz * 131072 + n; // m=0 (normalized q)
    float lg[16];
#pragma unroll
    for (int p = 0; p < 16; p++) lg[p] = 0.f;
    for (int d = 0; d < 128; d++) {
        float qv = __half2float(q[(long)d * 1024]);
#pragma unroll
        for (int p = 0; p < 16; p++) lg[p] += qv * kps[d][p];
    }
    float tv = temp2[h];
    float mx = -1e30f;
#pragma unroll
    for (int p = 0; p < 16; p++) { lg[p] *= tv; mx = fmaxf(mx, lg[p]); }
    float s = 0.f;
#pragma unroll
    for (int p = 0; p < 16; p++) { lg[p] = expf(lg[p] - mx); s += lg[p]; }
    float inv = 1.0f / s;
#pragma unroll
    for (int p = 0; p < 16; p++) lg[p] *= inv;
    half* ob = g_xsah + (long)b * 524288 + h * 1024 + n;
    for (int cc = 0; cc < 128; cc += 8) {
        float acc[8];
#pragma unroll
        for (int dd = 0; dd < 8; dd++) acc[dd] = 0.f;
#pragma unroll
        for (int p = 0; p < 16; p++) {
            float ap = lg[p];
#pragma unroll
            for (int dd = 0; dd < 8; dd++) acc[dd] += ap * vps[cc + dd][p];
        }
#pragma unroll
        for (int dd = 0; dd < 8; dd++) ob[(long)(cc + dd) * 4096] = __float2half(acc[dd]);
    }
}

// ---------------- depthwise 3x3 (SAME) + exact GELU, fp16 io --------------------
__global__ void dwconv_gelu(const float* __restrict__ w, const float* __restrict__ bias) {
    long bo = blockIdx.x;                 // b*2048 + o
    int och = (int)(bo & 2047);
    const half* img = g_t1h + bo * 1024;
    __shared__ float s[1024];
    int tid = threadIdx.x; // 256
    {
        uint2 u = *(const uint2*)&img[tid * 4];
        float2 a = __half22float2(*(half2*)&u.x), b2 = __half22float2(*(half2*)&u.y);
        s[tid * 4] = a.x; s[tid * 4 + 1] = a.y; s[tid * 4 + 2] = b2.x; s[tid * 4 + 3] = b2.y;
    }
    float wv[9];
#pragma unroll
    for (int k = 0; k < 9; k++) wv[k] = w[och * 9 + k];
    float bb = bias[och];
    __syncthreads();
    half* ob = g_t2h + bo * 1024;
    for (int p = tid; p < 1024; p += 256) {
        int h = p >> 5, ww = p & 31;
        float acc = bb;
#pragma unroll
        for (int i = 0; i < 3; i++) {
            int hh = h + i - 1;
            if (hh < 0 || hh > 31) continue;
#pragma unroll
            for (int j = 0; j < 3; j++) {
                int w2 = ww + j - 1;
                if (w2 < 0 || w2 > 31) continue;
                acc += s[hh * 32 + w2] * wv[i * 3 + j];
            }
        }
        ob[p] = __float2half(0.5f * acc * (1.0f + erff(acc * 0.70710678118654752440f)));
    }
}

// ---------------- launch ------------------------------------------------------
extern "C" void kernel_launch(void* const* d_in, const int* in_sizes, int n_in,
                              void* d_out_v, int out_size) {
    const float* x      = (const float*)d_in[0];
    const float* qkvv_w = (const float*)d_in[1];
    const float* E_w    = (const float*)d_in[2];
    const float* E_b    = (const float*)d_in[3];
    const float* F_w    = (const float*)d_in[4];
    const float* F_b    = (const float*)d_in[5];
    const float* temp   = (const float*)d_in[6];
    const float* temp2  = (const float*)d_in[7];
    const float* out_w  = (const float*)d_in[8];
    const float* out_b  = (const float*)d_in[9];
    const float* out2_w = (const float*)d_in[10];
    const float* out2_b = (const float*)d_in[11];
    const float* fc1_w  = (const float*)d_in[12];
    const float* fc1_b  = (const float*)d_in[13];
    const float* dw_w   = (const float*)d_in[14];
    const float* dw_b   = (const float*)d_in[15];
    const float* fc2_w  = (const float*)d_in[16];
    const float* fc2_b  = (const float*)d_in[17];
    float* dout = (float*)d_out_v;

    half *p_xfh, *p_qkvvTh, *p_attncah, *p_xcah, *p_xsah, *p_t1h, *p_t2h;
    half *p_wq, *p_wfc1, *p_wfc2, *p_wout, *p_wout2, *p_wEFh;
    float *p_kproj, *p_vproj;
    cudaGetSymbolAddress((void**)&p_xfh, g_xfh);
    cudaGetSymbolAddress((void**)&p_qkvvTh, g_qkvvTh);
    cudaGetSymbolAddress((void**)&p_attncah, g_attncah);
    cudaGetSymbolAddress((void**)&p_xcah, g_xcah);
    cudaGetSymbolAddress((void**)&p_xsah, g_xsah);
    cudaGetSymbolAddress((void**)&p_t1h, g_t1h);
    cudaGetSymbolAddress((void**)&p_t2h, g_t2h);
    cudaGetSymbolAddress((void**)&p_wq, g_wq);
    cudaGetSymbolAddress((void**)&p_wfc1, g_wfc1);
    cudaGetSymbolAddress((void**)&p_wfc2, g_wfc2);
    cudaGetSymbolAddress((void**)&p_wout, g_wout);
    cudaGetSymbolAddress((void**)&p_wout2, g_wout2);
    cudaGetSymbolAddress((void**)&p_wEFh, g_wEFh);
    cudaGetSymbolAddress((void**)&p_kproj, g_kproj);
    cudaGetSymbolAddress((void**)&p_vproj, g_vproj);

    // 0. weights fp32 -> fp16 (+ padded E/F)
    cvt_weights<<<3328, 256>>>(qkvv_w, fc1_w, fc2_w, out_w, out2_w);
    pad_wEF<<<256, 256>>>(E_w, F_w);

    // 1. pack x -> xf (half)
    pack_xf<<<16384, 128>>>(x);

    // 2. qkvv GEMM into transposed layout: per b: C[j][n] = wq[j,:].xf_b[n,:]
    {
        EpiQT e{p_qkvvTh};
        gemmH<false, true, EpiQT><<<dim3(8, 16, 16), 256>>>(
            p_wq, p_xfh, 2048, 1024, 512, 512, 512, 0, 524288, e);
    }

    // 3. k_proj / v_proj as tensor-core GEMM: [8192,16] = m-slice @ E/F^T, z = src
    {
        EpiKV e{p_kproj, p_vproj, E_b, F_b};
        gemmH<false, true, EpiKV><<<dim3(1, 64, 2), 256>>>(
            p_qkvvTh + 8388608, p_wEFh, 8192, 16, 1024,
            1024, 1024, 2L * 8388608, 131072, e);
    }

    // 4. L2-normalize q, k rows in place
    norm_scale<<<16384, 256>>>();

    // 5. channel-attn logits: per bz, [128,128] = qn @ kn^T (K=1024)
    {
        EpiH e{p_attncah, 128 * 128, 128, nullptr};
        gemmH<false, true, EpiH><<<dim3(1, 1, 64), 256>>>(
            p_qkvvTh, p_qkvvTh + 8388608, 128, 128, 1024, 1024, 1024, 131072, 131072, e);
    }

    // 6. softmax (* temp)
    softmax_ca<<<8192, 128>>>(temp);

    // 7. x_ca: per bz, [128,1024] = attn @ v_ca  (K=128)
    {
        EpiH e{p_xcah, 131072, 1024, nullptr};
        gemmH<false, false, EpiH><<<dim3(8, 1, 64), 256>>>(
            p_attncah, p_qkvvTh + 2L * 8388608, 128, 1024, 128, 128, 1024, 16384, 131072, e);
    }

    // 8. fused spatial attention -> g_xsah
    spatial_attn<<<dim3(8, 64), 128>>>(temp2);

    // 9. LFE fc1: per b, [2048,1024] = fc1_w @ xf_b^T (+bias)
    {
        EpiH e{p_t1h, 2097152, 1024, fc1_b};
        gemmH<false, true, EpiH><<<dim3(8, 16, 16), 256>>>(
            p_wfc1, p_xfh, 2048, 1024, 512, 512, 512, 0, 524288, e);
    }

    // 10. depthwise conv + GELU
    dwconv_gelu<<<32768, 256>>>(dw_w, dw_b);

    // 11. LFE fc2 -> d_out (assign, includes swap to (B,W,H,C))
    {
        EpiOut e{dout, fc2_b, 0, 0};
        gemmH<true, true, EpiOut><<<dim3(4, 8, 16), 256>>>(
            p_t2h, p_wfc2, 1024, 512, 2048, 1024, 2048, 2097152, 0, e);
    }

    // 12. out projection (spatial) -> d_out[..., 0:256] +=
    {
        EpiOut e{dout, out_b, 0, 1};
        gemmH<false, true, EpiOut><<<dim3(2, 8, 16), 256>>>(
            p_xsah, p_wout, 1024, 256, 512, 512, 512, 524288, 0, e);
    }

    // 13. out2 projection (channel) -> d_out[..., 256:512] +=
    {
        EpiOut e{dout, out2_b, 256, 1};
        gemmH<true, true, EpiOut><<<dim3(2, 8, 16), 256>>>(
            p_xcah, p_wout2, 1024, 256, 512, 1024, 512, 524288, 0, e);
    }
}

// round 10
// speedup vs baseline: 5.3485x; 1.0145x over previous
#include <cuda_runtime.h>
#include <cuda_fp16.h>
#include <math.h>

// Problem constants
// B=16, W=H=32, C=512, HEADS=4, DH=128, N=1024, P=16, HID=2048

// ---------------- scratch (device globals; no allocation allowed) -------------
__device__ half  g_xfh[16384 * 512];         // xf[bn][c]
__device__ half  g_qkvvTh[4 * 8192 * 1024];  // [m][b*4+h][d][n]
__device__ float g_kvpart[8 * 8192 * 16];    // [src*4+ks][bz*128+d][p]
__device__ half  g_attncah[64 * 128 * 128];  // [bz][d][e]
__device__ float g_capart[256 * 128 * 128];  // [bz*4+ks][d][e]
__device__ half  g_xcah[16 * 512 * 1024];    // [b][h*128+d][n]
__device__ half  g_xsah[16 * 512 * 1024];    // [b][n'*512+c'] flat
__device__ half  g_t1h[16 * 2048 * 1024];    // [b][o][n]
__device__ half  g_t2h[16 * 2048 * 1024];    // [b][o][n]
// fp16 weight copies
__device__ half  g_wq[2048 * 512];
__device__ half  g_wfc1[2048 * 512];
__device__ half  g_wfc2[512 * 2048];
__device__ half  g_wout[256 * 512];
__device__ half  g_wout2[256 * 512];
__device__ half  g_wEFh[2 * 128 * 1024];     // [src][p(128, pad)][n]  rows 16..127 = 0

// ---------------- async copy helpers ------------------------------------------
__device__ __forceinline__ void cpa16(unsigned dst, const void* src) {
    asm volatile("cp.async.cg.shared.global [%0], [%1], 16;\n" :: "r"(dst), "l"(src));
}

// ---------------- epilogues (pair interface: j, j+1) ---------------------------
struct EpiH {
    half* C; long csb; int ldc; const float* biasRow;
    __device__ __forceinline__ void operator()(int bz, int i, int j, float v0, float v1) const {
        if (biasRow) { float b = biasRow[i]; v0 += b; v1 += b; }
        *(half2*)&C[(long)bz * csb + (long)i * ldc + j] = __floats2half2_rn(v0, v1);
    }
};
// qkvv direct-to-transposed: i = weight row (0..2047) -> (m,h,d); j = n
struct EpiQT {
    half* out;
    __device__ __forceinline__ void operator()(int b, int i, int j, float v0, float v1) const {
        int m = i >> 9, hh = (i >> 7) & 3, d = i & 127;
        *(half2*)&out[((long)(m * 64 + b * 4 + hh)) * 131072 + (long)d * 1024 + j] =
            __floats2half2_rn(v0, v1);
    }
};
// kv partial: z = src*4+ks, i = bz*128+d, j = p (<16 valid), fp32 partial
struct EpiKVP {
    float* part;   // [8][8192][16]
    __device__ __forceinline__ void operator()(int z, int i, int j, float v0, float v1) const {
        if (j >= 16) return;
        long idx = ((long)z * 8192 + i) * 16 + j;
        part[idx] = v0; part[idx + 1] = v1;
    }
};
// channel-attn partial: z = bz*4+ks, fp32 partial [256][128][128]
struct EpiCAP {
    float* part;
    __device__ __forceinline__ void operator()(int z, int i, int j, float v0, float v1) const {
        long idx = ((long)z * 128 + i) * 128 + j;
        part[idx] = v0; part[idx + 1] = v1;
    }
};
// final d_out (B,W,H,C) fp32, n -> (h=n>>5, w=n&31), col offset, opt accumulate
struct EpiOut {
    float* out; const float* bias; int coff; int accum;
    __device__ __forceinline__ void operator()(int b, int n, int j, float v0, float v1) const {
        v0 += bias[j]; v1 += bias[j + 1];
        int h = n >> 5, w = n & 31;
        long idx = (((long)(b * 32 + w)) * 32 + h) * 512 + coff + j;
        if (accum) { out[idx] += v0; out[idx + 1] += v1; }
        else       { out[idx] = v0;  out[idx + 1] = v1; }
    }
};

// ---------------- FP16 GEMM: 3-stage cp.async ring, 1 sync/K-step --------------
// C[i][j] = sum_k A(i,k)*B(j,k), fp32 accumulate.
// AT=false: A (M,K) k-contiguous -> smem [m][k] pitch 40, ldmatrix
// AT=true : A (K,M) m-contiguous -> smem [k][m] pitch 136, ldmatrix.trans
// BT analogous. KSPLIT: blockIdx.z = bz*KSPLIT + ks; K = split length.
template<bool AT, bool BT, int KSPLIT, class Epi>
__global__ void __launch_bounds__(256) gemmH(
    const half* __restrict__ A, const half* __restrict__ B,
    int M, int N, int K, int lda, int ldb, long asb, long bsb, Epi epi)
{
    constexpr int ATILE = AT ? 32 * 136 : 128 * 40;   // halves per stage
    constexpr int BTILE = BT ? 128 * 40 : 32 * 136;
    extern __shared__ __align__(16) half sm[];

    int z = blockIdx.z;
    int bz = z / KSPLIT, ks = z % KSPLIT;
    const half* Ab = A + (long)bz * asb + (AT ? (long)ks * K * lda : (long)ks * K);
    const half* Bb = B + (long)bz * bsb + (BT ? (long)ks * K : (long)ks * K * ldb);
    int bm = blockIdx.y * 128, bn = blockIdx.x * 128;
    int tid = threadIdx.x, lane = tid & 31, warp = tid >> 5;
    int wm = (warp >> 2) * 64, wn = (warp & 3) * 32;
    int g = lane >> 2, t = lane & 3;

    unsigned AsU = (unsigned)__cvta_generic_to_shared(sm);
    unsigned BsU = (unsigned)__cvta_generic_to_shared(sm + 3 * ATILE);

    float c[4][4][4];
#pragma unroll
    for (int mt = 0; mt < 4; mt++)
#pragma unroll
        for (int nt = 0; nt < 4; nt++)
#pragma unroll
            for (int r = 0; r < 4; r++) c[mt][nt][r] = 0.f;

    auto issue = [&](int stage, int k0) {
#pragma unroll
        for (int i = 0; i < 2; i++) {
            int item = tid + i * 256;
            if (!AT) {
                int row = item >> 2, cc = item & 3;
                cpa16(AsU + (stage * ATILE + row * 40 + cc * 8) * 2,
                      Ab + (long)(bm + row) * lda + k0 + cc * 8);
            } else {
                int k = item >> 4, cc = item & 15;
                cpa16(AsU + (stage * ATILE + k * 136 + cc * 8) * 2,
                      Ab + (long)(k0 + k) * lda + bm + cc * 8);
            }
        }
#pragma unroll
        for (int i = 0; i < 2; i++) {
            int item = tid + i * 256;
            if (BT) {
                int row = item >> 2, cc = item & 3;
                cpa16(BsU + (stage * BTILE + row * 40 + cc * 8) * 2,
                      Bb + (long)(bn + row) * ldb + k0 + cc * 8);
            } else {
                int k = item >> 4, cc = item & 15;
                cpa16(BsU + (stage * BTILE + k * 136 + cc * 8) * 2,
                      Bb + (long)(k0 + k) * ldb + bn + cc * 8);
            }
        }
        asm volatile("cp.async.commit_group;\n" ::: "memory");
    };

    issue(0, 0);
    issue(1, 32);
    int nsteps = K >> 5;

    for (int si = 0; si < nsteps; si++) {
        int stage = si % 3;
        int kn = (si + 2) * 32;
        if (kn < K) {
            asm volatile("cp.async.wait_group 1;\n" ::: "memory");
        } else {
            asm volatile("cp.async.wait_group 0;\n" ::: "memory");
        }
        __syncthreads();
        if (kn < K) issue((si + 2) % 3, kn);

        unsigned abase = AsU + stage * ATILE * 2;
        unsigned bbase = BsU + stage * BTILE * 2;

#pragma unroll
        for (int kc = 0; kc < 2; kc++) {
            int kb = kc * 16;
            unsigned af[4][4], bf[4][2];
            if (!AT) {
#pragma unroll
                for (int mt = 0; mt < 4; mt++) {
                    int row = wm + mt * 16 + (lane & 15);
                    int kof = kb + ((lane >> 4) << 3);
                    unsigned addr = abase + (row * 40 + kof) * 2;
                    asm volatile(
                        "ldmatrix.sync.aligned.m8n8.x4.shared.b16 {%0,%1,%2,%3}, [%4];"
                        : "=r"(af[mt][0]), "=r"(af[mt][1]), "=r"(af[mt][2]), "=r"(af[mt][3])
                        : "r"(addr));
                }
            } else {
#pragma unroll
                for (int mt = 0; mt < 4; mt++) {
                    int row_k = kb + ((lane >> 4) & 1) * 8 + (lane & 7);
                    int col_m = wm + mt * 16 + ((lane >> 3) & 1) * 8;
                    unsigned addr = abase + (row_k * 136 + col_m) * 2;
                    asm volatile(
                        "ldmatrix.sync.aligned.m8n8.x4.trans.shared.b16 {%0,%1,%2,%3}, [%4];"
                        : "=r"(af[mt][0]), "=r"(af[mt][1]), "=r"(af[mt][2]), "=r"(af[mt][3])
                        : "r"(addr));
                }
            }
            if (BT) {
#pragma unroll
                for (int p = 0; p < 2; p++) {
                    int nt = 2 * p + (lane >> 4);
                    int row = wn + nt * 8 + (lane & 7);
                    int kof = kb + (((lane >> 3) & 1) << 3);
                    unsigned addr = bbase + (row * 40 + kof) * 2;
                    asm volatile(
                        "ldmatrix.sync.aligned.m8n8.x4.shared.b16 {%0,%1,%2,%3}, [%4];"
                        : "=r"(bf[2 * p][0]), "=r"(bf[2 * p][1]),
                          "=r"(bf[2 * p + 1][0]), "=r"(bf[2 * p + 1][1])
                        : "r"(addr));
                }
            } else {
#pragma unroll
                for (int p = 0; p < 2; p++) {
                    int row_k = kb + ((lane >> 3) & 1) * 8 + (lane & 7);
                    int col_n = wn + (2 * p + (lane >> 4)) * 8;
                    unsigned addr = bbase + (row_k * 136 + col_n) * 2;
                    asm volatile(
                        "ldmatrix.sync.aligned.m8n8.x4.trans.shared.b16 {%0,%1,%2,%3}, [%4];"
                        : "=r"(bf[2 * p][0]), "=r"(bf[2 * p][1]),
                          "=r"(bf[2 * p + 1][0]), "=r"(bf[2 * p + 1][1])
                        : "r"(addr));
                }
            }
#pragma unroll
            for (int mt = 0; mt < 4; mt++)
#pragma unroll
                for (int nt = 0; nt < 4; nt++) {
                    asm volatile(
                        "mma.sync.aligned.m16n8k16.row.col.f32.f16.f16.f32 "
                        "{%0,%1,%2,%3},{%4,%5,%6,%7},{%8,%9},{%0,%1,%2,%3};\n"
                        : "+f"(c[mt][nt][0]), "+f"(c[mt][nt][1]),
                          "+f"(c[mt][nt][2]), "+f"(c[mt][nt][3])
                        : "r"(af[mt][0]), "r"(af[mt][1]), "r"(af[mt][2]), "r"(af[mt][3]),
                          "r"(bf[nt][0]), "r"(bf[nt][1]));
                }
        }
    }

#pragma unroll
    for (int mt = 0; mt < 4; mt++)
#pragma unroll
        for (int nt = 0; nt < 4; nt++) {
            int i = wm + mt * 16 + g;
            int j = wn + nt * 8 + t * 2;
            epi(z, bm + i,     bn + j, c[mt][nt][0], c[mt][nt][1]);
            epi(z, bm + i + 8, bn + j, c[mt][nt][2], c[mt][nt][3]);
        }
}

// smem bytes per instantiation
template<bool AT, bool BT>
constexpr int gemm_smem() {
    return ((AT ? 32 * 136 : 128 * 40) + (BT ? 128 * 40 : 32 * 136)) * 3 * 2;
}

// ---------------- weight conversion fp32 -> fp16 -------------------------------
__global__ void cvt_weights(const float* __restrict__ qw, const float* __restrict__ f1,
                            const float* __restrict__ f2, const float* __restrict__ ow,
                            const float* __restrict__ o2) {
    long i4 = (long)blockIdx.x * 256 + threadIdx.x;   // < 851968
    const float* src; half* dst; long off;
    if (i4 < 262144)      { src = qw; dst = g_wq;   off = i4; }
    else if (i4 < 524288) { src = f1; dst = g_wfc1; off = i4 - 262144; }
    else if (i4 < 786432) { src = f2; dst = g_wfc2; off = i4 - 524288; }
    else if (i4 < 819200) { src = ow; dst = g_wout; off = i4 - 786432; }
    else                  { src = o2; dst = g_wout2; off = i4 - 819200; }
    float4 v = *(const float4*)(src + off * 4);
    half2 h0 = __floats2half2_rn(v.x, v.y), h1 = __floats2half2_rn(v.z, v.w);
    uint2 u; u.x = *(unsigned*)&h0; u.y = *(unsigned*)&h1;
    *(uint2*)(dst + off * 4) = u;
}

// ---------------- pad E_w/F_w into fp16 [2][128][1024], rows>=16 zero ----------
__global__ void pad_wEF(const float* __restrict__ E_w, const float* __restrict__ F_w) {
    long i4 = (long)blockIdx.x * 256 + threadIdx.x;   // < 65536 (float4 units)
    int z = (int)(i4 >> 15);
    long rem = i4 & 32767;
    int p = (int)(rem >> 8);
    int n4 = (int)(rem & 255);
    half2 h0, h1;
    if (p < 16) {
        const float* w = (z ? F_w : E_w) + (long)p * 1024 + n4 * 4;
        float4 v = *(const float4*)w;
        h0 = __floats2half2_rn(v.x, v.y); h1 = __floats2half2_rn(v.z, v.w);
    } else {
        h0 = __floats2half2_rn(0.f, 0.f); h1 = h0;
    }
    uint2 u; u.x = *(unsigned*)&h0; u.y = *(unsigned*)&h1;
    *(uint2*)(g_wEFh + i4 * 4) = u;
}

// ---------------- pack: x (B,W,H,C) fp32 -> xf half [bn][c] --------------------
__global__ void pack_xf(const float* __restrict__ x) {
    int blk = blockIdx.x;                  // b*1024 + n
    int b = blk >> 10, n = blk & 1023;
    int h = n >> 5, w = n & 31;
    const float* src = x + (((long)(b * 32 + w)) * 32 + h) * 512;
    half* dst = g_xfh + (long)blk * 512;
    int t = threadIdx.x; // 128
    float4 v = *(const float4*)&src[t * 4];
    half2 h0 = __floats2half2_rn(v.x, v.y), h1 = __floats2half2_rn(v.z, v.w);
    uint2 u; u.x = *(unsigned*)&h0; u.y = *(unsigned*)&h1;
    *(uint2*)&dst[t * 4] = u;
}

// ---------------- L2-normalize q and k rows (fp16 in place, fp32 math) ---------
__global__ void norm_scale() {
    half* row = g_qkvvTh + (long)blockIdx.x * 1024;   // rows 0..16383 = m0,m1
    int t = threadIdx.x; // 256
    half2 h[2];
    *(uint2*)h = *(const uint2*)(row + t * 4);
    float2 a = __half22float2(h[0]), b = __half22float2(h[1]);
    float s = a.x*a.x + a.y*a.y + b.x*b.x + b.y*b.y;
    __shared__ float sd[256];
    sd[t] = s; __syncthreads();
    for (int o = 128; o > 0; o >>= 1) { if (t < o) sd[t] += sd[t + o]; __syncthreads(); }
    float inv = 1.0f / fmaxf(sqrtf(sd[0]), 1e-12f);
    h[0] = __floats2half2_rn(a.x * inv, a.y * inv);
    h[1] = __floats2half2_rn(b.x * inv, b.y * inv);
    *(uint2*)(row + t * 4) = *(uint2*)h;
}

// ---------------- softmax over e (128): sums 4 K-split partials ----------------
__global__ void softmax_ca(const float* __restrict__ temp) {
    int r = blockIdx.x;           // bz*128 + d
    int bz = r >> 7;
    int h = (bz & 3);
    float tv = temp[h];
    int t = threadIdx.x; // 128
    long base = ((long)(bz * 4) * 128 + (r & 127)) * 128 + t;
    float v = g_capart[base] + g_capart[base + 16384] + g_capart[base + 32768] + g_capart[base + 49152];
    v *= tv;
    __shared__ float sd[128];
    sd[t] = v; __syncthreads();
    for (int o = 64; o > 0; o >>= 1) { if (t < o) sd[t] = fmaxf(sd[t], sd[t + o]); __syncthreads(); }
    float mx = sd[0]; __syncthreads();
    float e = expf(v - mx);
    sd[t] = e; __syncthreads();
    for (int o = 64; o > 0; o >>= 1) { if (t < o) sd[t] += sd[t + o]; __syncthreads(); }
    g_attncah[(long)r * 128 + t] = __float2half(e / sd[0]);
}

// ---------------- fused projected spatial attention (sums kv partials) ---------
__global__ void spatial_attn(const float* __restrict__ temp2,
                             const float* __restrict__ E_b, const float* __restrict__ F_b) {
    int bz = blockIdx.y; int b = bz >> 2, h = bz & 3;
    int n = blockIdx.x * 128 + threadIdx.x;
    __shared__ float kps[128][16];
    __shared__ float vps[128][16];
    for (int i = threadIdx.x; i < 2048; i += 128) {
        int d = i >> 4, p = i & 15;
        long base = ((long)(bz * 128 + d)) * 16 + p;
        float kv = E_b[p], vv = F_b[p];
#pragma unroll
        for (int s = 0; s < 4; s++) {
            kv += g_kvpart[(long)s * 131072 + base];
            vv += g_kvpart[(long)(4 + s) * 131072 + base];
        }
        kps[d][p] = kv; vps[d][p] = vv;
    }
    __syncthreads();
    const half* q = g_qkvvTh + (long)bz * 131072 + n; // m=0 (normalized q)
    float lg[16];
#pragma unroll
    for (int p = 0; p < 16; p++) lg[p] = 0.f;
    for (int d = 0; d < 128; d++) {
        float qv = __half2float(q[(long)d * 1024]);
#pragma unroll
        for (int p = 0; p < 16; p++) lg[p] += qv * kps[d][p];
    }
    float tv = temp2[h];
    float mx = -1e30f;
#pragma unroll
    for (int p = 0; p < 16; p++) { lg[p] *= tv; mx = fmaxf(mx, lg[p]); }
    float s = 0.f;
#pragma unroll
    for (int p = 0; p < 16; p++) { lg[p] = expf(lg[p] - mx); s += lg[p]; }
    float inv = 1.0f / s;
#pragma unroll
    for (int p = 0; p < 16; p++) lg[p] *= inv;
    half* ob = g_xsah + (long)b * 524288 + h * 1024 + n;
    for (int cc = 0; cc < 128; cc += 8) {
        float acc[8];
#pragma unroll
        for (int dd = 0; dd < 8; dd++) acc[dd] = 0.f;
#pragma unroll
        for (int p = 0; p < 16; p++) {
            float ap = lg[p];
#pragma unroll
            for (int dd = 0; dd < 8; dd++) acc[dd] += ap * vps[cc + dd][p];
        }
#pragma unroll
        for (int dd = 0; dd < 8; dd++) ob[(long)(cc + dd) * 4096] = __float2half(acc[dd]);
    }
}

// ---------------- depthwise 3x3 (SAME) + exact GELU, fp16 io --------------------
__global__ void dwconv_gelu(const float* __restrict__ w, const float* __restrict__ bias) {
    long bo = blockIdx.x;                 // b*2048 + o
    int och = (int)(bo & 2047);
    const half* img = g_t1h + bo * 1024;
    __shared__ float s[1024];
    int tid = threadIdx.x; // 256
    {
        uint2 u = *(const uint2*)&img[tid * 4];
        float2 a = __half22float2(*(half2*)&u.x), b2 = __half22float2(*(half2*)&u.y);
        s[tid * 4] = a.x; s[tid * 4 + 1] = a.y; s[tid * 4 + 2] = b2.x; s[tid * 4 + 3] = b2.y;
    }
    float wv[9];
#pragma unroll
    for (int k = 0; k < 9; k++) wv[k] = w[och * 9 + k];
    float bb = bias[och];
    __syncthreads();
    half* ob = g_t2h + bo * 1024;
    for (int p = tid; p < 1024; p += 256) {
        int h = p >> 5, ww = p & 31;
        float acc = bb;
#pragma unroll
        for (int i = 0; i < 3; i++) {
            int hh = h + i - 1;
            if (hh < 0 || hh > 31) continue;
#pragma unroll
            for (int j = 0; j < 3; j++) {
                int w2 = ww + j - 1;
                if (w2 < 0 || w2 > 31) continue;
                acc += s[hh * 32 + w2] * wv[i * 3 + j];
            }
        }
        ob[p] = __float2half(0.5f * acc * (1.0f + erff(acc * 0.70710678118654752440f)));
    }
}

// ---------------- launch ------------------------------------------------------
extern "C" void kernel_launch(void* const* d_in, const int* in_sizes, int n_in,
                              void* d_out_v, int out_size) {
    const float* x      = (const float*)d_in[0];
    const float* qkvv_w = (const float*)d_in[1];
    const float* E_w    = (const float*)d_in[2];
    const float* E_b    = (const float*)d_in[3];
    const float* F_w    = (const float*)d_in[4];
    const float* F_b    = (const float*)d_in[5];
    const float* temp   = (const float*)d_in[6];
    const float* temp2  = (const float*)d_in[7];
    const float* out_w  = (const float*)d_in[8];
    const float* out_b  = (const float*)d_in[9];
    const float* out2_w = (const float*)d_in[10];
    const float* out2_b = (const float*)d_in[11];
    const float* fc1_w  = (const float*)d_in[12];
    const float* fc1_b  = (const float*)d_in[13];
    const float* dw_w   = (const float*)d_in[14];
    const float* dw_b   = (const float*)d_in[15];
    const float* fc2_w  = (const float*)d_in[16];
    const float* fc2_b  = (const float*)d_in[17];
    float* dout = (float*)d_out_v;

    half *p_xfh, *p_qkvvTh, *p_attncah, *p_xcah, *p_xsah, *p_t1h, *p_t2h;
    half *p_wq, *p_wfc1, *p_wfc2, *p_wout, *p_wout2, *p_wEFh;
    float *p_kvpart, *p_capart;
    cudaGetSymbolAddress((void**)&p_xfh, g_xfh);
    cudaGetSymbolAddress((void**)&p_qkvvTh, g_qkvvTh);
    cudaGetSymbolAddress((void**)&p_attncah, g_attncah);
    cudaGetSymbolAddress((void**)&p_xcah, g_xcah);
    cudaGetSymbolAddress((void**)&p_xsah, g_xsah);
    cudaGetSymbolAddress((void**)&p_t1h, g_t1h);
    cudaGetSymbolAddress((void**)&p_t2h, g_t2h);
    cudaGetSymbolAddress((void**)&p_wq, g_wq);
    cudaGetSymbolAddress((void**)&p_wfc1, g_wfc1);
    cudaGetSymbolAddress((void**)&p_wfc2, g_wfc2);
    cudaGetSymbolAddress((void**)&p_wout, g_wout);
    cudaGetSymbolAddress((void**)&p_wout2, g_wout2);
    cudaGetSymbolAddress((void**)&p_wEFh, g_wEFh);
    cudaGetSymbolAddress((void**)&p_kvpart, g_kvpart);
    cudaGetSymbolAddress((void**)&p_capart, g_capart);

    // opt into >48KB dynamic smem for each gemm instantiation
    constexpr int S_FT = gemm_smem<false, true>();   // 61440
    constexpr int S_FF = gemm_smem<false, false>();  // 56832
    constexpr int S_TT = gemm_smem<true, true>();    // 56832
    cudaFuncSetAttribute((const void*)gemmH<false, true, 1, EpiQT>,
                         cudaFuncAttributeMaxDynamicSharedMemorySize, S_FT);
    cudaFuncSetAttribute((const void*)gemmH<false, true, 4, EpiKVP>,
                         cudaFuncAttributeMaxDynamicSharedMemorySize, S_FT);
    cudaFuncSetAttribute((const void*)gemmH<false, true, 4, EpiCAP>,
                         cudaFuncAttributeMaxDynamicSharedMemorySize, S_FT);
    cudaFuncSetAttribute((const void*)gemmH<false, false, 1, EpiH>,
                         cudaFuncAttributeMaxDynamicSharedMemorySize, S_FF);
    cudaFuncSetAttribute((const void*)gemmH<false, true, 1, EpiH>,
                         cudaFuncAttributeMaxDynamicSharedMemorySize, S_FT);
    cudaFuncSetAttribute((const void*)gemmH<true, true, 1, EpiOut>,
                         cudaFuncAttributeMaxDynamicSharedMemorySize, S_TT);
    cudaFuncSetAttribute((const void*)gemmH<false, true, 1, EpiOut>,
                         cudaFuncAttributeMaxDynamicSharedMemorySize, S_FT);

    // 0. weights fp32 -> fp16 (+ padded E/F)
    cvt_weights<<<3328, 256>>>(qkvv_w, fc1_w, fc2_w, out_w, out2_w);
    pad_wEF<<<256, 256>>>(E_w, F_w);

    // 1. pack x -> xf (half)
    pack_xf<<<16384, 128>>>(x);

    // 2. qkvv GEMM into transposed layout
    {
        EpiQT e{p_qkvvTh};
        gemmH<false, true, 1, EpiQT><<<dim3(8, 16, 16), 256, S_FT>>>(
            p_wq, p_xfh, 2048, 1024, 512, 512, 512, 0, 524288, e);
    }

    // 3. k_proj / v_proj partials: z = src*4+ks, K split 256
    {
        EpiKVP e{p_kvpart};
        gemmH<false, true, 4, EpiKVP><<<dim3(1, 64, 8), 256, S_FT>>>(
            p_qkvvTh + 8388608, p_wEFh, 8192, 128, 256,
            1024, 1024, 2L * 8388608, 131072, e);
    }

    // 4. L2-normalize q, k rows in place
    norm_scale<<<16384, 256>>>();

    // 5. channel-attn logits partials: z = bz*4+ks, K split 256
    {
        EpiCAP e{p_capart};
        gemmH<false, true, 4, EpiCAP><<<dim3(1, 1, 256), 256, S_FT>>>(
            p_qkvvTh, p_qkvvTh + 8388608, 128, 128, 256, 1024, 1024, 131072, 131072, e);
    }

    // 6. softmax (sums partials, * temp)
    softmax_ca<<<8192, 128>>>(temp);

    // 7. x_ca: per bz, [128,1024] = attn @ v_ca  (K=128)
    {
        EpiH e{p_xcah, 131072, 1024, nullptr};
        gemmH<false, false, 1, EpiH><<<dim3(8, 1, 64), 256, S_FF>>>(
            p_attncah, p_qkvvTh + 2L * 8388608, 128, 1024, 128, 128, 1024, 16384, 131072, e);
    }

    // 8. fused spatial attention -> g_xsah (sums kv partials + bias)
    spatial_attn<<<dim3(8, 64), 128>>>(temp2, E_b, F_b);

    // 9. LFE fc1: per b, [2048,1024] = fc1_w @ xf_b^T (+bias)
    {
        EpiH e{p_t1h, 2097152, 1024, fc1_b};
        gemmH<false, true, 1, EpiH><<<dim3(8, 16, 16), 256, S_FT>>>(
            p_wfc1, p_xfh, 2048, 1024, 512, 512, 512, 0, 524288, e);
    }

    // 10. depthwise conv + GELU
    dwconv_gelu<<<32768, 256>>>(dw_w, dw_b);

    // 11. LFE fc2 -> d_out (assign, includes swap to (B,W,H,C))
    {
        EpiOut e{dout, fc2_b, 0, 0};
        gemmH<true, true, 1, EpiOut><<<dim3(4, 8, 16), 256, S_TT>>>(
            p_t2h, p_wfc2, 1024, 512, 2048, 1024, 2048, 2097152, 0, e);
    }

    // 12. out projection (spatial) -> d_out[..., 0:256] +=
    {
        EpiOut e{dout, out_b, 0, 1};
        gemmH<false, true, 1, EpiOut><<<dim3(2, 8, 16), 256, S_FT>>>(
            p_xsah, p_wout, 1024, 256, 512, 512, 512, 524288, 0, e);
    }

    // 13. out2 projection (channel) -> d_out[..., 256:512] +=
    {
        EpiOut e{dout, out2_b, 256, 1};
        gemmH<true, true, 1, EpiOut><<<dim3(2, 8, 16), 256, S_TT>>>(
            p_xcah, p_wout2, 1024, 256, 512, 1024, 512, 524288, 0, e);
    }
}

// round 11
// speedup vs baseline: 5.5703x; 1.0415x over previous
#include <cuda_runtime.h>
#include <cuda_fp16.h>
#include <math.h>

// Problem constants
// B=16, W=H=32, C=512, HEADS=4, DH=128, N=1024, P=16, HID=2048

// ---------------- scratch (device globals; no allocation allowed) -------------
__device__ half  g_xfh[16384 * 512];         // xf[bn][c]
__device__ half  g_qkvvTh[4 * 8192 * 1024];  // [m][b*4+h][d][n]
__device__ float g_kvpart[8 * 8192 * 16];    // [src*4+ks][bz*128+d][p]
__device__ half  g_attncah[64 * 128 * 128];  // [bz][d][e]
__device__ float g_capart[256 * 128 * 128];  // [bz*4+ks][d][e]
__device__ half  g_xcah[16 * 512 * 1024];    // [b][h*128+d][n]
__device__ half  g_xsah[16 * 512 * 1024];    // [b][n'*512+c'] flat
__device__ half  g_t1h[16 * 2048 * 1024];    // [b][o][n]
__device__ half  g_t2h[16 * 2048 * 1024];    // [b][o][n]
// fp16 weight copies
__device__ half  g_wq[2048 * 512];
__device__ half  g_wfc1[2048 * 512];
__device__ half  g_wfc2[512 * 2048];
__device__ half  g_wout[256 * 512];
__device__ half  g_wout2[256 * 512];
__device__ half  g_wEFh[2 * 128 * 1024];     // [src][p(128, pad)][n]  rows 16..127 = 0

// ---------------- async copy helpers ------------------------------------------
__device__ __forceinline__ void cpa16(unsigned dst, const void* src) {
    asm volatile("cp.async.cg.shared.global [%0], [%1], 16;\n" :: "r"(dst), "l"(src));
}

// ---------------- epilogues (pair interface: j, j+1) ---------------------------
struct EpiH {
    half* C; long csb; int ldc; const float* biasRow;
    __device__ __forceinline__ void operator()(int bz, int i, int j, float v0, float v1) const {
        if (biasRow) { float b = biasRow[i]; v0 += b; v1 += b; }
        *(half2*)&C[(long)bz * csb + (long)i * ldc + j] = __floats2half2_rn(v0, v1);
    }
};
// qkvv direct-to-transposed: i = weight row (0..2047) -> (m,h,d); j = n
struct EpiQT {
    half* out;
    __device__ __forceinline__ void operator()(int b, int i, int j, float v0, float v1) const {
        int m = i >> 9, hh = (i >> 7) & 3, d = i & 127;
        *(half2*)&out[((long)(m * 64 + b * 4 + hh)) * 131072 + (long)d * 1024 + j] =
            __floats2half2_rn(v0, v1);
    }
};
// kv partial: z = src*4+ks, i = bz*128+d, j = p (<16 valid), fp32 partial
struct EpiKVP {
    float* part;   // [8][8192][16]
    __device__ __forceinline__ void operator()(int z, int i, int j, float v0, float v1) const {
        if (j >= 16) return;
        long idx = ((long)z * 8192 + i) * 16 + j;
        part[idx] = v0; part[idx + 1] = v1;
    }
};
// channel-attn partial: z = bz*4+ks, fp32 partial [256][128][128]
struct EpiCAP {
    float* part;
    __device__ __forceinline__ void operator()(int z, int i, int j, float v0, float v1) const {
        long idx = ((long)z * 128 + i) * 128 + j;
        part[idx] = v0; part[idx + 1] = v1;
    }
};
// final d_out (B,W,H,C) fp32, n -> (h=n>>5, w=n&31), col offset, opt accumulate
struct EpiOut {
    float* out; const float* bias; int coff; int accum;
    __device__ __forceinline__ void operator()(int b, int n, int j, float v0, float v1) const {
        v0 += bias[j]; v1 += bias[j + 1];
        int h = n >> 5, w = n & 31;
        long idx = (((long)(b * 32 + w)) * 32 + h) * 512 + coff + j;
        if (accum) { out[idx] += v0; out[idx + 1] += v1; }
        else       { out[idx] = v0;  out[idx + 1] = v1; }
    }
};

// ---------------- FP16 GEMM: 3-stage cp.async ring, 1 sync/K-step --------------
// C[i][j] = sum_k A(i,k)*B(j,k), fp32 accumulate.
// AT=false: A (M,K) k-contiguous -> smem [m][k] pitch 40, ldmatrix
// AT=true : A (K,M) m-contiguous -> smem [k][m] pitch 136, ldmatrix.trans
// BT analogous. KSPLIT: blockIdx.z = bz*KSPLIT + ks; K = split length.
template<bool AT, bool BT, int KSPLIT, class Epi>
__global__ void __launch_bounds__(256, 2) gemmH(
    const half* __restrict__ A, const half* __restrict__ B,
    int M, int N, int K, int lda, int ldb, long asb, long bsb, Epi epi)
{
    constexpr int ATILE = AT ? 32 * 136 : 128 * 40;   // halves per stage
    constexpr int BTILE = BT ? 128 * 40 : 32 * 136;
    extern __shared__ __align__(16) half sm[];

    int z = blockIdx.z;
    int bz = z / KSPLIT, ks = z % KSPLIT;
    const half* Ab = A + (long)bz * asb + (AT ? (long)ks * K * lda : (long)ks * K);
    const half* Bb = B + (long)bz * bsb + (BT ? (long)ks * K : (long)ks * K * ldb);
    int bm = blockIdx.y * 128, bn = blockIdx.x * 128;
    int tid = threadIdx.x, lane = tid & 31, warp = tid >> 5;
    int wm = (warp >> 2) * 64, wn = (warp & 3) * 32;
    int g = lane >> 2, t = lane & 3;

    unsigned AsU = (unsigned)__cvta_generic_to_shared(sm);
    unsigned BsU = (unsigned)__cvta_generic_to_shared(sm + 3 * ATILE);

    float c[4][4][4];
#pragma unroll
    for (int mt = 0; mt < 4; mt++)
#pragma unroll
        for (int nt = 0; nt < 4; nt++)
#pragma unroll
            for (int r = 0; r < 4; r++) c[mt][nt][r] = 0.f;

    auto issue = [&](int stage, int k0) {
#pragma unroll
        for (int i = 0; i < 2; i++) {
            int item = tid + i * 256;
            if (!AT) {
                int row = item >> 2, cc = item & 3;
                cpa16(AsU + (stage * ATILE + row * 40 + cc * 8) * 2,
                      Ab + (long)(bm + row) * lda + k0 + cc * 8);
            } else {
                int k = item >> 4, cc = item & 15;
                cpa16(AsU + (stage * ATILE + k * 136 + cc * 8) * 2,
                      Ab + (long)(k0 + k) * lda + bm + cc * 8);
            }
        }
#pragma unroll
        for (int i = 0; i < 2; i++) {
            int item = tid + i * 256;
            if (BT) {
                int row = item >> 2, cc = item & 3;
                cpa16(BsU + (stage * BTILE + row * 40 + cc * 8) * 2,
                      Bb + (long)(bn + row) * ldb + k0 + cc * 8);
            } else {
                int k = item >> 4, cc = item & 15;
                cpa16(BsU + (stage * BTILE + k * 136 + cc * 8) * 2,
                      Bb + (long)(k0 + k) * ldb + bn + cc * 8);
            }
        }
        asm volatile("cp.async.commit_group;\n" ::: "memory");
    };

    issue(0, 0);
    issue(1, 32);
    int nsteps = K >> 5;

    for (int si = 0; si < nsteps; si++) {
        int stage = si % 3;
        int kn = (si + 2) * 32;
        if (kn < K) {
            asm volatile("cp.async.wait_group 1;\n" ::: "memory");
        } else {
            asm volatile("cp.async.wait_group 0;\n" ::: "memory");
        }
        __syncthreads();
        if (kn < K) issue((si + 2) % 3, kn);

        unsigned abase = AsU + stage * ATILE * 2;
        unsigned bbase = BsU + stage * BTILE * 2;

#pragma unroll
        for (int kc = 0; kc < 2; kc++) {
            int kb = kc * 16;
            unsigned af[4][4], bf[4][2];
            if (!AT) {
#pragma unroll
                for (int mt = 0; mt < 4; mt++) {
                    int row = wm + mt * 16 + (lane & 15);
                    int kof = kb + ((lane >> 4) << 3);
                    unsigned addr = abase + (row * 40 + kof) * 2;
                    asm volatile(
                        "ldmatrix.sync.aligned.m8n8.x4.shared.b16 {%0,%1,%2,%3}, [%4];"
                        : "=r"(af[mt][0]), "=r"(af[mt][1]), "=r"(af[mt][2]), "=r"(af[mt][3])
                        : "r"(addr));
                }
            } else {
#pragma unroll
                for (int mt = 0; mt < 4; mt++) {
                    int row_k = kb + ((lane >> 4) & 1) * 8 + (lane & 7);
                    int col_m = wm + mt * 16 + ((lane >> 3) & 1) * 8;
                    unsigned addr = abase + (row_k * 136 + col_m) * 2;
                    asm volatile(
                        "ldmatrix.sync.aligned.m8n8.x4.trans.shared.b16 {%0,%1,%2,%3}, [%4];"
                        : "=r"(af[mt][0]), "=r"(af[mt][1]), "=r"(af[mt][2]), "=r"(af[mt][3])
                        : "r"(addr));
                }
            }
            if (BT) {
#pragma unroll
                for (int p = 0; p < 2; p++) {
                    int nt = 2 * p + (lane >> 4);
                    int row = wn + nt * 8 + (lane & 7);
                    int kof = kb + (((lane >> 3) & 1) << 3);
                    unsigned addr = bbase + (row * 40 + kof) * 2;
                    asm volatile(
                        "ldmatrix.sync.aligned.m8n8.x4.shared.b16 {%0,%1,%2,%3}, [%4];"
                        : "=r"(bf[2 * p][0]), "=r"(bf[2 * p][1]),
                          "=r"(bf[2 * p + 1][0]), "=r"(bf[2 * p + 1][1])
                        : "r"(addr));
                }
            } else {
#pragma unroll
                for (int p = 0; p < 2; p++) {
                    int row_k = kb + ((lane >> 3) & 1) * 8 + (lane & 7);
                    int col_n = wn + (2 * p + (lane >> 4)) * 8;
                    unsigned addr = bbase + (row_k * 136 + col_n) * 2;
                    asm volatile(
                        "ldmatrix.sync.aligned.m8n8.x4.trans.shared.b16 {%0,%1,%2,%3}, [%4];"
                        : "=r"(bf[2 * p][0]), "=r"(bf[2 * p][1]),
                          "=r"(bf[2 * p + 1][0]), "=r"(bf[2 * p + 1][1])
                        : "r"(addr));
                }
            }
#pragma unroll
            for (int mt = 0; mt < 4; mt++)
#pragma unroll
                for (int nt = 0; nt < 4; nt++) {
                    asm volatile(
                        "mma.sync.aligned.m16n8k16.row.col.f32.f16.f16.f32 "
                        "{%0,%1,%2,%3},{%4,%5,%6,%7},{%8,%9},{%0,%1,%2,%3};\n"
                        : "+f"(c[mt][nt][0]), "+f"(c[mt][nt][1]),
                          "+f"(c[mt][nt][2]), "+f"(c[mt][nt][3])
                        : "r"(af[mt][0]), "r"(af[mt][1]), "r"(af[mt][2]), "r"(af[mt][3]),
                          "r"(bf[nt][0]), "r"(bf[nt][1]));
                }
        }
    }

#pragma unroll
    for (int mt = 0; mt < 4; mt++)
#pragma unroll
        for (int nt = 0; nt < 4; nt++) {
            int i = wm + mt * 16 + g;
            int j = wn + nt * 8 + t * 2;
            epi(z, bm + i,     bn + j, c[mt][nt][0], c[mt][nt][1]);
            epi(z, bm + i + 8, bn + j, c[mt][nt][2], c[mt][nt][3]);
        }
}

// smem bytes per instantiation
template<bool AT, bool BT>
constexpr int gemm_smem() {
    return ((AT ? 32 * 136 : 128 * 40) + (BT ? 128 * 40 : 32 * 136)) * 3 * 2;
}

// ---------------- weight conversion fp32 -> fp16 -------------------------------
__global__ void cvt_weights(const float* __restrict__ qw, const float* __restrict__ f1,
                            const float* __restrict__ f2, const float* __restrict__ ow,
                            const float* __restrict__ o2) {
    long i4 = (long)blockIdx.x * 256 + threadIdx.x;   // < 851968
    const float* src; half* dst; long off;
    if (i4 < 262144)      { src = qw; dst = g_wq;   off = i4; }
    else if (i4 < 524288) { src = f1; dst = g_wfc1; off = i4 - 262144; }
    else if (i4 < 786432) { src = f2; dst = g_wfc2; off = i4 - 524288; }
    else if (i4 < 819200) { src = ow; dst = g_wout; off = i4 - 786432; }
    else                  { src = o2; dst = g_wout2; off = i4 - 819200; }
    float4 v = *(const float4*)(src + off * 4);
    half2 h0 = __floats2half2_rn(v.x, v.y), h1 = __floats2half2_rn(v.z, v.w);
    uint2 u; u.x = *(unsigned*)&h0; u.y = *(unsigned*)&h1;
    *(uint2*)(dst + off * 4) = u;
}

// ---------------- pad E_w/F_w into fp16 [2][128][1024], rows>=16 zero ----------
__global__ void pad_wEF(const float* __restrict__ E_w, const float* __restrict__ F_w) {
    long i4 = (long)blockIdx.x * 256 + threadIdx.x;   // < 65536 (float4 units)
    int z = (int)(i4 >> 15);
    long rem = i4 & 32767;
    int p = (int)(rem >> 8);
    int n4 = (int)(rem & 255);
    half2 h0, h1;
    if (p < 16) {
        const float* w = (z ? F_w : E_w) + (long)p * 1024 + n4 * 4;
        float4 v = *(const float4*)w;
        h0 = __floats2half2_rn(v.x, v.y); h1 = __floats2half2_rn(v.z, v.w);
    } else {
        h0 = __floats2half2_rn(0.f, 0.f); h1 = h0;
    }
    uint2 u; u.x = *(unsigned*)&h0; u.y = *(unsigned*)&h1;
    *(uint2*)(g_wEFh + i4 * 4) = u;
}

// ---------------- pack: x (B,W,H,C) fp32 -> xf half [bn][c] --------------------
__global__ void pack_xf(const float* __restrict__ x) {
    int blk = blockIdx.x;                  // b*1024 + n
    int b = blk >> 10, n = blk & 1023;
    int h = n >> 5, w = n & 31;
    const float* src = x + (((long)(b * 32 + w)) * 32 + h) * 512;
    half* dst = g_xfh + (long)blk * 512;
    int t = threadIdx.x; // 128
    float4 v = *(const float4*)&src[t * 4];
    half2 h0 = __floats2half2_rn(v.x, v.y), h1 = __floats2half2_rn(v.z, v.w);
    uint2 u; u.x = *(unsigned*)&h0; u.y = *(unsigned*)&h1;
    *(uint2*)&dst[t * 4] = u;
}

// ---------------- L2-normalize q and k rows (fp16 in place, fp32 math) ---------
__global__ void norm_scale() {
    half* row = g_qkvvTh + (long)blockIdx.x * 1024;   // rows 0..16383 = m0,m1
    int t = threadIdx.x; // 256
    half2 h[2];
    *(uint2*)h = *(const uint2*)(row + t * 4);
    float2 a = __half22float2(h[0]), b = __half22float2(h[1]);
    float s = a.x*a.x + a.y*a.y + b.x*b.x + b.y*b.y;
    __shared__ float sd[256];
    sd[t] = s; __syncthreads();
    for (int o = 128; o > 0; o >>= 1) { if (t < o) sd[t] += sd[t + o]; __syncthreads(); }
    float inv = 1.0f / fmaxf(sqrtf(sd[0]), 1e-12f);
    h[0] = __floats2half2_rn(a.x * inv, a.y * inv);
    h[1] = __floats2half2_rn(b.x * inv, b.y * inv);
    *(uint2*)(row + t * 4) = *(uint2*)h;
}

// ---------------- softmax over e (128): sums 4 K-split partials ----------------
__global__ void softmax_ca(const float* __restrict__ temp) {
    int r = blockIdx.x;           // bz*128 + d
    int bz = r >> 7;
    int h = (bz & 3);
    float tv = temp[h];
    int t = threadIdx.x; // 128
    long base = ((long)(bz * 4) * 128 + (r & 127)) * 128 + t;
    float v = g_capart[base] + g_capart[base + 16384] + g_capart[base + 32768] + g_capart[base + 49152];
    v *= tv;
    __shared__ float sd[128];
    sd[t] = v; __syncthreads();
    for (int o = 64; o > 0; o >>= 1) { if (t < o) sd[t] = fmaxf(sd[t], sd[t + o]); __syncthreads(); }
    float mx = sd[0]; __syncthreads();
    float e = expf(v - mx);
    sd[t] = e; __syncthreads();
    for (int o = 64; o > 0; o >>= 1) { if (t < o) sd[t] += sd[t + o]; __syncthreads(); }
    g_attncah[(long)r * 128 + t] = __float2half(e / sd[0]);
}

// ---------------- fused projected spatial attention (sums kv partials) ---------
__global__ void spatial_attn(const float* __restrict__ temp2,
                             const float* __restrict__ E_b, const float* __restrict__ F_b) {
    int bz = blockIdx.y; int b = bz >> 2, h = bz & 3;
    int n = blockIdx.x * 128 + threadIdx.x;
    __shared__ float kps[128][16];
    __shared__ float vps[128][16];
    for (int i = threadIdx.x; i < 2048; i += 128) {
        int d = i >> 4, p = i & 15;
        long base = ((long)(bz * 128 + d)) * 16 + p;
        float kv = E_b[p], vv = F_b[p];
#pragma unroll
        for (int s = 0; s < 4; s++) {
            kv += g_kvpart[(long)s * 131072 + base];
            vv += g_kvpart[(long)(4 + s) * 131072 + base];
        }
        kps[d][p] = kv; vps[d][p] = vv;
    }
    __syncthreads();
    const half* q = g_qkvvTh + (long)bz * 131072 + n; // m=0 (normalized q)
    float lg[16];
#pragma unroll
    for (int p = 0; p < 16; p++) lg[p] = 0.f;
    for (int d = 0; d < 128; d++) {
        float qv = __half2float(q[(long)d * 1024]);
#pragma unroll
        for (int p = 0; p < 16; p++) lg[p] += qv * kps[d][p];
    }
    float tv = temp2[h];
    float mx = -1e30f;
#pragma unroll
    for (int p = 0; p < 16; p++) { lg[p] *= tv; mx = fmaxf(mx, lg[p]); }
    float s = 0.f;
#pragma unroll
    for (int p = 0; p < 16; p++) { lg[p] = expf(lg[p] - mx); s += lg[p]; }
    float inv = 1.0f / s;
#pragma unroll
    for (int p = 0; p < 16; p++) lg[p] *= inv;
    half* ob = g_xsah + (long)b * 524288 + h * 1024 + n;
    for (int cc = 0; cc < 128; cc += 8) {
        float acc[8];
#pragma unroll
        for (int dd = 0; dd < 8; dd++) acc[dd] = 0.f;
#pragma unroll
        for (int p = 0; p < 16; p++) {
            float ap = lg[p];
#pragma unroll
            for (int dd = 0; dd < 8; dd++) acc[dd] += ap * vps[cc + dd][p];
        }
#pragma unroll
        for (int dd = 0; dd < 8; dd++) ob[(long)(cc + dd) * 4096] = __float2half(acc[dd]);
    }
}

// ---------------- depthwise 3x3 (SAME) + exact GELU, fp16 io --------------------
__global__ void dwconv_gelu(const float* __restrict__ w, const float* __restrict__ bias) {
    long bo = blockIdx.x;                 // b*2048 + o
    int och = (int)(bo & 2047);
    const half* img = g_t1h + bo * 1024;
    __shared__ float s[1024];
    int tid = threadIdx.x; // 256
    {
        uint2 u = *(const uint2*)&img[tid * 4];
        float2 a = __half22float2(*(half2*)&u.x), b2 = __half22float2(*(half2*)&u.y);
        s[tid * 4] = a.x; s[tid * 4 + 1] = a.y; s[tid * 4 + 2] = b2.x; s[tid * 4 + 3] = b2.y;
    }
    float wv[9];
#pragma unroll
    for (int k = 0; k < 9; k++) wv[k] = w[och * 9 + k];
    float bb = bias[och];
    __syncthreads();
    half* ob = g_t2h + bo * 1024;
    for (int p = tid; p < 1024; p += 256) {
        int h = p >> 5, ww = p & 31;
        float acc = bb;
#pragma unroll
        for (int i = 0; i < 3; i++) {
            int hh = h + i - 1;
            if (hh < 0 || hh > 31) continue;
#pragma unroll
            for (int j = 0; j < 3; j++) {
                int w2 = ww + j - 1;
                if (w2 < 0 || w2 > 31) continue;
                acc += s[hh * 32 + w2] * wv[i * 3 + j];
            }
        }
        ob[p] = __float2half(0.5f * acc * (1.0f + erff(acc * 0.70710678118654752440f)));
    }
}

// ---------------- launch ------------------------------------------------------
extern "C" void kernel_launch(void* const* d_in, const int* in_sizes, int n_in,
                              void* d_out_v, int out_size) {
    const float* x      = (const float*)d_in[0];
    const float* qkvv_w = (const float*)d_in[1];
    const float* E_w    = (const float*)d_in[2];
    const float* E_b    = (const float*)d_in[3];
    const float* F_w    = (const float*)d_in[4];
    const float* F_b    = (const float*)d_in[5];
    const float* temp   = (const float*)d_in[6];
    const float* temp2  = (const float*)d_in[7];
    const float* out_w  = (const float*)d_in[8];
    const float* out_b  = (const float*)d_in[9];
    const float* out2_w = (const float*)d_in[10];
    const float* out2_b = (const float*)d_in[11];
    const float* fc1_w  = (const float*)d_in[12];
    const float* fc1_b  = (const float*)d_in[13];
    const float* dw_w   = (const float*)d_in[14];
    const float* dw_b   = (const float*)d_in[15];
    const float* fc2_w  = (const float*)d_in[16];
    const float* fc2_b  = (const float*)d_in[17];
    float* dout = (float*)d_out_v;

    half *p_xfh, *p_qkvvTh, *p_attncah, *p_xcah, *p_xsah, *p_t1h, *p_t2h;
    half *p_wq, *p_wfc1, *p_wfc2, *p_wout, *p_wout2, *p_wEFh;
    float *p_kvpart, *p_capart;
    cudaGetSymbolAddress((void**)&p_xfh, g_xfh);
    cudaGetSymbolAddress((void**)&p_qkvvTh, g_qkvvTh);
    cudaGetSymbolAddress((void**)&p_attncah, g_attncah);
    cudaGetSymbolAddress((void**)&p_xcah, g_xcah);
    cudaGetSymbolAddress((void**)&p_xsah, g_xsah);
    cudaGetSymbolAddress((void**)&p_t1h, g_t1h);
    cudaGetSymbolAddress((void**)&p_t2h, g_t2h);
    cudaGetSymbolAddress((void**)&p_wq, g_wq);
    cudaGetSymbolAddress((void**)&p_wfc1, g_wfc1);
    cudaGetSymbolAddress((void**)&p_wfc2, g_wfc2);
    cudaGetSymbolAddress((void**)&p_wout, g_wout);
    cudaGetSymbolAddress((void**)&p_wout2, g_wout2);
    cudaGetSymbolAddress((void**)&p_wEFh, g_wEFh);
    cudaGetSymbolAddress((void**)&p_kvpart, g_kvpart);
    cudaGetSymbolAddress((void**)&p_capart, g_capart);

    // opt into >48KB dynamic smem + max shared carveout so 2 blocks fit per SM
    constexpr int S_FT = gemm_smem<false, true>();   // 61440
    constexpr int S_FF = gemm_smem<false, false>();  // 56832
    constexpr int S_TT = gemm_smem<true, true>();    // 56832
    auto setup = [](const void* f, int smem) {
        cudaFuncSetAttribute(f, cudaFuncAttributeMaxDynamicSharedMemorySize, smem);
        cudaFuncSetAttribute(f, cudaFuncAttributePreferredSharedMemoryCarveout, 100);
    };
    setup((const void*)gemmH<false, true, 1, EpiQT>,  S_FT);
    setup((const void*)gemmH<false, true, 4, EpiKVP>, S_FT);
    setup((const void*)gemmH<false, true, 4, EpiCAP>, S_FT);
    setup((const void*)gemmH<false, false, 1, EpiH>,  S_FF);
    setup((const void*)gemmH<false, true, 1, EpiH>,   S_FT);
    setup((const void*)gemmH<true, true, 1, EpiOut>,  S_TT);
    setup((const void*)gemmH<false, true, 1, EpiOut>, S_FT);

    // 0. weights fp32 -> fp16 (+ padded E/F)
    cvt_weights<<<3328, 256>>>(qkvv_w, fc1_w, fc2_w, out_w, out2_w);
    pad_wEF<<<256, 256>>>(E_w, F_w);

    // 1. pack x -> xf (half)
    pack_xf<<<16384, 128>>>(x);

    // 2. qkvv GEMM into transposed layout
    {
        EpiQT e{p_qkvvTh};
        gemmH<false, true, 1, EpiQT><<<dim3(8, 16, 16), 256, S_FT>>>(
            p_wq, p_xfh, 2048, 1024, 512, 512, 512, 0, 524288, e);
    }

    // 3. k_proj / v_proj partials: z = src*4+ks, K split 256
    {
        EpiKVP e{p_kvpart};
        gemmH<false, true, 4, EpiKVP><<<dim3(1, 64, 8), 256, S_FT>>>(
            p_qkvvTh + 8388608, p_wEFh, 8192, 128, 256,
            1024, 1024, 2L * 8388608, 131072, e);
    }

    // 4. L2-normalize q, k rows in place
    norm_scale<<<16384, 256>>>();

    // 5. channel-attn logits partials: z = bz*4+ks, K split 256
    {
        EpiCAP e{p_capart};
        gemmH<false, true, 4, EpiCAP><<<dim3(1, 1, 256), 256, S_FT>>>(
            p_qkvvTh, p_qkvvTh + 8388608, 128, 128, 256, 1024, 1024, 131072, 131072, e);
    }

    // 6. softmax (sums partials, * temp)
    softmax_ca<<<8192, 128>>>(temp);

    // 7. x_ca: per bz, [128,1024] = attn @ v_ca  (K=128)
    {
        EpiH e{p_xcah, 131072, 1024, nullptr};
        gemmH<false, false, 1, EpiH><<<dim3(8, 1, 64), 256, S_FF>>>(
            p_attncah, p_qkvvTh + 2L * 8388608, 128, 1024, 128, 128, 1024, 16384, 131072, e);
    }

    // 8. fused spatial attention -> g_xsah (sums kv partials + bias)
    spatial_attn<<<dim3(8, 64), 128>>>(temp2, E_b, F_b);

    // 9. LFE fc1: per b, [2048,1024] = fc1_w @ xf_b^T (+bias)
    {
        EpiH e{p_t1h, 2097152, 1024, fc1_b};
        gemmH<false, true, 1, EpiH><<<dim3(8, 16, 16), 256, S_FT>>>(
            p_wfc1, p_xfh, 2048, 1024, 512, 512, 512, 0, 524288, e);
    }

    // 10. depthwise conv + GELU
    dwconv_gelu<<<32768, 256>>>(dw_w, dw_b);

    // 11. LFE fc2 -> d_out (assign, includes swap to (B,W,H,C))
    {
        EpiOut e{dout, fc2_b, 0, 0};
        gemmH<true, true, 1, EpiOut><<<dim3(4, 8, 16), 256, S_TT>>>(
            p_t2h, p_wfc2, 1024, 512, 2048, 1024, 2048, 2097152, 0, e);
    }

    // 12. out projection (spatial) -> d_out[..., 0:256] +=
    {
        EpiOut e{dout, out_b, 0, 1};
        gemmH<false, true, 1, EpiOut><<<dim3(2, 8, 16), 256, S_FT>>>(
            p_xsah, p_wout, 1024, 256, 512, 512, 512, 524288, 0, e);
    }

    // 13. out2 projection (channel) -> d_out[..., 256:512] +=
    {
        EpiOut e{dout, out2_b, 256, 1};
        gemmH<true, true, 1, EpiOut><<<dim3(2, 8, 16), 256, S_TT>>>(
            p_xcah, p_wout2, 1024, 256, 512, 1024, 512, 524288, 0, e);
    }
}

// round 13
// speedup vs baseline: 5.9450x; 1.0673x over previous
#include <cuda_runtime.h>
#include <cuda_fp16.h>
#include <math.h>

// Problem constants
// B=16, W=H=32, C=512, HEADS=4, DH=128, N=1024, P=16, HID=2048

// ---------------- scratch (device globals; no allocation allowed) -------------
__device__ half  g_xfh[16384 * 512];         // xf[bn][c]
__device__ half  g_qkvvTh[4 * 8192 * 1024];  // [m][b*4+h][d][n]
__device__ float g_kvpart[8 * 8192 * 16];    // [src*4+ks][bz*128+d][p]
__device__ half  g_attncah[64 * 128 * 128];  // [bz][d][e]
__device__ float g_capart[256 * 128 * 128];  // [bz*4+ks][d][e]
__device__ half  g_xcah[16 * 512 * 1024];    // [b][h*128+d][n]
__device__ half  g_xsah[16 * 512 * 1024];    // [b][n'*512+c'] flat
__device__ half  g_t1h[16 * 2048 * 1024];    // [b][o][n]
__device__ half  g_t2h[16 * 2048 * 1024];    // [b][o][n]
// fp16 weight copies
__device__ half  g_wq[2048 * 512];
__device__ half  g_wfc1[2048 * 512];
__device__ half  g_wfc2[512 * 2048];
__device__ half  g_wout[256 * 512];
__device__ half  g_wout2[256 * 512];
__device__ half  g_wEFh[2 * 128 * 1024];     // [src][p(128, pad)][n]  rows 16..127 = 0

// ---------------- async copy helpers ------------------------------------------
__device__ __forceinline__ void cpa16(unsigned dst, const void* src) {
    asm volatile("cp.async.cg.shared.global [%0], [%1], 16;\n" :: "r"(dst), "l"(src));
}

// ---------------- epilogues (pair interface: j, j+1) ---------------------------
struct EpiH {
    half* C; long csb; int ldc; const float* biasRow;
    __device__ __forceinline__ void operator()(int bz, int i, int j, float v0, float v1) const {
        if (biasRow) { float b = biasRow[i]; v0 += b; v1 += b; }
        *(half2*)&C[(long)bz * csb + (long)i * ldc + j] = __floats2half2_rn(v0, v1);
    }
};
// qkvv direct-to-transposed: i = weight row (0..2047) -> (m,h,d); j = n
struct EpiQT {
    half* out;
    __device__ __forceinline__ void operator()(int b, int i, int j, float v0, float v1) const {
        int m = i >> 9, hh = (i >> 7) & 3, d = i & 127;
        *(half2*)&out[((long)(m * 64 + b * 4 + hh)) * 131072 + (long)d * 1024 + j] =
            __floats2half2_rn(v0, v1);
    }
};
// kv partial: z = src*4+ks, i = bz*128+d, j = p (<16 valid), fp32 partial
struct EpiKVP {
    float* part;   // [8][8192][16]
    __device__ __forceinline__ void operator()(int z, int i, int j, float v0, float v1) const {
        if (j >= 16) return;
        long idx = ((long)z * 8192 + i) * 16 + j;
        part[idx] = v0; part[idx + 1] = v1;
    }
};
// channel-attn partial: z = bz*4+ks, fp32 partial [256][128][128]
struct EpiCAP {
    float* part;
    __device__ __forceinline__ void operator()(int z, int i, int j, float v0, float v1) const {
        long idx = ((long)z * 128 + i) * 128 + j;
        part[idx] = v0; part[idx + 1] = v1;
    }
};
// final d_out (B,W,H,C) fp32, n -> (h=n>>5, w=n&31), col offset, opt accumulate
struct EpiOut {
    float* out; const float* bias; int coff; int accum;
    __device__ __forceinline__ void operator()(int b, int n, int j, float v0, float v1) const {
        v0 += bias[j]; v1 += bias[j + 1];
        int h = n >> 5, w = n & 31;
        long idx = (((long)(b * 32 + w)) * 32 + h) * 512 + coff + j;
        if (accum) { out[idx] += v0; out[idx + 1] += v1; }
        else       { out[idx] = v0;  out[idx + 1] = v1; }
    }
};

// ---------------- FP16 GEMM: 3-stage cp.async ring, 1 sync/K-step --------------
// C[i][j] = sum_k A(i,k)*B(j,k), fp32 accumulate.
// AT=false: A (M,K) k-contiguous -> smem [m][k] pitch 40, ldmatrix
// AT=true : A (K,M) m-contiguous -> smem [k][m] pitch 136, ldmatrix.trans
// BT analogous. KSPLIT: blockIdx.z = bz*KSPLIT + ks; K = split length.
template<bool AT, bool BT, int KSPLIT, class Epi>
__global__ void __launch_bounds__(256, 2) gemmH(
    const half* __restrict__ A, const half* __restrict__ B,
    int M, int N, int K, int lda, int ldb, long asb, long bsb, Epi epi)
{
    constexpr int ATILE = AT ? 32 * 136 : 128 * 40;   // halves per stage
    constexpr int BTILE = BT ? 128 * 40 : 32 * 136;
    extern __shared__ __align__(16) half sm[];

    int z = blockIdx.z;
    int bz = z / KSPLIT, ks = z % KSPLIT;
    const half* Ab = A + (long)bz * asb + (AT ? (long)ks * K * lda : (long)ks * K);
    const half* Bb = B + (long)bz * bsb + (BT ? (long)ks * K : (long)ks * K * ldb);
    int bm = blockIdx.y * 128, bn = blockIdx.x * 128;
    int tid = threadIdx.x, lane = tid & 31, warp = tid >> 5;
    int wm = (warp >> 2) * 64, wn = (warp & 3) * 32;
    int g = lane >> 2, t = lane & 3;

    unsigned AsU = (unsigned)__cvta_generic_to_shared(sm);
    unsigned BsU = (unsigned)__cvta_generic_to_shared(sm + 3 * ATILE);

    float c[4][4][4];
#pragma unroll
    for (int mt = 0; mt < 4; mt++)
#pragma unroll
        for (int nt = 0; nt < 4; nt++)
#pragma unroll
            for (int r = 0; r < 4; r++) c[mt][nt][r] = 0.f;

    auto issue = [&](int stage, int k0) {
#pragma unroll
        for (int i = 0; i < 2; i++) {
            int item = tid + i * 256;
            if (!AT) {
                int row = item >> 2, cc = item & 3;
                cpa16(AsU + (stage * ATILE + row * 40 + cc * 8) * 2,
                      Ab + (long)(bm + row) * lda + k0 + cc * 8);
            } else {
                int k = item >> 4, cc = item & 15;
                cpa16(AsU + (stage * ATILE + k * 136 + cc * 8) * 2,
                      Ab + (long)(k0 + k) * lda + bm + cc * 8);
            }
        }
#pragma unroll
        for (int i = 0; i < 2; i++) {
            int item = tid + i * 256;
            if (BT) {
                int row = item >> 2, cc = item & 3;
                cpa16(BsU + (stage * BTILE + row * 40 + cc * 8) * 2,
                      Bb + (long)(bn + row) * ldb + k0 + cc * 8);
            } else {
                int k = item >> 4, cc = item & 15;
                cpa16(BsU + (stage * BTILE + k * 136 + cc * 8) * 2,
                      Bb + (long)(k0 + k) * ldb + bn + cc * 8);
            }
        }
        asm volatile("cp.async.commit_group;\n" ::: "memory");
    };

    issue(0, 0);
    issue(1, 32);
    int nsteps = K >> 5;

    for (int si = 0; si < nsteps; si++) {
        int stage = si % 3;
        int kn = (si + 2) * 32;
        if (kn < K) {
            asm volatile("cp.async.wait_group 1;\n" ::: "memory");
        } else {
            asm volatile("cp.async.wait_group 0;\n" ::: "memory");
        }
        __syncthreads();
        if (kn < K) issue((si + 2) % 3, kn);

        unsigned abase = AsU + stage * ATILE * 2;
        unsigned bbase = BsU + stage * BTILE * 2;

#pragma unroll
        for (int kc = 0; kc < 2; kc++) {
            int kb = kc * 16;
            unsigned af[4][4], bf[4][2];
            if (!AT) {
#pragma unroll
                for (int mt = 0; mt < 4; mt++) {
                    int row = wm + mt * 16 + (lane & 15);
                    int kof = kb + ((lane >> 4) << 3);
                    unsigned addr = abase + (row * 40 + kof) * 2;
                    asm volatile(
                        "ldmatrix.sync.aligned.m8n8.x4.shared.b16 {%0,%1,%2,%3}, [%4];"
                        : "=r"(af[mt][0]), "=r"(af[mt][1]), "=r"(af[mt][2]), "=r"(af[mt][3])
                        : "r"(addr));
                }
            } else {
#pragma unroll
                for (int mt = 0; mt < 4; mt++) {
                    int row_k = kb + ((lane >> 4) & 1) * 8 + (lane & 7);
                    int col_m = wm + mt * 16 + ((lane >> 3) & 1) * 8;
                    unsigned addr = abase + (row_k * 136 + col_m) * 2;
                    asm volatile(
                        "ldmatrix.sync.aligned.m8n8.x4.trans.shared.b16 {%0,%1,%2,%3}, [%4];"
                        : "=r"(af[mt][0]), "=r"(af[mt][1]), "=r"(af[mt][2]), "=r"(af[mt][3])
                        : "r"(addr));
                }
            }
            if (BT) {
#pragma unroll
                for (int p = 0; p < 2; p++) {
                    int nt = 2 * p + (lane >> 4);
                    int row = wn + nt * 8 + (lane & 7);
                    int kof = kb + (((lane >> 3) & 1) << 3);
                    unsigned addr = bbase + (row * 40 + kof) * 2;
                    asm volatile(
                        "ldmatrix.sync.aligned.m8n8.x4.shared.b16 {%0,%1,%2,%3}, [%4];"
                        : "=r"(bf[2 * p][0]), "=r"(bf[2 * p][1]),
                          "=r"(bf[2 * p + 1][0]), "=r"(bf[2 * p + 1][1])
                        : "r"(addr));
                }
            } else {
#pragma unroll
                for (int p = 0; p < 2; p++) {
                    int row_k = kb + ((lane >> 3) & 1) * 8 + (lane & 7);
                    int col_n = wn + (2 * p + (lane >> 4)) * 8;
                    unsigned addr = bbase + (row_k * 136 + col_n) * 2;
                    asm volatile(
                        "ldmatrix.sync.aligned.m8n8.x4.trans.shared.b16 {%0,%1,%2,%3}, [%4];"
                        : "=r"(bf[2 * p][0]), "=r"(bf[2 * p][1]),
                          "=r"(bf[2 * p + 1][0]), "=r"(bf[2 * p + 1][1])
                        : "r"(addr));
                }
            }
#pragma unroll
            for (int mt = 0; mt < 4; mt++)
#pragma unroll
                for (int nt = 0; nt < 4; nt++) {
                    asm volatile(
                        "mma.sync.aligned.m16n8k16.row.col.f32.f16.f16.f32 "
                        "{%0,%1,%2,%3},{%4,%5,%6,%7},{%8,%9},{%0,%1,%2,%3};\n"
                        : "+f"(c[mt][nt][0]), "+f"(c[mt][nt][1]),
                          "+f"(c[mt][nt][2]), "+f"(c[mt][nt][3])
                        : "r"(af[mt][0]), "r"(af[mt][1]), "r"(af[mt][2]), "r"(af[mt][3]),
                          "r"(bf[nt][0]), "r"(bf[nt][1]));
                }
        }
    }

#pragma unroll
    for (int mt = 0; mt < 4; mt++)
#pragma unroll
        for (int nt = 0; nt < 4; nt++) {
            int i = wm + mt * 16 + g;
            int j = wn + nt * 8 + t * 2;
            epi(z, bm + i,     bn + j, c[mt][nt][0], c[mt][nt][1]);
            epi(z, bm + i + 8, bn + j, c[mt][nt][2], c[mt][nt][3]);
        }
}

// smem bytes per instantiation
template<bool AT, bool BT>
constexpr int gemm_smem() {
    return ((AT ? 32 * 136 : 128 * 40) + (BT ? 128 * 40 : 32 * 136)) * 3 * 2;
}

// ---------------- weight conversion fp32 -> fp16 -------------------------------
__global__ void cvt_weights(const float* __restrict__ qw, const float* __restrict__ f1,
                            const float* __restrict__ f2, const float* __restrict__ ow,
                            const float* __restrict__ o2) {
    long i4 = (long)blockIdx.x * 256 + threadIdx.x;   // < 851968
    const float* src; half* dst; long off;
    if (i4 < 262144)      { src = qw; dst = g_wq;   off = i4; }
    else if (i4 < 524288) { src = f1; dst = g_wfc1; off = i4 - 262144; }
    else if (i4 < 786432) { src = f2; dst = g_wfc2; off = i4 - 524288; }
    else if (i4 < 819200) { src = ow; dst = g_wout; off = i4 - 786432; }
    else                  { src = o2; dst = g_wout2; off = i4 - 819200; }
    float4 v = *(const float4*)(src + off * 4);
    half2 h0 = __floats2half2_rn(v.x, v.y), h1 = __floats2half2_rn(v.z, v.w);
    uint2 u; u.x = *(unsigned*)&h0; u.y = *(unsigned*)&h1;
    *(uint2*)(dst + off * 4) = u;
}

// ---------------- pad E_w/F_w into fp16 [2][128][1024], rows>=16 zero ----------
__global__ void pad_wEF(const float* __restrict__ E_w, const float* __restrict__ F_w) {
    long i4 = (long)blockIdx.x * 256 + threadIdx.x;   // < 65536 (float4 units)
    int z = (int)(i4 >> 15);
    long rem = i4 & 32767;
    int p = (int)(rem >> 8);
    int n4 = (int)(rem & 255);
    half2 h0, h1;
    if (p < 16) {
        const float* w = (z ? F_w : E_w) + (long)p * 1024 + n4 * 4;
        float4 v = *(const float4*)w;
        h0 = __floats2half2_rn(v.x, v.y); h1 = __floats2half2_rn(v.z, v.w);
    } else {
        h0 = __floats2half2_rn(0.f, 0.f); h1 = h0;
    }
    uint2 u; u.x = *(unsigned*)&h0; u.y = *(unsigned*)&h1;
    *(uint2*)(g_wEFh + i4 * 4) = u;
}

// ---------------- pack: x (B,W,H,C) fp32 -> xf half [bn][c] --------------------
__global__ void pack_xf(const float* __restrict__ x) {
    int blk = blockIdx.x;                  // b*1024 + n
    int b = blk >> 10, n = blk & 1023;
    int h = n >> 5, w = n & 31;
    const float* src = x + (((long)(b * 32 + w)) * 32 + h) * 512;
    half* dst = g_xfh + (long)blk * 512;
    int t = threadIdx.x; // 128
    float4 v = *(const float4*)&src[t * 4];
    half2 h0 = __floats2half2_rn(v.x, v.y), h1 = __floats2half2_rn(v.z, v.w);
    uint2 u; u.x = *(unsigned*)&h0; u.y = *(unsigned*)&h1;
    *(uint2*)&dst[t * 4] = u;
}

// ---------------- L2-normalize q and k rows (fp16 in place, fp32 math) ---------
__global__ void norm_scale() {
    half* row = g_qkvvTh + (long)blockIdx.x * 1024;   // rows 0..16383 = m0,m1
    int t = threadIdx.x; // 256
    half2 h[2];
    *(uint2*)h = *(const uint2*)(row + t * 4);
    float2 a = __half22float2(h[0]), b = __half22float2(h[1]);
    float s = a.x*a.x + a.y*a.y + b.x*b.x + b.y*b.y;
    __shared__ float sd[256];
    sd[t] = s; __syncthreads();
    for (int o = 128; o > 0; o >>= 1) { if (t < o) sd[t] += sd[t + o]; __syncthreads(); }
    float inv = 1.0f / fmaxf(sqrtf(sd[0]), 1e-12f);
    h[0] = __floats2half2_rn(a.x * inv, a.y * inv);
    h[1] = __floats2half2_rn(b.x * inv, b.y * inv);
    *(uint2*)(row + t * 4) = *(uint2*)h;
}

// ---------------- softmax over e (128): sums 4 K-split partials ----------------
__global__ void softmax_ca(const float* __restrict__ temp) {
    int r = blockIdx.x;           // bz*128 + d
    int bz = r >> 7;
    int h = (bz & 3);
    float tv = temp[h];
    int t = threadIdx.x; // 128
    long base = ((long)(bz * 4) * 128 + (r & 127)) * 128 + t;
    float v = g_capart[base] + g_capart[base + 16384] + g_capart[base + 32768] + g_capart[base + 49152];
    v *= tv;
    __shared__ float sd[128];
    sd[t] = v; __syncthreads();
    for (int o = 64; o > 0; o >>= 1) { if (t < o) sd[t] = fmaxf(sd[t], sd[t + o]); __syncthreads(); }
    float mx = sd[0]; __syncthreads();
    float e = expf(v - mx);
    sd[t] = e; __syncthreads();
    for (int o = 64; o > 0; o >>= 1) { if (t < o) sd[t] += sd[t + o]; __syncthreads(); }
    g_attncah[(long)r * 128 + t] = __float2half(e / sd[0]);
}

// ---------------- fused projected spatial attention (sums kv partials) ---------
__global__ void spatial_attn(const float* __restrict__ temp2,
                             const float* __restrict__ E_b, const float* __restrict__ F_b) {
    int bz = blockIdx.y; int b = bz >> 2, h = bz & 3;
    int n = blockIdx.x * 128 + threadIdx.x;
    __shared__ float kps[128][16];
    __shared__ float vps[128][16];
    for (int i = threadIdx.x; i < 2048; i += 128) {
        int d = i >> 4, p = i & 15;
        long base = ((long)(bz * 128 + d)) * 16 + p;
        float kv = E_b[p], vv = F_b[p];
#pragma unroll
        for (int s = 0; s < 4; s++) {
            kv += g_kvpart[(long)s * 131072 + base];
            vv += g_kvpart[(long)(4 + s) * 131072 + base];
        }
        kps[d][p] = kv; vps[d][p] = vv;
    }
    __syncthreads();
    const half* q = g_qkvvTh + (long)bz * 131072 + n; // m=0 (normalized q)
    float lg[16];
#pragma unroll
    for (int p = 0; p < 16; p++) lg[p] = 0.f;
    for (int d = 0; d < 128; d++) {
        float qv = __half2float(q[(long)d * 1024]);
#pragma unroll
        for (int p = 0; p < 16; p++) lg[p] += qv * kps[d][p];
    }
    float tv = temp2[h];
    float mx = -1e30f;
#pragma unroll
    for (int p = 0; p < 16; p++) { lg[p] *= tv; mx = fmaxf(mx, lg[p]); }
    float s = 0.f;
#pragma unroll
    for (int p = 0; p < 16; p++) { lg[p] = expf(lg[p] - mx); s += lg[p]; }
    float inv = 1.0f / s;
#pragma unroll
    for (int p = 0; p < 16; p++) lg[p] *= inv;
    half* ob = g_xsah + (long)b * 524288 + h * 1024 + n;
    for (int cc = 0; cc < 128; cc += 8) {
        float acc[8];
#pragma unroll
        for (int dd = 0; dd < 8; dd++) acc[dd] = 0.f;
#pragma unroll
        for (int p = 0; p < 16; p++) {
            float ap = lg[p];
#pragma unroll
            for (int dd = 0; dd < 8; dd++) acc[dd] += ap * vps[cc + dd][p];
        }
#pragma unroll
        for (int dd = 0; dd < 8; dd++) ob[(long)(cc + dd) * 4096] = __float2half(acc[dd]);
    }
}

// ---------------- depthwise 3x3 (SAME) + exact GELU, fp16 io --------------------
__global__ void dwconv_gelu(const float* __restrict__ w, const float* __restrict__ bias) {
    long bo = blockIdx.x;                 // b*2048 + o
    int och = (int)(bo & 2047);
    const half* img = g_t1h + bo * 1024;
    __shared__ float s[1024];
    int tid = threadIdx.x; // 256
    {
        uint2 u = *(const uint2*)&img[tid * 4];
        float2 a = __half22float2(*(half2*)&u.x), b2 = __half22float2(*(half2*)&u.y);
        s[tid * 4] = a.x; s[tid * 4 + 1] = a.y; s[tid * 4 + 2] = b2.x; s[tid * 4 + 3] = b2.y;
    }
    float wv[9];
#pragma unroll
    for (int k = 0; k < 9; k++) wv[k] = w[och * 9 + k];
    float bb = bias[och];
    __syncthreads();
    half* ob = g_t2h + bo * 1024;
    for (int p = tid; p < 1024; p += 256) {
        int h = p >> 5, ww = p & 31;
        float acc = bb;
#pragma unroll
        for (int i = 0; i < 3; i++) {
            int hh = h + i - 1;
            if (hh < 0 || hh > 31) continue;
#pragma unroll
            for (int j = 0; j < 3; j++) {
                int w2 = ww + j - 1;
                if (w2 < 0 || w2 > 31) continue;
                acc += s[hh * 32 + w2] * wv[i * 3 + j];
            }
        }
        ob[p] = __float2half(0.5f * acc * (1.0f + erff(acc * 0.70710678118654752440f)));
    }
}

// ---------------- launch ------------------------------------------------------
extern "C" void kernel_launch(void* const* d_in, const int* in_sizes, int n_in,
                              void* d_out_v, int out_size) {
    const float* x      = (const float*)d_in[0];
    const float* qkvv_w = (const float*)d_in[1];
    const float* E_w    = (const float*)d_in[2];
    const float* E_b    = (const float*)d_in[3];
    const float* F_w    = (const float*)d_in[4];
    const float* F_b    = (const float*)d_in[5];
    const float* temp   = (const float*)d_in[6];
    const float* temp2  = (const float*)d_in[7];
    const float* out_w  = (const float*)d_in[8];
    const float* out_b  = (const float*)d_in[9];
    const float* out2_w = (const float*)d_in[10];
    const float* out2_b = (const float*)d_in[11];
    const float* fc1_w  = (const float*)d_in[12];
    const float* fc1_b  = (const float*)d_in[13];
    const float* dw_w   = (const float*)d_in[14];
    const float* dw_b   = (const float*)d_in[15];
    const float* fc2_w  = (const float*)d_in[16];
    const float* fc2_b  = (const float*)d_in[17];
    float* dout = (float*)d_out_v;

    half *p_xfh, *p_qkvvTh, *p_attncah, *p_xcah, *p_xsah, *p_t1h, *p_t2h;
    half *p_wq, *p_wfc1, *p_wfc2, *p_wout, *p_wout2, *p_wEFh;
    float *p_kvpart, *p_capart;
    cudaGetSymbolAddress((void**)&p_xfh, g_xfh);
    cudaGetSymbolAddress((void**)&p_qkvvTh, g_qkvvTh);
    cudaGetSymbolAddress((void**)&p_attncah, g_attncah);
    cudaGetSymbolAddress((void**)&p_xcah, g_xcah);
    cudaGetSymbolAddress((void**)&p_xsah, g_xsah);
    cudaGetSymbolAddress((void**)&p_t1h, g_t1h);
    cudaGetSymbolAddress((void**)&p_t2h, g_t2h);
    cudaGetSymbolAddress((void**)&p_wq, g_wq);
    cudaGetSymbolAddress((void**)&p_wfc1, g_wfc1);
    cudaGetSymbolAddress((void**)&p_wfc2, g_wfc2);
    cudaGetSymbolAddress((void**)&p_wout, g_wout);
    cudaGetSymbolAddress((void**)&p_wout2, g_wout2);
    cudaGetSymbolAddress((void**)&p_wEFh, g_wEFh);
    cudaGetSymbolAddress((void**)&p_kvpart, g_kvpart);
    cudaGetSymbolAddress((void**)&p_capart, g_capart);

    // opt into >48KB dynamic smem + max shared carveout (2 blocks/SM)
    constexpr int S_FT = gemm_smem<false, true>();   // 61440
    constexpr int S_FF = gemm_smem<false, false>();  // 56832
    constexpr int S_TT = gemm_smem<true, true>();    // 56832
    auto setup = [](const void* f, int smem) {
        cudaFuncSetAttribute(f, cudaFuncAttributeMaxDynamicSharedMemorySize, smem);
        cudaFuncSetAttribute(f, cudaFuncAttributePreferredSharedMemoryCarveout, 100);
    };
    setup((const void*)gemmH<false, true, 1, EpiQT>,  S_FT);
    setup((const void*)gemmH<false, true, 4, EpiKVP>, S_FT);
    setup((const void*)gemmH<false, true, 4, EpiCAP>, S_FT);
    setup((const void*)gemmH<false, false, 1, EpiH>,  S_FF);
    setup((const void*)gemmH<false, true, 1, EpiH>,   S_FT);
    setup((const void*)gemmH<true, true, 1, EpiOut>,  S_TT);
    setup((const void*)gemmH<false, true, 1, EpiOut>, S_FT);

    // ---- fork/join streams inside the capture: attention chain || LFE chain ----
    // (capture-time host ops only; graph replay preserves the concurrency)
    cudaStream_t s0 = 0;
    {
        cudaStreamCaptureStatus st = cudaStreamCaptureStatusNone;
        cudaStreamIsCapturing(s0, &st);   // harness captures on the legacy stream
    }
    cudaStream_t sA, sB;
    cudaStreamCreateWithFlags(&sA, cudaStreamNonBlocking);
    cudaStreamCreateWithFlags(&sB, cudaStreamNonBlocking);
    cudaEvent_t evRoot, evA, evB;
    cudaEventCreateWithFlags(&evRoot, cudaEventDisableTiming);
    cudaEventCreateWithFlags(&evA, cudaEventDisableTiming);
    cudaEventCreateWithFlags(&evB, cudaEventDisableTiming);

    // ---- shared prologue on main stream
    cvt_weights<<<3328, 256, 0, s0>>>(qkvv_w, fc1_w, fc2_w, out_w, out2_w);
    pad_wEF<<<256, 256, 0, s0>>>(E_w, F_w);
    pack_xf<<<16384, 128, 0, s0>>>(x);

    cudaEventRecord(evRoot, s0);
    cudaStreamWaitEvent(sA, evRoot, 0);
    cudaStreamWaitEvent(sB, evRoot, 0);

    // ======== branch A (stream sA): dual attention ========
    {
        EpiQT e{p_qkvvTh};
        gemmH<false, true, 1, EpiQT><<<dim3(8, 16, 16), 256, S_FT, sA>>>(
            p_wq, p_xfh, 2048, 1024, 512, 512, 512, 0, 524288, e);
    }
    {
        EpiKVP e{p_kvpart};
        gemmH<false, true, 4, EpiKVP><<<dim3(1, 64, 8), 256, S_FT, sA>>>(
            p_qkvvTh + 8388608, p_wEFh, 8192, 128, 256,
            1024, 1024, 2L * 8388608, 131072, e);
    }
    norm_scale<<<16384, 256, 0, sA>>>();
    {
        EpiCAP e{p_capart};
        gemmH<false, true, 4, EpiCAP><<<dim3(1, 1, 256), 256, S_FT, sA>>>(
            p_qkvvTh, p_qkvvTh + 8388608, 128, 128, 256, 1024, 1024, 131072, 131072, e);
    }
    softmax_ca<<<8192, 128, 0, sA>>>(temp);
    {
        EpiH e{p_xcah, 131072, 1024, nullptr};
        gemmH<false, false, 1, EpiH><<<dim3(8, 1, 64), 256, S_FF, sA>>>(
            p_attncah, p_qkvvTh + 2L * 8388608, 128, 1024, 128, 128, 1024, 16384, 131072, e);
    }
    spatial_attn<<<dim3(8, 64), 128, 0, sA>>>(temp2, E_b, F_b);

    // ======== branch B (stream sB): LFE conv-MLP ========
    {
        EpiH e{p_t1h, 2097152, 1024, fc1_b};
        gemmH<false, true, 1, EpiH><<<dim3(8, 16, 16), 256, S_FT, sB>>>(
            p_wfc1, p_xfh, 2048, 1024, 512, 512, 512, 0, 524288, e);
    }
    dwconv_gelu<<<32768, 256, 0, sB>>>(dw_w, dw_b);
    {
        EpiOut e{dout, fc2_b, 0, 0};   // assign: must precede the += epilogues
        gemmH<true, true, 1, EpiOut><<<dim3(4, 8, 16), 256, S_TT, sB>>>(
            p_t2h, p_wfc2, 1024, 512, 2048, 1024, 2048, 2097152, 0, e);
    }

    // ---- join both branches back into the main stream
    cudaEventRecord(evA, sA);
    cudaEventRecord(evB, sB);
    cudaStreamWaitEvent(s0, evA, 0);
    cudaStreamWaitEvent(s0, evB, 0);

    // ---- epilogue on main stream: accumulate projections into d_out
    {
        EpiOut e{dout, out_b, 0, 1};
        gemmH<false, true, 1, EpiOut><<<dim3(2, 8, 16), 256, S_FT, s0>>>(
            p_xsah, p_wout, 1024, 256, 512, 512, 512, 524288, 0, e);
    }
    {
        EpiOut e{dout, out2_b, 256, 1};
        gemmH<true, true, 1, EpiOut><<<dim3(2, 8, 16), 256, S_TT, s0>>>(
            p_xcah, p_wout2, 1024, 256, 512, 1024, 512, 524288, 0, e);
    }

    cudaEventDestroy(evRoot);
    cudaEventDestroy(evA);
    cudaEventDestroy(evB);
    cudaStreamDestroy(sA);
    cudaStreamDestroy(sB);
}